// round 4
// baseline (speedup 1.0000x reference)
#include <cuda_runtime.h>
#include <math.h>
#include <cstdint>

// ---------------------------------------------------------------------------
// Problem constants (PerceiverResampler)
// ---------------------------------------------------------------------------
#define DIMV   1024
#define NDEPTH 6
#define NHEADS 16
#define DHEAD  64
#define INNERV 1024
#define NLAT   64
#define FFV    4096
#define BTV    32
#define MEDIA  1024
#define LNEPS  1e-5f

// ---------------------------------------------------------------------------
// Scratch (static device allocations)
// ---------------------------------------------------------------------------
__device__ float g_xhat[(size_t)BTV * MEDIA * DIMV];
__device__ float g_kvm [(size_t)BTV * MEDIA * 2 * INNERV];
__device__ float g_lat [(size_t)BTV * NLAT * DIMV];
__device__ float g_latn[(size_t)BTV * NLAT * DIMV];
__device__ float g_qb  [(size_t)BTV * NLAT * INNERV];
__device__ float g_kvl [(size_t)BTV * NLAT * 2 * INNERV];
__device__ float g_attn[(size_t)BTV * NLAT * INNERV];
__device__ float g_ffh [(size_t)BTV * NLAT * FFV];
// tf32-rounded weight copies, ORIGINAL [K,N] layout (no transpose needed)
__device__ float g_wkvR [(size_t)NDEPTH * DIMV * 2 * INNERV];   // scaled by nm_g
__device__ float g_wkvRl[(size_t)NDEPTH * DIMV * 2 * INNERV];   // plain
__device__ float g_wqR  [(size_t)NDEPTH * DIMV * INNERV];
__device__ float g_woR  [(size_t)NDEPTH * INNERV * DIMV];
__device__ float g_w1R  [(size_t)NDEPTH * DIMV * FFV];
__device__ float g_w2R  [(size_t)NDEPTH * FFV * DIMV];
__device__ float g_kvbias[(size_t)NDEPTH * 2 * INNERV];         // nm_b @ wkv (fp32)

// ---------------------------------------------------------------------------
// helpers
// ---------------------------------------------------------------------------
__device__ __forceinline__ uint32_t smem_u32(const void* p) {
    uint32_t a;
    asm("{ .reg .u64 t; cvta.to.shared.u64 t, %1; cvt.u32.u64 %0, t; }"
        : "=r"(a) : "l"(p));
    return a;
}
__device__ __forceinline__ float tf32r(float x) {
    uint32_t u;
    asm("cvt.rna.tf32.f32 %0, %1;" : "=r"(u) : "f"(x));
    return __uint_as_float(u);
}
__device__ __forceinline__ void cp_async16(uint32_t dst, const void* src) {
    asm volatile("cp.async.cg.shared.global [%0], [%1], 16;" :: "r"(dst), "l"(src));
}
__device__ __forceinline__ void cp_commit() {
    asm volatile("cp.async.commit_group;" ::: "memory");
}
__device__ __forceinline__ void cp_wait1() {
    asm volatile("cp.async.wait_group 1;" ::: "memory");
}
__device__ __forceinline__ void cp_wait0() {
    asm volatile("cp.async.wait_group 0;" ::: "memory");
}
__device__ __forceinline__ void mma_tf32(float& c0, float& c1, float& c2, float& c3,
                                         uint32_t a0, uint32_t a1, uint32_t a2, uint32_t a3,
                                         uint32_t b0, uint32_t b1) {
    asm volatile(
        "mma.sync.aligned.m16n8k8.row.col.f32.tf32.tf32.f32 "
        "{%0,%1,%2,%3}, {%4,%5,%6,%7}, {%8,%9}, {%0,%1,%2,%3};"
        : "+f"(c0), "+f"(c1), "+f"(c2), "+f"(c3)
        : "r"(a0), "r"(a1), "r"(a2), "r"(a3), "r"(b0), "r"(b1));
}
__device__ __forceinline__ float gelu_exact(float x) {
    return 0.5f * x * (1.0f + erff(x * 0.70710678118654752f));
}

// ---------------------------------------------------------------------------
// Elementwise tf32 round (+optional per-k row scale), batched over layers.
//   out[f] = tf32( in[f] * scale[layer*DIMV + k] ),  f in [0, NDEPTH*KN)
// ---------------------------------------------------------------------------
__global__ void __launch_bounds__(256) wround_kernel(
    const float* __restrict__ in, float* __restrict__ out,
    int KN, int N, const float* __restrict__ scale)
{
    size_t i4 = (size_t)blockIdx.x * 256 + threadIdx.x;
    size_t f  = i4 * 4;
    float4 v = *(const float4*)(in + f);
    if (scale) {
        int layer = (int)(f / (size_t)KN);
        int k     = (int)((f - (size_t)layer * KN) / (size_t)N);
        float s = scale[layer * DIMV + k];
        v.x *= s; v.y *= s; v.z *= s; v.w *= s;
    }
    v.x = tf32r(v.x); v.y = tf32r(v.y); v.z = tf32r(v.z); v.w = tf32r(v.w);
    *(float4*)(out + f) = v;
}

// ---------------------------------------------------------------------------
// bias[layer][n] = sum_k b[layer][k] * W[layer][k][n]   (fp32, coalesced)
// ---------------------------------------------------------------------------
__global__ void __launch_bounds__(256) bias_kernel(
    const float* __restrict__ b, const float* __restrict__ W,
    float* __restrict__ out, int K, int N)
{
    int layer = blockIdx.y;
    int n = blockIdx.x * 256 + threadIdx.x;
    const float* Wl = W + (size_t)layer * K * N;
    const float* bl = b + (size_t)layer * K;
    float s = 0.f;
    for (int k = 0; k < K; k++) s = fmaf(bl[k], Wl[(size_t)k * N + n], s);
    out[(size_t)layer * N + n] = s;
}

// ---------------------------------------------------------------------------
// lat broadcast
// ---------------------------------------------------------------------------
__global__ void __launch_bounds__(256) init_lat_kernel(
    const float* __restrict__ latents, float* __restrict__ lat)
{
    int idx4 = blockIdx.x * 256 + threadIdx.x;
    int row  = idx4 >> 8;
    int c4   = idx4 & 255;
    int n    = row & 63;
    float4 v = *(const float4*)(latents + (size_t)n * DIMV + (c4 << 2));
    *(float4*)(lat + ((size_t)row << 10) + (c4 << 2)) = v;
}

// ---------------------------------------------------------------------------
// LayerNorm rows of 1024.  doRound: tf32-round output.
// ---------------------------------------------------------------------------
__global__ void __launch_bounds__(256) ln_kernel(
    const float* __restrict__ in, float* __restrict__ out,
    const float* __restrict__ g, const float* __restrict__ b, int doRound)
{
    __shared__ float red[2][8];
    size_t row = blockIdx.x;
    const float* x = in + row * DIMV;
    int t = threadIdx.x;

    float4 v = *(const float4*)(x + (t << 2));
    float s  = v.x + v.y + v.z + v.w;
    float ss = v.x*v.x + v.y*v.y + v.z*v.z + v.w*v.w;
    #pragma unroll
    for (int off = 16; off; off >>= 1) {
        s  += __shfl_xor_sync(0xffffffffu, s,  off);
        ss += __shfl_xor_sync(0xffffffffu, ss, off);
    }
    int w = t >> 5, lane = t & 31;
    if (lane == 0) { red[0][w] = s; red[1][w] = ss; }
    __syncthreads();
    if (t == 0) {
        float ts = 0.f, tss = 0.f;
        #pragma unroll
        for (int i = 0; i < 8; i++) { ts += red[0][i]; tss += red[1][i]; }
        red[0][0] = ts; red[1][0] = tss;
    }
    __syncthreads();
    float mean = red[0][0] * (1.f / 1024.f);
    float var  = red[1][0] * (1.f / 1024.f) - mean * mean;
    float inv  = rsqrtf(var + LNEPS);

    float gx = 1.f, gy = 1.f, gz = 1.f, gw = 1.f;
    float bx = 0.f, by = 0.f, bz = 0.f, bw = 0.f;
    if (g) {
        float4 gg = *(const float4*)(g + (t << 2));
        float4 bb = *(const float4*)(b + (t << 2));
        gx = gg.x; gy = gg.y; gz = gg.z; gw = gg.w;
        bx = bb.x; by = bb.y; bz = bb.z; bw = bb.w;
    }
    float4 o;
    o.x = (v.x - mean) * inv * gx + bx;
    o.y = (v.y - mean) * inv * gy + by;
    o.z = (v.z - mean) * inv * gz + bz;
    o.w = (v.w - mean) * inv * gw + bw;
    if (doRound) {
        o.x = tf32r(o.x); o.y = tf32r(o.y); o.z = tf32r(o.z); o.w = tf32r(o.w);
    }
    *(float4*)(out + row * DIMV + (t << 2)) = o;
}

// ---------------------------------------------------------------------------
// tf32 mma.sync GEMM:  C[M,N] = op( A[M,K] @ B[K,N] (+bias[n]) (+resid) )
//   A tf32-rounded [M,K]; B tf32-rounded [K,N] (original layout, no transpose:
//   the .col B-fragment reads Bs[k][n] directly).
//   Block: BM=128, BN=32*JF.  8 warps (2m x 4n), warp tile 64 x (8*JF).
//   BK=32, cp.async double-buffered.
//   PADN = 32*JF + 8  (== 8 mod 32  ->  B-fragment LDS conflict-free)
// ---------------------------------------------------------------------------
#define PADK 36
template <int JF>
__global__ void __launch_bounds__(256, (JF == 4) ? 2 : 1) gemm_mma(
    const float* __restrict__ A, const float* __restrict__ B, float* __restrict__ C,
    int K, int lda, int ldb, int ldc,
    const float* __restrict__ bias, const float* __restrict__ resid,
    int doGelu, int doRound)
{
    constexpr int BN   = 32 * JF;
    constexpr int PADN = BN + 8;
    extern __shared__ float sm[];
    float* As = sm;                        // [2][128][PADK]
    float* Bs = sm + 2 * 128 * PADK;       // [2][32][PADN]
    const uint32_t asb = smem_u32(As);
    const uint32_t bsb = smem_u32(Bs);

    const int tid  = threadIdx.x;
    const int wid  = tid >> 5;
    const int lane = tid & 31;
    const int wm   = wid >> 2;          // 0..1
    const int wn   = wid & 3;           // 0..3
    const int g    = lane >> 2;         // 0..7
    const int t    = lane & 3;          // 0..3
    const int m0   = blockIdx.y << 7;
    const int n0   = blockIdx.x * BN;
    const int NK   = K >> 5;

    float acc[4][JF][4];
    #pragma unroll
    for (int i = 0; i < 4; i++)
        #pragma unroll
        for (int j = 0; j < JF; j++)
            #pragma unroll
            for (int r = 0; r < 4; r++) acc[i][j][r] = 0.f;

    auto load_tile = [&](int kt, int buf) {
        const int kg = kt << 5;
        // A: 128x32 = 1024 float4
        #pragma unroll
        for (int p = 0; p < 4; p++) {
            int idx = p * 256 + tid;
            int row = idx >> 3;
            int c4  = (idx & 7) << 2;
            cp_async16(asb + ((buf * 128 + row) * PADK + c4) * 4,
                       A + (size_t)(m0 + row) * lda + kg + c4);
        }
        // B: 32xBN = 8*JF float4 per row
        #pragma unroll
        for (int p = 0; p < JF; p++) {
            int idx = p * 256 + tid;
            int row, c4;
            if (JF == 8) { row = idx >> 6; c4 = (idx & 63) << 2; }
            else         { row = idx >> 5; c4 = (idx & 31) << 2; }
            cp_async16(bsb + ((buf * 32 + row) * PADN + c4) * 4,
                       B + (size_t)(kg + row) * ldb + n0 + c4);
        }
    };

    load_tile(0, 0);
    cp_commit();

    for (int kt = 0; kt < NK; kt++) {
        const int buf = kt & 1;
        if (kt + 1 < NK) {
            load_tile(kt + 1, buf ^ 1);
            cp_commit();
            cp_wait1();
        } else {
            cp_wait0();
        }
        __syncthreads();

        const float* Ab = As + (size_t)(buf * 128) * PADK;
        const float* Bb = Bs + (size_t)(buf * 32) * PADN;
        #pragma unroll
        for (int ks = 0; ks < 4; ks++) {
            const int kk = ks << 3;
            uint32_t af[4][4], bf[JF][2];
            #pragma unroll
            for (int i = 0; i < 4; i++) {
                const float* ap = Ab + (size_t)(wm * 64 + i * 16 + g) * PADK + kk + t;
                af[i][0] = __float_as_uint(ap[0]);
                af[i][1] = __float_as_uint(ap[8 * PADK]);
                af[i][2] = __float_as_uint(ap[4]);
                af[i][3] = __float_as_uint(ap[8 * PADK + 4]);
            }
            #pragma unroll
            for (int j = 0; j < JF; j++) {
                const int col = wn * (8 * JF) + j * 8 + g;
                bf[j][0] = __float_as_uint(Bb[(size_t)(kk + t)     * PADN + col]);
                bf[j][1] = __float_as_uint(Bb[(size_t)(kk + t + 4) * PADN + col]);
            }
            #pragma unroll
            for (int i = 0; i < 4; i++)
                #pragma unroll
                for (int j = 0; j < JF; j++)
                    mma_tf32(acc[i][j][0], acc[i][j][1], acc[i][j][2], acc[i][j][3],
                             af[i][0], af[i][1], af[i][2], af[i][3],
                             bf[j][0], bf[j][1]);
        }
        __syncthreads();
    }

    // epilogue
    #pragma unroll
    for (int i = 0; i < 4; i++) {
        int mrow = m0 + wm * 64 + i * 16 + g;
        #pragma unroll
        for (int j = 0; j < JF; j++) {
            int ncol = n0 + wn * (8 * JF) + j * 8 + 2 * t;
            #pragma unroll
            for (int half = 0; half < 2; half++) {
                int mr = mrow + half * 8;
                float c0 = acc[i][j][2 * half + 0];
                float c1 = acc[i][j][2 * half + 1];
                if (bias) {
                    float2 bv = *(const float2*)(bias + ncol);
                    c0 += bv.x; c1 += bv.y;
                }
                if (resid) {
                    float2 rv = *(const float2*)(resid + (size_t)mr * ldc + ncol);
                    c0 += rv.x; c1 += rv.y;
                }
                if (doGelu) { c0 = gelu_exact(c0); c1 = gelu_exact(c1); }
                if (doRound) { c0 = tf32r(c0); c1 = tf32r(c1); }
                float2 o; o.x = c0; o.y = c1;
                *(float2*)(C + (size_t)mr * ldc + ncol) = o;
            }
        }
    }
}

// ---------------------------------------------------------------------------
// Attention (fp32 SIMT, loop-interchanged to cut LDS issue pressure).
// Output tf32-rounded (feeds wo GEMM).
// ---------------------------------------------------------------------------
__global__ void __launch_bounds__(256) attn_kernel(
    const float* __restrict__ q,   const float* __restrict__ kvm,
    const float* __restrict__ kvl, float* __restrict__ outp)
{
    __shared__ float qs[64][64];
    __shared__ float ks[32][65];
    __shared__ float vs[32][65];
    __shared__ float ps[8][8][32];

    const int bt = blockIdx.x >> 4;
    const int h  = blockIdx.x & 15;
    const int tid  = threadIdx.x;
    const int w    = tid >> 5;
    const int lane = tid & 31;
    const float scale = 0.125f;

    for (int idx = tid; idx < 1024; idx += 256) {
        int r = idx >> 4;
        int c = (idx & 15) << 2;
        float4 v = *(const float4*)(q + ((size_t)bt * 64 + r) * INNERV + h * DHEAD + c);
        qs[r][c + 0] = v.x * scale;
        qs[r][c + 1] = v.y * scale;
        qs[r][c + 2] = v.z * scale;
        qs[r][c + 3] = v.w * scale;
    }

    float m[8], l[8], o0[8], o1[8];
    #pragma unroll
    for (int i = 0; i < 8; i++) { m[i] = -1e30f; l[i] = 0.f; o0[i] = 0.f; o1[i] = 0.f; }
    __syncthreads();

    for (int chunk = 0; chunk < 34; ++chunk) {
        int j0 = chunk << 5;
        const float* kb;
        if (j0 < 1024) kb = kvm + ((size_t)bt * 1024 + j0) * 2048 + h * DHEAD;
        else           kb = kvl + ((size_t)bt * 64 + (j0 - 1024)) * 2048 + h * DHEAD;

        for (int idx = tid; idx < 512; idx += 256) {
            int r = idx >> 4;
            int c = (idx & 15) << 2;
            const float* src = kb + (size_t)r * 2048 + c;
            float4 kk = *(const float4*)(src);
            ks[r][c + 0] = kk.x; ks[r][c + 1] = kk.y; ks[r][c + 2] = kk.z; ks[r][c + 3] = kk.w;
            float4 vv = *(const float4*)(src + 1024);
            vs[r][c + 0] = vv.x; vs[r][c + 1] = vv.y; vs[r][c + 2] = vv.z; vs[r][c + 3] = vv.w;
        }
        __syncthreads();

        // QK: d-outer (1 K-LDS + 8 broadcast-LDS + 8 FMA per d)
        float s[8];
        #pragma unroll
        for (int i = 0; i < 8; i++) s[i] = 0.f;
        #pragma unroll 8
        for (int d = 0; d < 64; ++d) {
            float kd = ks[lane][d];
            #pragma unroll
            for (int i = 0; i < 8; i++)
                s[i] = fmaf(qs[(w << 3) + i][d], kd, s[i]);
        }
        #pragma unroll
        for (int i = 0; i < 8; i++) {
            float cm = s[i];
            #pragma unroll
            for (int off = 16; off; off >>= 1)
                cm = fmaxf(cm, __shfl_xor_sync(0xffffffffu, cm, off));
            float mt = fmaxf(m[i], cm);
            float p  = __expf(s[i] - mt);
            float psum = p;
            #pragma unroll
            for (int off = 16; off; off >>= 1)
                psum += __shfl_xor_sync(0xffffffffu, psum, off);
            float corr = __expf(m[i] - mt);
            l[i] = l[i] * corr + psum;
            m[i] = mt;
            o0[i] *= corr;
            o1[i] *= corr;
            ps[w][i][lane] = p;
        }
        __syncwarp();
        // PV: jj-outer (2 V-LDS + 8 broadcast-LDS + 16 FMA per jj)
        #pragma unroll 4
        for (int jj = 0; jj < 32; jj++) {
            float v0 = vs[jj][lane];
            float v1 = vs[jj][lane + 32];
            #pragma unroll
            for (int i = 0; i < 8; i++) {
                float p = ps[w][i][jj];
                o0[i] = fmaf(p, v0, o0[i]);
                o1[i] = fmaf(p, v1, o1[i]);
            }
        }
        __syncthreads();
    }

    #pragma unroll
    for (int i = 0; i < 8; i++) {
        float inv = 1.f / l[i];
        size_t row = (size_t)bt * 64 + (w << 3) + i;
        outp[row * INNERV + h * DHEAD + lane]      = tf32r(o0[i] * inv);
        outp[row * INNERV + h * DHEAD + lane + 32] = tf32r(o1[i] * inv);
    }
}

// ---------------------------------------------------------------------------
// Host orchestration
// ---------------------------------------------------------------------------
extern "C" void kernel_launch(void* const* d_in, const int* in_sizes, int n_in,
                              void* d_out, int out_size)
{
    const float* x       = (const float*)d_in[0];
    const float* latents = (const float*)d_in[1];
    const float* nm_g    = (const float*)d_in[2];
    const float* nm_b    = (const float*)d_in[3];
    const float* nl_g    = (const float*)d_in[4];
    const float* nl_b    = (const float*)d_in[5];
    const float* wq      = (const float*)d_in[6];
    const float* wkv     = (const float*)d_in[7];
    const float* wo      = (const float*)d_in[8];
    const float* ff_g    = (const float*)d_in[9];
    const float* ff_b    = (const float*)d_in[10];
    const float* w1      = (const float*)d_in[11];
    const float* w2      = (const float*)d_in[12];
    const float* fin_g   = (const float*)d_in[13];
    const float* fin_b   = (const float*)d_in[14];

    float *xhat, *kvm, *lat, *latn, *qb, *kvl, *attn, *ffh;
    float *wkvR, *wkvRl, *wqR, *woR, *w1R, *w2R, *kvbias;
    cudaGetSymbolAddress((void**)&xhat,  g_xhat);
    cudaGetSymbolAddress((void**)&kvm,   g_kvm);
    cudaGetSymbolAddress((void**)&lat,   g_lat);
    cudaGetSymbolAddress((void**)&latn,  g_latn);
    cudaGetSymbolAddress((void**)&qb,    g_qb);
    cudaGetSymbolAddress((void**)&kvl,   g_kvl);
    cudaGetSymbolAddress((void**)&attn,  g_attn);
    cudaGetSymbolAddress((void**)&ffh,   g_ffh);
    cudaGetSymbolAddress((void**)&wkvR,  g_wkvR);
    cudaGetSymbolAddress((void**)&wkvRl, g_wkvRl);
    cudaGetSymbolAddress((void**)&wqR,   g_wqR);
    cudaGetSymbolAddress((void**)&woR,   g_woR);
    cudaGetSymbolAddress((void**)&w1R,   g_w1R);
    cudaGetSymbolAddress((void**)&w2R,   g_w2R);
    cudaGetSymbolAddress((void**)&kvbias, g_kvbias);

    const int SMEM_J8 = (2 * 128 * PADK + 2 * 32 * (256 + 8)) * 4;  // 104448
    const int SMEM_J4 = (2 * 128 * PADK + 2 * 32 * (128 + 8)) * 4;  //  71680
    cudaFuncSetAttribute(gemm_mma<8>, cudaFuncAttributeMaxDynamicSharedMemorySize, SMEM_J8);
    cudaFuncSetAttribute(gemm_mma<4>, cudaFuncAttributeMaxDynamicSharedMemorySize, SMEM_J4);

    // ---- preproc arranged so launch index 5 == first kvm GEMM (for ncu) ----
    // 0: wkv scaled round
    wround_kernel<<<(NDEPTH * DIMV * 2 * INNERV) / 1024, 256>>>(
        wkv, wkvR, DIMV * 2 * INNERV, 2 * INNERV, nm_g);
    // 1: xhat = tf32(LN(x)) (affine folded into wkvR/kvbias)
    ln_kernel<<<BTV * MEDIA, 256>>>(x, xhat, nullptr, nullptr, 1);
    // 2: lat broadcast
    init_lat_kernel<<<2048, 256>>>(latents, lat);
    // 3: wkv plain round
    wround_kernel<<<(NDEPTH * DIMV * 2 * INNERV) / 1024, 256>>>(
        wkv, wkvRl, DIMV * 2 * INNERV, 2 * INNERV, nullptr);
    // 4: kv bias rows (fp32)
    bias_kernel<<<dim3(2 * INNERV / 256, NDEPTH), 256>>>(
        nm_b, wkv, kvbias, DIMV, 2 * INNERV);
    // 5: layer-0 media KV projection  [32768,1024]@[1024,2048]  <-- profiled
    gemm_mma<8><<<dim3(2 * INNERV / 256, BTV * MEDIA / 128), 256, SMEM_J8>>>(
        xhat, wkvR, kvm, DIMV, DIMV, 2 * INNERV, 2 * INNERV,
        kvbias, nullptr, 0, 0);
    // remaining weight rounds
    wround_kernel<<<(NDEPTH * DIMV * INNERV) / 1024, 256>>>(
        wq, wqR, DIMV * INNERV, INNERV, nullptr);
    wround_kernel<<<(NDEPTH * INNERV * DIMV) / 1024, 256>>>(
        wo, woR, INNERV * DIMV, DIMV, nullptr);
    wround_kernel<<<(NDEPTH * DIMV * FFV) / 1024, 256>>>(
        w1, w1R, DIMV * FFV, FFV, nullptr);
    wround_kernel<<<(NDEPTH * FFV * DIMV) / 1024, 256>>>(
        w2, w2R, FFV * DIMV, DIMV, nullptr);

    for (int i = 0; i < NDEPTH; i++) {
        const float* wkvR_i  = wkvR  + (size_t)i * DIMV * 2 * INNERV;
        const float* wkvRl_i = wkvRl + (size_t)i * DIMV * 2 * INNERV;
        const float* wqR_i   = wqR   + (size_t)i * DIMV * INNERV;
        const float* woR_i   = woR   + (size_t)i * INNERV * DIMV;
        const float* w1R_i   = w1R   + (size_t)i * DIMV * FFV;
        const float* w2R_i   = w2R   + (size_t)i * FFV * DIMV;
        const float* kvb_i   = kvbias + (size_t)i * 2 * INNERV;

        if (i > 0) {
            gemm_mma<8><<<dim3(2 * INNERV / 256, BTV * MEDIA / 128), 256, SMEM_J8>>>(
                xhat, wkvR_i, kvm, DIMV, DIMV, 2 * INNERV, 2 * INNERV,
                kvb_i, nullptr, 0, 0);
        }

        ln_kernel<<<BTV * NLAT, 256>>>(lat, latn,
            nl_g + (size_t)i * DIMV, nl_b + (size_t)i * DIMV, 1);
        gemm_mma<4><<<dim3(INNERV / 128, 16), 256, SMEM_J4>>>(
            latn, wqR_i, qb, DIMV, DIMV, INNERV, INNERV,
            nullptr, nullptr, 0, 0);
        gemm_mma<8><<<dim3(2 * INNERV / 256, 16), 256, SMEM_J8>>>(
            latn, wkvRl_i, kvl, DIMV, DIMV, 2 * INNERV, 2 * INNERV,
            nullptr, nullptr, 0, 0);

        attn_kernel<<<BTV * NHEADS, 256>>>(qb, kvm, kvl, attn);

        gemm_mma<4><<<dim3(DIMV / 128, 16), 256, SMEM_J4>>>(
            attn, woR_i, lat, INNERV, INNERV, DIMV, DIMV,
            nullptr, lat, 0, 0);

        ln_kernel<<<BTV * NLAT, 256>>>(lat, latn,
            ff_g + (size_t)i * DIMV, ff_b + (size_t)i * DIMV, 1);
        gemm_mma<8><<<dim3(FFV / 256, 16), 256, SMEM_J8>>>(
            latn, w1R_i, ffh, DIMV, DIMV, FFV, FFV,
            nullptr, nullptr, 1, 1);
        gemm_mma<4><<<dim3(DIMV / 128, 16), 256, SMEM_J4>>>(
            ffh, w2R_i, lat, FFV, FFV, DIMV, DIMV,
            nullptr, lat, 0, 0);
    }

    ln_kernel<<<BTV * NLAT, 256>>>(lat, (float*)d_out, fin_g, fin_b, 0);
}

// round 5
// speedup vs baseline: 1.3127x; 1.3127x over previous
#include <cuda_runtime.h>
#include <math.h>
#include <cstdint>

// ---------------------------------------------------------------------------
// Problem constants (PerceiverResampler)
// ---------------------------------------------------------------------------
#define DIMV   1024
#define NDEPTH 6
#define NHEADS 16
#define DHEAD  64
#define INNERV 1024
#define NLAT   64
#define FFV    4096
#define BTV    32
#define MEDIA  1024
#define LNEPS  1e-5f

// ---------------------------------------------------------------------------
// Scratch (static device allocations)
// ---------------------------------------------------------------------------
__device__ float g_xhat[(size_t)BTV * MEDIA * DIMV];
__device__ float g_kvm [(size_t)BTV * MEDIA * 2 * INNERV];
__device__ float g_lat [(size_t)BTV * NLAT * DIMV];
__device__ float g_latn[(size_t)BTV * NLAT * DIMV];
__device__ float g_qb  [(size_t)BTV * NLAT * INNERV];
__device__ float g_kvl [(size_t)BTV * NLAT * 2 * INNERV];
__device__ float g_attn[(size_t)BTV * NLAT * INNERV];
__device__ float g_ffh [(size_t)BTV * NLAT * FFV];
// tf32-rounded weight copies, ORIGINAL [K,N] layout
__device__ float g_wkvR [(size_t)NDEPTH * DIMV * 2 * INNERV];   // scaled by nm_g
__device__ float g_wkvRl[(size_t)NDEPTH * DIMV * 2 * INNERV];   // plain
__device__ float g_wqR  [(size_t)NDEPTH * DIMV * INNERV];
__device__ float g_woR  [(size_t)NDEPTH * INNERV * DIMV];
__device__ float g_w1R  [(size_t)NDEPTH * DIMV * FFV];
__device__ float g_w2R  [(size_t)NDEPTH * FFV * DIMV];
__device__ float g_kvbias[(size_t)NDEPTH * 2 * INNERV];         // nm_b @ wkv

// ---------------------------------------------------------------------------
// helpers
// ---------------------------------------------------------------------------
__device__ __forceinline__ uint32_t smem_u32(const void* p) {
    uint32_t a;
    asm("{ .reg .u64 t; cvta.to.shared.u64 t, %1; cvt.u32.u64 %0, t; }"
        : "=r"(a) : "l"(p));
    return a;
}
__device__ __forceinline__ float tf32r(float x) {
    uint32_t u;
    asm("cvt.rna.tf32.f32 %0, %1;" : "=r"(u) : "f"(x));
    return __uint_as_float(u);
}
__device__ __forceinline__ void cp_async16(uint32_t dst, const void* src) {
    asm volatile("cp.async.cg.shared.global [%0], [%1], 16;" :: "r"(dst), "l"(src));
}
__device__ __forceinline__ void cp_commit() {
    asm volatile("cp.async.commit_group;" ::: "memory");
}
__device__ __forceinline__ void cp_wait1() {
    asm volatile("cp.async.wait_group 1;" ::: "memory");
}
__device__ __forceinline__ void cp_wait0() {
    asm volatile("cp.async.wait_group 0;" ::: "memory");
}
__device__ __forceinline__ void mma_tf32(float& c0, float& c1, float& c2, float& c3,
                                         uint32_t a0, uint32_t a1, uint32_t a2, uint32_t a3,
                                         uint32_t b0, uint32_t b1) {
    asm volatile(
        "mma.sync.aligned.m16n8k8.row.col.f32.tf32.tf32.f32 "
        "{%0,%1,%2,%3}, {%4,%5,%6,%7}, {%8,%9}, {%0,%1,%2,%3};"
        : "+f"(c0), "+f"(c1), "+f"(c2), "+f"(c3)
        : "r"(a0), "r"(a1), "r"(a2), "r"(a3), "r"(b0), "r"(b1));
}
__device__ __forceinline__ float gelu_exact(float x) {
    return 0.5f * x * (1.0f + erff(x * 0.70710678118654752f));
}

// ---------------------------------------------------------------------------
// Elementwise tf32 round (+optional per-k row scale), batched over layers
// ---------------------------------------------------------------------------
__global__ void __launch_bounds__(256) wround_kernel(
    const float* __restrict__ in, float* __restrict__ out,
    int KN, int N, const float* __restrict__ scale)
{
    size_t i4 = (size_t)blockIdx.x * 256 + threadIdx.x;
    size_t f  = i4 * 4;
    float4 v = *(const float4*)(in + f);
    if (scale) {
        int layer = (int)(f / (size_t)KN);
        int k     = (int)((f - (size_t)layer * KN) / (size_t)N);
        float s = scale[layer * DIMV + k];
        v.x *= s; v.y *= s; v.z *= s; v.w *= s;
    }
    v.x = tf32r(v.x); v.y = tf32r(v.y); v.z = tf32r(v.z); v.w = tf32r(v.w);
    *(float4*)(out + f) = v;
}

// ---------------------------------------------------------------------------
// bias[layer][n] = sum_k b[layer][k] * W[layer][k][n]
// ---------------------------------------------------------------------------
__global__ void __launch_bounds__(256) bias_kernel(
    const float* __restrict__ b, const float* __restrict__ W,
    float* __restrict__ out, int K, int N)
{
    int layer = blockIdx.y;
    int n = blockIdx.x * 256 + threadIdx.x;
    const float* Wl = W + (size_t)layer * K * N;
    const float* bl = b + (size_t)layer * K;
    float s = 0.f;
    for (int k = 0; k < K; k++) s = fmaf(bl[k], Wl[(size_t)k * N + n], s);
    out[(size_t)layer * N + n] = s;
}

// ---------------------------------------------------------------------------
// lat broadcast
// ---------------------------------------------------------------------------
__global__ void __launch_bounds__(256) init_lat_kernel(
    const float* __restrict__ latents, float* __restrict__ lat)
{
    int idx4 = blockIdx.x * 256 + threadIdx.x;
    int row  = idx4 >> 8;
    int c4   = idx4 & 255;
    int n    = row & 63;
    float4 v = *(const float4*)(latents + (size_t)n * DIMV + (c4 << 2));
    *(float4*)(lat + ((size_t)row << 10) + (c4 << 2)) = v;
}

// ---------------------------------------------------------------------------
// LayerNorm rows of 1024
// ---------------------------------------------------------------------------
__global__ void __launch_bounds__(256) ln_kernel(
    const float* __restrict__ in, float* __restrict__ out,
    const float* __restrict__ g, const float* __restrict__ b, int doRound)
{
    __shared__ float red[2][8];
    size_t row = blockIdx.x;
    const float* x = in + row * DIMV;
    int t = threadIdx.x;

    float4 v = *(const float4*)(x + (t << 2));
    float s  = v.x + v.y + v.z + v.w;
    float ss = v.x*v.x + v.y*v.y + v.z*v.z + v.w*v.w;
    #pragma unroll
    for (int off = 16; off; off >>= 1) {
        s  += __shfl_xor_sync(0xffffffffu, s,  off);
        ss += __shfl_xor_sync(0xffffffffu, ss, off);
    }
    int w = t >> 5, lane = t & 31;
    if (lane == 0) { red[0][w] = s; red[1][w] = ss; }
    __syncthreads();
    if (t == 0) {
        float ts = 0.f, tss = 0.f;
        #pragma unroll
        for (int i = 0; i < 8; i++) { ts += red[0][i]; tss += red[1][i]; }
        red[0][0] = ts; red[1][0] = tss;
    }
    __syncthreads();
    float mean = red[0][0] * (1.f / 1024.f);
    float var  = red[1][0] * (1.f / 1024.f) - mean * mean;
    float inv  = rsqrtf(var + LNEPS);

    float gx = 1.f, gy = 1.f, gz = 1.f, gw = 1.f;
    float bx = 0.f, by = 0.f, bz = 0.f, bw = 0.f;
    if (g) {
        float4 gg = *(const float4*)(g + (t << 2));
        float4 bb = *(const float4*)(b + (t << 2));
        gx = gg.x; gy = gg.y; gz = gg.z; gw = gg.w;
        bx = bb.x; by = bb.y; bz = bb.z; bw = bb.w;
    }
    float4 o;
    o.x = (v.x - mean) * inv * gx + bx;
    o.y = (v.y - mean) * inv * gy + by;
    o.z = (v.z - mean) * inv * gz + bz;
    o.w = (v.w - mean) * inv * gw + bw;
    if (doRound) {
        o.x = tf32r(o.x); o.y = tf32r(o.y); o.z = tf32r(o.z); o.w = tf32r(o.w);
    }
    *(float4*)(out + row * DIMV + (t << 2)) = o;
}

// ---------------------------------------------------------------------------
// tf32 mma.sync GEMM:  C[M,N] = op( A[M,K] @ B[K,N] (+bias[n]) (+resid) )
//   Block: BM = 32*IM (IM=4 -> 128, IM=2 -> 64), BN = 32*JF (JF=4 -> 128).
//   8 warps (2m x 4n); warp tile (IM*16) x (JF*8).  BK=32, 2-stage cp.async.
//   B stays in original [K,N] layout (PADN == 8 mod 32 -> conflict-free).
// ---------------------------------------------------------------------------
#define PADK 36
template <int IM, int JF>
__global__ void __launch_bounds__(256, (IM == 4) ? 2 : 3) gemm_mma(
    const float* __restrict__ A, const float* __restrict__ B, float* __restrict__ C,
    int K, int lda, int ldb, int ldc,
    const float* __restrict__ bias, const float* __restrict__ resid,
    int doGelu, int doRound)
{
    constexpr int BM   = 32 * IM;
    constexpr int BN   = 32 * JF;
    constexpr int PADN = BN + 8;
    extern __shared__ float sm[];
    float* As = sm;                        // [2][BM][PADK]
    float* Bs = sm + 2 * BM * PADK;        // [2][32][PADN]
    const uint32_t asb = smem_u32(As);
    const uint32_t bsb = smem_u32(Bs);

    const int tid  = threadIdx.x;
    const int wid  = tid >> 5;
    const int lane = tid & 31;
    const int wm   = wid >> 2;          // 0..1
    const int wn   = wid & 3;           // 0..3
    const int g    = lane >> 2;         // 0..7
    const int t    = lane & 3;          // 0..3
    const int m0   = blockIdx.y * BM;
    const int n0   = blockIdx.x * BN;
    const int NK   = K >> 5;

    float acc[IM][JF][4];
    #pragma unroll
    for (int i = 0; i < IM; i++)
        #pragma unroll
        for (int j = 0; j < JF; j++)
            #pragma unroll
            for (int r = 0; r < 4; r++) acc[i][j][r] = 0.f;

    auto load_tile = [&](int kt, int buf) {
        const int kg = kt << 5;
        #pragma unroll
        for (int p = 0; p < IM; p++) {           // A: BM x 32 = IM*256 float4
            int idx = p * 256 + tid;
            int row = idx >> 3;
            int c4  = (idx & 7) << 2;
            cp_async16(asb + ((buf * BM + row) * PADK + c4) * 4,
                       A + (size_t)(m0 + row) * lda + kg + c4);
        }
        #pragma unroll
        for (int p = 0; p < JF; p++) {           // B: 32 x BN = JF*256 float4
            int idx = p * 256 + tid;
            int row = idx >> 5;
            int c4  = (idx & 31) << 2;
            cp_async16(bsb + ((buf * 32 + row) * PADN + c4) * 4,
                       B + (size_t)(kg + row) * ldb + n0 + c4);
        }
    };

    load_tile(0, 0);
    cp_commit();

    for (int kt = 0; kt < NK; kt++) {
        const int buf = kt & 1;
        if (kt + 1 < NK) {
            load_tile(kt + 1, buf ^ 1);
            cp_commit();
            cp_wait1();
        } else {
            cp_wait0();
        }
        __syncthreads();

        const float* Ab = As + (size_t)(buf * BM) * PADK;
        const float* Bb = Bs + (size_t)(buf * 32) * PADN;
        #pragma unroll
        for (int ks = 0; ks < 4; ks++) {
            const int kk = ks << 3;
            uint32_t af[IM][4], bf[JF][2];
            #pragma unroll
            for (int i = 0; i < IM; i++) {
                const float* ap = Ab + (size_t)(wm * (IM * 16) + i * 16 + g) * PADK + kk + t;
                af[i][0] = __float_as_uint(ap[0]);
                af[i][1] = __float_as_uint(ap[8 * PADK]);
                af[i][2] = __float_as_uint(ap[4]);
                af[i][3] = __float_as_uint(ap[8 * PADK + 4]);
            }
            #pragma unroll
            for (int j = 0; j < JF; j++) {
                const int col = wn * (8 * JF) + j * 8 + g;
                bf[j][0] = __float_as_uint(Bb[(size_t)(kk + t)     * PADN + col]);
                bf[j][1] = __float_as_uint(Bb[(size_t)(kk + t + 4) * PADN + col]);
            }
            #pragma unroll
            for (int i = 0; i < IM; i++)
                #pragma unroll
                for (int j = 0; j < JF; j++)
                    mma_tf32(acc[i][j][0], acc[i][j][1], acc[i][j][2], acc[i][j][3],
                             af[i][0], af[i][1], af[i][2], af[i][3],
                             bf[j][0], bf[j][1]);
        }
        __syncthreads();
    }

    // epilogue
    #pragma unroll
    for (int i = 0; i < IM; i++) {
        int mrow = m0 + wm * (IM * 16) + i * 16 + g;
        #pragma unroll
        for (int j = 0; j < JF; j++) {
            int ncol = n0 + wn * (8 * JF) + j * 8 + 2 * t;
            #pragma unroll
            for (int half = 0; half < 2; half++) {
                int mr = mrow + half * 8;
                float c0 = acc[i][j][2 * half + 0];
                float c1 = acc[i][j][2 * half + 1];
                if (bias) {
                    float2 bv = *(const float2*)(bias + ncol);
                    c0 += bv.x; c1 += bv.y;
                }
                if (resid) {
                    float2 rv = *(const float2*)(resid + (size_t)mr * ldc + ncol);
                    c0 += rv.x; c1 += rv.y;
                }
                if (doGelu) { c0 = gelu_exact(c0); c1 = gelu_exact(c1); }
                if (doRound) { c0 = tf32r(c0); c1 = tf32r(c1); }
                float2 o; o.x = c0; o.y = c1;
                *(float2*)(C + (size_t)mr * ldc + ncol) = o;
            }
        }
    }
}

// ---------------------------------------------------------------------------
// Tensor-core attention (mma.sync tf32).  Block = (bt, head), 4 warps.
// Warp w owns q rows [w*16, w*16+16).  Q A-fragments preloaded in registers.
// KV streamed in 32-token chunks (32 media + 2 latent = 34), 2-stage cp.async.
// Online softmax entirely in C-fragment registers; P staged via per-warp smem.
// ---------------------------------------------------------------------------
__global__ void __launch_bounds__(128, 4) attn_mma_kernel(
    const float* __restrict__ q,   const float* __restrict__ kvm,
    const float* __restrict__ kvl, float* __restrict__ outp)
{
    __shared__ float ks[2][32][68];   // chunk K  [token][d]
    __shared__ float vs[2][32][72];   // chunk V  [token][d]
    __shared__ float ps[4][16][36];   // per-warp P tile [qrow][token]

    const int bt   = blockIdx.x >> 4;
    const int h    = blockIdx.x & 15;
    const int tid  = threadIdx.x;
    const int w    = tid >> 5;
    const int lane = tid & 31;
    const int g    = lane >> 2;       // 0..7
    const int t    = lane & 3;        // 0..3

    // --- preload Q fragments (scaled by dh^-0.5 = 0.125, exact power of 2) ---
    uint32_t qa[8][4];
    {
        const float* Qb = q + ((size_t)bt * 64 + w * 16) * INNERV + h * DHEAD;
        #pragma unroll
        for (int k = 0; k < 8; k++) {
            qa[k][0] = __float_as_uint(Qb[(size_t)g       * INNERV + k * 8 + t]     * 0.125f);
            qa[k][1] = __float_as_uint(Qb[(size_t)(g + 8) * INNERV + k * 8 + t]     * 0.125f);
            qa[k][2] = __float_as_uint(Qb[(size_t)g       * INNERV + k * 8 + t + 4] * 0.125f);
            qa[k][3] = __float_as_uint(Qb[(size_t)(g + 8) * INNERV + k * 8 + t + 4] * 0.125f);
        }
    }

    float out[8][4];
    #pragma unroll
    for (int j = 0; j < 8; j++)
        #pragma unroll
        for (int r = 0; r < 4; r++) out[j][r] = 0.f;
    float m0 = -1e30f, m1 = -1e30f, l0 = 0.f, l1 = 0.f;

    const uint32_t kb0 = smem_u32(&ks[0][0][0]);
    const uint32_t vb0 = smem_u32(&vs[0][0][0]);

    auto load_chunk = [&](int ch, int buf) {
        const float* base;
        if (ch < 32) base = kvm + ((size_t)bt * 1024 + ch * 32) * 2048 + h * DHEAD;
        else         base = kvl + ((size_t)bt * 64 + (ch - 32) * 32) * 2048 + h * DHEAD;
        #pragma unroll
        for (int p = 0; p < 4; p++) {
            int idx = p * 128 + tid;          // 512 float4 for K (and V)
            int r   = idx >> 4;
            int c4  = (idx & 15) << 2;
            cp_async16(kb0 + ((buf * 32 + r) * 68 + c4) * 4,
                       base + (size_t)r * 2048 + c4);
            cp_async16(vb0 + ((buf * 32 + r) * 72 + c4) * 4,
                       base + (size_t)r * 2048 + 1024 + c4);
        }
    };

    load_chunk(0, 0);
    cp_commit();

    for (int ch = 0; ch < 34; ch++) {
        const int buf = ch & 1;
        if (ch + 1 < 34) {
            load_chunk(ch + 1, buf ^ 1);
            cp_commit();
            cp_wait1();
        } else {
            cp_wait0();
        }
        __syncthreads();

        // --- QK^T: sim[4 kv-tiles][4] ---
        float sim[4][4];
        #pragma unroll
        for (int j = 0; j < 4; j++)
            #pragma unroll
            for (int r = 0; r < 4; r++) sim[j][r] = 0.f;
        #pragma unroll
        for (int k = 0; k < 8; k++) {
            #pragma unroll
            for (int j = 0; j < 4; j++) {
                uint32_t b0 = __float_as_uint(ks[buf][8 * j + g][k * 8 + t]);
                uint32_t b1 = __float_as_uint(ks[buf][8 * j + g][k * 8 + t + 4]);
                mma_tf32(sim[j][0], sim[j][1], sim[j][2], sim[j][3],
                         qa[k][0], qa[k][1], qa[k][2], qa[k][3], b0, b1);
            }
        }

        // --- online softmax on fragments (rows g, g+8; quad = same g) ---
        float cm0 = -1e30f, cm1 = -1e30f;
        #pragma unroll
        for (int j = 0; j < 4; j++) {
            cm0 = fmaxf(cm0, fmaxf(sim[j][0], sim[j][1]));
            cm1 = fmaxf(cm1, fmaxf(sim[j][2], sim[j][3]));
        }
        cm0 = fmaxf(cm0, __shfl_xor_sync(0xffffffffu, cm0, 1));
        cm0 = fmaxf(cm0, __shfl_xor_sync(0xffffffffu, cm0, 2));
        cm1 = fmaxf(cm1, __shfl_xor_sync(0xffffffffu, cm1, 1));
        cm1 = fmaxf(cm1, __shfl_xor_sync(0xffffffffu, cm1, 2));
        float mt0 = fmaxf(m0, cm0), mt1 = fmaxf(m1, cm1);
        float corr0 = __expf(m0 - mt0), corr1 = __expf(m1 - mt1);
        float rs0 = 0.f, rs1 = 0.f;
        #pragma unroll
        for (int j = 0; j < 4; j++) {
            sim[j][0] = __expf(sim[j][0] - mt0);
            sim[j][1] = __expf(sim[j][1] - mt0);
            sim[j][2] = __expf(sim[j][2] - mt1);
            sim[j][3] = __expf(sim[j][3] - mt1);
            rs0 += sim[j][0] + sim[j][1];
            rs1 += sim[j][2] + sim[j][3];
        }
        rs0 += __shfl_xor_sync(0xffffffffu, rs0, 1);
        rs0 += __shfl_xor_sync(0xffffffffu, rs0, 2);
        rs1 += __shfl_xor_sync(0xffffffffu, rs1, 1);
        rs1 += __shfl_xor_sync(0xffffffffu, rs1, 2);
        l0 = l0 * corr0 + rs0;  m0 = mt0;
        l1 = l1 * corr1 + rs1;  m1 = mt1;
        #pragma unroll
        for (int j = 0; j < 8; j++) {
            out[j][0] *= corr0; out[j][1] *= corr0;
            out[j][2] *= corr1; out[j][3] *= corr1;
        }

        // --- stage P in per-warp smem ---
        #pragma unroll
        for (int j = 0; j < 4; j++) {
            *(float2*)&ps[w][g][8 * j + 2 * t]     = make_float2(sim[j][0], sim[j][1]);
            *(float2*)&ps[w][g + 8][8 * j + 2 * t] = make_float2(sim[j][2], sim[j][3]);
        }
        __syncwarp();

        // --- P @ V ---
        #pragma unroll
        for (int k = 0; k < 4; k++) {
            uint32_t a0 = __float_as_uint(ps[w][g][k * 8 + t]);
            uint32_t a1 = __float_as_uint(ps[w][g + 8][k * 8 + t]);
            uint32_t a2 = __float_as_uint(ps[w][g][k * 8 + t + 4]);
            uint32_t a3 = __float_as_uint(ps[w][g + 8][k * 8 + t + 4]);
            #pragma unroll
            for (int j = 0; j < 8; j++) {
                uint32_t b0 = __float_as_uint(vs[buf][k * 8 + t][8 * j + g]);
                uint32_t b1 = __float_as_uint(vs[buf][k * 8 + t + 4][8 * j + g]);
                mma_tf32(out[j][0], out[j][1], out[j][2], out[j][3],
                         a0, a1, a2, a3, b0, b1);
            }
        }
        __syncthreads();   // protect ks/vs buffer reuse by next load
    }

    // --- epilogue: rows bt*64 + w*16 + g (+8), cols h*64 + 8j + 2t ---
    float inv0 = 1.f / l0, inv1 = 1.f / l1;
    float* O0 = outp + ((size_t)bt * 64 + w * 16 + g)     * INNERV + h * DHEAD;
    float* O1 = outp + ((size_t)bt * 64 + w * 16 + g + 8) * INNERV + h * DHEAD;
    #pragma unroll
    for (int j = 0; j < 8; j++) {
        float2 o0, o1;
        o0.x = tf32r(out[j][0] * inv0);  o0.y = tf32r(out[j][1] * inv0);
        o1.x = tf32r(out[j][2] * inv1);  o1.y = tf32r(out[j][3] * inv1);
        *(float2*)(O0 + 8 * j + 2 * t) = o0;
        *(float2*)(O1 + 8 * j + 2 * t) = o1;
    }
}

// ---------------------------------------------------------------------------
// Host orchestration
// ---------------------------------------------------------------------------
extern "C" void kernel_launch(void* const* d_in, const int* in_sizes, int n_in,
                              void* d_out, int out_size)
{
    const float* x       = (const float*)d_in[0];
    const float* latents = (const float*)d_in[1];
    const float* nm_g    = (const float*)d_in[2];
    const float* nm_b    = (const float*)d_in[3];
    const float* nl_g    = (const float*)d_in[4];
    const float* nl_b    = (const float*)d_in[5];
    const float* wq      = (const float*)d_in[6];
    const float* wkv     = (const float*)d_in[7];
    const float* wo      = (const float*)d_in[8];
    const float* ff_g    = (const float*)d_in[9];
    const float* ff_b    = (const float*)d_in[10];
    const float* w1      = (const float*)d_in[11];
    const float* w2      = (const float*)d_in[12];
    const float* fin_g   = (const float*)d_in[13];
    const float* fin_b   = (const float*)d_in[14];

    float *xhat, *kvm, *lat, *latn, *qb, *kvl, *attn, *ffh;
    float *wkvR, *wkvRl, *wqR, *woR, *w1R, *w2R, *kvbias;
    cudaGetSymbolAddress((void**)&xhat,  g_xhat);
    cudaGetSymbolAddress((void**)&kvm,   g_kvm);
    cudaGetSymbolAddress((void**)&lat,   g_lat);
    cudaGetSymbolAddress((void**)&latn,  g_latn);
    cudaGetSymbolAddress((void**)&qb,    g_qb);
    cudaGetSymbolAddress((void**)&kvl,   g_kvl);
    cudaGetSymbolAddress((void**)&attn,  g_attn);
    cudaGetSymbolAddress((void**)&ffh,   g_ffh);
    cudaGetSymbolAddress((void**)&wkvR,  g_wkvR);
    cudaGetSymbolAddress((void**)&wkvRl, g_wkvRl);
    cudaGetSymbolAddress((void**)&wqR,   g_wqR);
    cudaGetSymbolAddress((void**)&woR,   g_woR);
    cudaGetSymbolAddress((void**)&w1R,   g_w1R);
    cudaGetSymbolAddress((void**)&w2R,   g_w2R);
    cudaGetSymbolAddress((void**)&kvbias, g_kvbias);

    const int SMEM_44 = (2 * 128 * PADK + 2 * 32 * 136) * 4;   // 71680
    const int SMEM_24 = (2 *  64 * PADK + 2 * 32 * 136) * 4;   // 53248
    cudaFuncSetAttribute(gemm_mma<4,4>, cudaFuncAttributeMaxDynamicSharedMemorySize, SMEM_44);
    cudaFuncSetAttribute(gemm_mma<2,4>, cudaFuncAttributeMaxDynamicSharedMemorySize, SMEM_24);

    // ---- preproc ----
    wround_kernel<<<(NDEPTH * DIMV * 2 * INNERV) / 1024, 256>>>(
        wkv, wkvR, DIMV * 2 * INNERV, 2 * INNERV, nm_g);
    ln_kernel<<<BTV * MEDIA, 256>>>(x, xhat, nullptr, nullptr, 1);
    init_lat_kernel<<<2048, 256>>>(latents, lat);
    wround_kernel<<<(NDEPTH * DIMV * 2 * INNERV) / 1024, 256>>>(
        wkv, wkvRl, DIMV * 2 * INNERV, 2 * INNERV, nullptr);
    bias_kernel<<<dim3(2 * INNERV / 256, NDEPTH), 256>>>(
        nm_b, wkv, kvbias, DIMV, 2 * INNERV);
    // layer-0 media KV projection (early so ncu -s lands on it with luck)
    gemm_mma<4,4><<<dim3(16, 256), 256, SMEM_44>>>(
        xhat, wkvR, kvm, DIMV, DIMV, 2 * INNERV, 2 * INNERV,
        kvbias, nullptr, 0, 0);
    wround_kernel<<<(NDEPTH * DIMV * INNERV) / 1024, 256>>>(
        wq, wqR, DIMV * INNERV, INNERV, nullptr);
    wround_kernel<<<(NDEPTH * INNERV * DIMV) / 1024, 256>>>(
        wo, woR, INNERV * DIMV, DIMV, nullptr);
    wround_kernel<<<(NDEPTH * DIMV * FFV) / 1024, 256>>>(
        w1, w1R, DIMV * FFV, FFV, nullptr);
    wround_kernel<<<(NDEPTH * FFV * DIMV) / 1024, 256>>>(
        w2, w2R, FFV * DIMV, DIMV, nullptr);

    for (int i = 0; i < NDEPTH; i++) {
        const float* wkvR_i  = wkvR  + (size_t)i * DIMV * 2 * INNERV;
        const float* wkvRl_i = wkvRl + (size_t)i * DIMV * 2 * INNERV;
        const float* wqR_i   = wqR   + (size_t)i * DIMV * INNERV;
        const float* woR_i   = woR   + (size_t)i * INNERV * DIMV;
        const float* w1R_i   = w1R   + (size_t)i * DIMV * FFV;
        const float* w2R_i   = w2R   + (size_t)i * FFV * DIMV;
        const float* kvb_i   = kvbias + (size_t)i * 2 * INNERV;

        if (i > 0) {
            gemm_mma<4,4><<<dim3(16, 256), 256, SMEM_44>>>(
                xhat, wkvR_i, kvm, DIMV, DIMV, 2 * INNERV, 2 * INNERV,
                kvb_i, nullptr, 0, 0);
        }

        ln_kernel<<<BTV * NLAT, 256>>>(lat, latn,
            nl_g + (size_t)i * DIMV, nl_b + (size_t)i * DIMV, 1);
        gemm_mma<2,4><<<dim3(8, 32), 256, SMEM_24>>>(
            latn, wqR_i, qb, DIMV, DIMV, INNERV, INNERV,
            nullptr, nullptr, 0, 0);
        gemm_mma<2,4><<<dim3(16, 32), 256, SMEM_24>>>(
            latn, wkvRl_i, kvl, DIMV, DIMV, 2 * INNERV, 2 * INNERV,
            nullptr, nullptr, 0, 0);

        attn_mma_kernel<<<BTV * NHEADS, 128>>>(qb, kvm, kvl, attn);

        gemm_mma<2,4><<<dim3(8, 32), 256, SMEM_24>>>(
            attn, woR_i, lat, INNERV, INNERV, DIMV, DIMV,
            nullptr, lat, 0, 0);

        ln_kernel<<<BTV * NLAT, 256>>>(lat, latn,
            ff_g + (size_t)i * DIMV, ff_b + (size_t)i * DIMV, 1);
        gemm_mma<2,4><<<dim3(32, 32), 256, SMEM_24>>>(
            latn, w1R_i, ffh, DIMV, DIMV, FFV, FFV,
            nullptr, nullptr, 1, 1);
        gemm_mma<2,4><<<dim3(8, 32), 256, SMEM_24>>>(
            ffh, w2R_i, lat, FFV, FFV, DIMV, DIMV,
            nullptr, lat, 0, 0);
    }

    ln_kernel<<<BTV * NLAT, 256>>>(lat, (float*)d_out, fin_g, fin_b, 0);
}

// round 6
// speedup vs baseline: 2.1482x; 1.6365x over previous
#include <cuda_runtime.h>
#include <cuda_fp16.h>
#include <math.h>
#include <cstdint>

// ---------------------------------------------------------------------------
// Problem constants (PerceiverResampler)
// ---------------------------------------------------------------------------
#define DIMV   1024
#define NDEPTH 6
#define NHEADS 16
#define DHEAD  64
#define INNERV 1024
#define NLAT   64
#define FFV    4096
#define BTV    32
#define MEDIA  1024
#define LNEPS  1e-5f

// ---------------------------------------------------------------------------
// Scratch (static device allocations)
// ---------------------------------------------------------------------------
__device__ __half g_xhat[(size_t)BTV * MEDIA * DIMV];          // half A-operand
__device__ float  g_kvm [(size_t)BTV * MEDIA * 2 * INNERV];    // fp32 (attention)
__device__ float  g_lat [(size_t)BTV * NLAT * DIMV];
__device__ __half g_latn[(size_t)BTV * NLAT * DIMV];
__device__ float  g_qb  [(size_t)BTV * NLAT * INNERV];
__device__ float  g_kvl [(size_t)BTV * NLAT * 2 * INNERV];
__device__ __half g_attn[(size_t)BTV * NLAT * INNERV];
__device__ __half g_ffh [(size_t)BTV * NLAT * FFV];
// k-pair-packed half weights: u32[k/2][n] = {w[k][n], w[k+1][n]}
__device__ uint32_t g_wkvP [(size_t)NDEPTH * (DIMV/2) * 2 * INNERV];  // scaled by nm_g
__device__ uint32_t g_wkvPl[(size_t)NDEPTH * (DIMV/2) * 2 * INNERV];  // plain
__device__ uint32_t g_wqP  [(size_t)NDEPTH * (DIMV/2) * INNERV];
__device__ uint32_t g_woP  [(size_t)NDEPTH * (INNERV/2) * DIMV];
__device__ uint32_t g_w1P  [(size_t)NDEPTH * (DIMV/2) * FFV];
__device__ uint32_t g_w2P  [(size_t)NDEPTH * (FFV/2) * DIMV];
__device__ float g_kvbias[(size_t)NDEPTH * 2 * INNERV];               // nm_b @ wkv

// ---------------------------------------------------------------------------
// helpers
// ---------------------------------------------------------------------------
__device__ __forceinline__ uint32_t smem_u32(const void* p) {
    uint32_t a;
    asm("{ .reg .u64 t; cvta.to.shared.u64 t, %1; cvt.u32.u64 %0, t; }"
        : "=r"(a) : "l"(p));
    return a;
}
__device__ __forceinline__ void cp_async16(uint32_t dst, const void* src) {
    asm volatile("cp.async.cg.shared.global [%0], [%1], 16;" :: "r"(dst), "l"(src));
}
__device__ __forceinline__ void cp_commit() {
    asm volatile("cp.async.commit_group;" ::: "memory");
}
__device__ __forceinline__ void cp_wait1() {
    asm volatile("cp.async.wait_group 1;" ::: "memory");
}
__device__ __forceinline__ void cp_wait0() {
    asm volatile("cp.async.wait_group 0;" ::: "memory");
}
// fp16 x fp16 -> fp32 acc
__device__ __forceinline__ void mma_f16(float& c0, float& c1, float& c2, float& c3,
                                        uint32_t a0, uint32_t a1, uint32_t a2, uint32_t a3,
                                        uint32_t b0, uint32_t b1) {
    asm volatile(
        "mma.sync.aligned.m16n8k16.row.col.f32.f16.f16.f32 "
        "{%0,%1,%2,%3}, {%4,%5,%6,%7}, {%8,%9}, {%0,%1,%2,%3};"
        : "+f"(c0), "+f"(c1), "+f"(c2), "+f"(c3)
        : "r"(a0), "r"(a1), "r"(a2), "r"(a3), "r"(b0), "r"(b1));
}
// tf32 path kept for the attention kernel (unchanged from R5)
__device__ __forceinline__ void mma_tf32(float& c0, float& c1, float& c2, float& c3,
                                         uint32_t a0, uint32_t a1, uint32_t a2, uint32_t a3,
                                         uint32_t b0, uint32_t b1) {
    asm volatile(
        "mma.sync.aligned.m16n8k8.row.col.f32.tf32.tf32.f32 "
        "{%0,%1,%2,%3}, {%4,%5,%6,%7}, {%8,%9}, {%0,%1,%2,%3};"
        : "+f"(c0), "+f"(c1), "+f"(c2), "+f"(c3)
        : "r"(a0), "r"(a1), "r"(a2), "r"(a3), "r"(b0), "r"(b1));
}
__device__ __forceinline__ void ldsm4(uint32_t* r, uint32_t addr) {
    asm volatile("ldmatrix.sync.aligned.m8n8.x4.shared.b16 {%0,%1,%2,%3}, [%4];"
                 : "=r"(r[0]), "=r"(r[1]), "=r"(r[2]), "=r"(r[3]) : "r"(addr));
}
__device__ __forceinline__ float gelu_exact(float x) {
    return 0.5f * x * (1.0f + erff(x * 0.70710678118654752f));
}

// ---------------------------------------------------------------------------
// Weight pack: out32[layer][k2][n] = half2( in[layer][2k2][n]*s(2k2), in[layer][2k2+1][n]*s(2k2+1) )
// ---------------------------------------------------------------------------
__global__ void __launch_bounds__(256) wpack_kernel(
    const float* __restrict__ in, uint32_t* __restrict__ out,
    int K2N, int N, int K, const float* __restrict__ scale)
{
    int idx = blockIdx.x * 256 + threadIdx.x;
    int layer = idx / K2N;
    int rem   = idx - layer * K2N;
    int k2 = rem / N;
    int n  = rem - k2 * N;
    const float* base = in + ((size_t)layer * K + 2 * k2) * N + n;
    float v0 = base[0], v1 = base[N];
    if (scale) {
        v0 *= scale[layer * K + 2 * k2];
        v1 *= scale[layer * K + 2 * k2 + 1];
    }
    __half2 h = __floats2half2_rn(v0, v1);
    out[idx] = *(uint32_t*)&h;
}

// ---------------------------------------------------------------------------
// bias[layer][n] = sum_k b[layer][k] * W[layer][k][n]  (fp32)
// ---------------------------------------------------------------------------
__global__ void __launch_bounds__(256) bias_kernel(
    const float* __restrict__ b, const float* __restrict__ W,
    float* __restrict__ out, int K, int N)
{
    int layer = blockIdx.y;
    int n = blockIdx.x * 256 + threadIdx.x;
    const float* Wl = W + (size_t)layer * K * N;
    const float* bl = b + (size_t)layer * K;
    float s = 0.f;
    for (int k = 0; k < K; k++) s = fmaf(bl[k], Wl[(size_t)k * N + n], s);
    out[(size_t)layer * N + n] = s;
}

// ---------------------------------------------------------------------------
// lat broadcast
// ---------------------------------------------------------------------------
__global__ void __launch_bounds__(256) init_lat_kernel(
    const float* __restrict__ latents, float* __restrict__ lat)
{
    int idx4 = blockIdx.x * 256 + threadIdx.x;
    int row  = idx4 >> 8;
    int c4   = idx4 & 255;
    int n    = row & 63;
    float4 v = *(const float4*)(latents + (size_t)n * DIMV + (c4 << 2));
    *(float4*)(lat + ((size_t)row << 10) + (c4 << 2)) = v;
}

// ---------------------------------------------------------------------------
// LayerNorm rows of 1024.  outHalf: write __half (GEMM A operand) else float.
// ---------------------------------------------------------------------------
__global__ void __launch_bounds__(256) ln_kernel(
    const float* __restrict__ in, void* __restrict__ out,
    const float* __restrict__ g, const float* __restrict__ b, int outHalf)
{
    __shared__ float red[2][8];
    size_t row = blockIdx.x;
    const float* x = in + row * DIMV;
    int t = threadIdx.x;

    float4 v = *(const float4*)(x + (t << 2));
    float s  = v.x + v.y + v.z + v.w;
    float ss = v.x*v.x + v.y*v.y + v.z*v.z + v.w*v.w;
    #pragma unroll
    for (int off = 16; off; off >>= 1) {
        s  += __shfl_xor_sync(0xffffffffu, s,  off);
        ss += __shfl_xor_sync(0xffffffffu, ss, off);
    }
    int w = t >> 5, lane = t & 31;
    if (lane == 0) { red[0][w] = s; red[1][w] = ss; }
    __syncthreads();
    if (t == 0) {
        float ts = 0.f, tss = 0.f;
        #pragma unroll
        for (int i = 0; i < 8; i++) { ts += red[0][i]; tss += red[1][i]; }
        red[0][0] = ts; red[1][0] = tss;
    }
    __syncthreads();
    float mean = red[0][0] * (1.f / 1024.f);
    float var  = red[1][0] * (1.f / 1024.f) - mean * mean;
    float inv  = rsqrtf(var + LNEPS);

    float gx = 1.f, gy = 1.f, gz = 1.f, gw = 1.f;
    float bx = 0.f, by = 0.f, bz = 0.f, bw = 0.f;
    if (g) {
        float4 gg = *(const float4*)(g + (t << 2));
        float4 bb = *(const float4*)(b + (t << 2));
        gx = gg.x; gy = gg.y; gz = gg.z; gw = gg.w;
        bx = bb.x; by = bb.y; bz = bb.z; bw = bb.w;
    }
    float4 o;
    o.x = (v.x - mean) * inv * gx + bx;
    o.y = (v.y - mean) * inv * gy + by;
    o.z = (v.z - mean) * inv * gz + bz;
    o.w = (v.w - mean) * inv * gw + bw;
    if (outHalf) {
        __half2* oh = (__half2*)((__half*)out + row * DIMV + (t << 2));
        oh[0] = __floats2half2_rn(o.x, o.y);
        oh[1] = __floats2half2_rn(o.z, o.w);
    } else {
        *(float4*)((float*)out + row * DIMV + (t << 2)) = o;
    }
}

// ---------------------------------------------------------------------------
// fp16 mma.sync GEMM:  C[M,N] = op( A[M,K] @ B[K,N] (+bias[n]) (+resid) )
//   A: __half row-major [M,K].  B: k-pair packed u32[K/2][N].
//   Block: BM = 32*IM (IM=4 -> 128, IM=2 -> 64), BN = 128 fixed.
//   8 warps (2m x 4n); warp tile (IM*16) x 32.  BK=32, 2-stage cp.async.
//   A frags via ldmatrix.x4 (smem stride 40 halves); B frags 2x LDS.32
//   (smem stride 136 u32 == 8 mod 32 -> conflict-free).
//   flags: 1 = gelu epilogue, 2 = output __half.
// ---------------------------------------------------------------------------
#define SA 40     // A smem row stride in halves
#define SB 136    // B smem row stride in u32
template <int IM>
__global__ void __launch_bounds__(256, (IM == 4) ? 2 : 3) gemm_h(
    const __half* __restrict__ A, const uint32_t* __restrict__ Bp, void* __restrict__ Cv,
    int K, int lda, int ldbn, int ldc,
    const float* __restrict__ bias, const float* __restrict__ resid, int flags)
{
    constexpr int BM = 32 * IM;
    __shared__ __half   As[2][BM][SA];
    __shared__ uint32_t Bs[2][16][SB];

    const int tid  = threadIdx.x;
    const int wid  = tid >> 5;
    const int lane = tid & 31;
    const int wm   = wid >> 2;          // 0..1
    const int wn   = wid & 3;           // 0..3
    const int g    = lane >> 2;         // 0..7
    const int t    = lane & 3;          // 0..3
    const int m0   = blockIdx.y * BM;
    const int n0   = blockIdx.x * 128;
    const int NK   = K >> 5;
    const int wbase = wm * (IM * 16);
    // ldmatrix lane geometry
    const int lrow = (lane & 7) + ((lane >> 3) & 1) * 8;   // 0..15
    const int lcol = (lane >> 4) * 8;                      // 0 or 8 (halves)

    const uint32_t aBase = smem_u32(&As[0][0][0]);
    const uint32_t bBase = smem_u32(&Bs[0][0][0]);

    float acc[IM][4][4];
    #pragma unroll
    for (int i = 0; i < IM; i++)
        #pragma unroll
        for (int j = 0; j < 4; j++)
            #pragma unroll
            for (int r = 0; r < 4; r++) acc[i][j][r] = 0.f;

    auto load_tile = [&](int kt, int buf) {
        const int kg = kt << 5;
        // A: BM rows x 64B -> BM*4 cp16
        #pragma unroll
        for (int p = 0; p < IM / 2; p++) {
            int idx = p * 256 + tid;
            int row = idx >> 2;
            int c   = (idx & 3) << 3;     // halves
            cp_async16(aBase + ((buf * BM + row) * SA + c) * 2,
                       A + (size_t)(m0 + row) * lda + kg + c);
        }
        // B: 16 k2-rows x 128 u32 -> 512 cp16
        #pragma unroll
        for (int p = 0; p < 2; p++) {
            int idx = p * 256 + tid;
            int r   = idx >> 5;
            int c4  = (idx & 31) << 2;    // u32
            cp_async16(bBase + ((buf * 16 + r) * SB + c4) * 4,
                       Bp + (size_t)((kg >> 1) + r) * ldbn + n0 + c4);
        }
    };

    load_tile(0, 0);
    cp_commit();

    for (int kt = 0; kt < NK; kt++) {
        const int buf = kt & 1;
        if (kt + 1 < NK) {
            load_tile(kt + 1, buf ^ 1);
            cp_commit();
            cp_wait1();
        } else {
            cp_wait0();
        }
        __syncthreads();

        #pragma unroll
        for (int c = 0; c < 2; c++) {          // two k16 chunks per BK=32
            const int koff  = c << 4;          // halves
            const int k2off = c << 3;          // u32 rows
            uint32_t af[IM][4], bf[4][2];
            #pragma unroll
            for (int i = 0; i < IM; i++) {
                uint32_t addr = aBase +
                    ((uint32_t)(buf * BM + wbase + i * 16 + lrow) * SA + koff + lcol) * 2;
                ldsm4(af[i], addr);
            }
            #pragma unroll
            for (int j = 0; j < 4; j++) {
                const int col = wn * 32 + j * 8 + g;
                bf[j][0] = Bs[buf][k2off + t][col];
                bf[j][1] = Bs[buf][k2off + t + 4][col];
            }
            #pragma unroll
            for (int i = 0; i < IM; i++)
                #pragma unroll
                for (int j = 0; j < 4; j++)
                    mma_f16(acc[i][j][0], acc[i][j][1], acc[i][j][2], acc[i][j][3],
                            af[i][0], af[i][1], af[i][2], af[i][3],
                            bf[j][0], bf[j][1]);
        }
        __syncthreads();
    }

    // epilogue
    const int doGelu  = flags & 1;
    const int outHalf = flags & 2;
    #pragma unroll
    for (int i = 0; i < IM; i++) {
        int mrow = m0 + wbase + i * 16 + g;
        #pragma unroll
        for (int j = 0; j < 4; j++) {
            int ncol = n0 + wn * 32 + j * 8 + 2 * t;
            #pragma unroll
            for (int half = 0; half < 2; half++) {
                int mr = mrow + half * 8;
                float c0 = acc[i][j][2 * half + 0];
                float c1 = acc[i][j][2 * half + 1];
                if (bias) {
                    float2 bv = *(const float2*)(bias + ncol);
                    c0 += bv.x; c1 += bv.y;
                }
                if (resid) {
                    float2 rv = *(const float2*)(resid + (size_t)mr * ldc + ncol);
                    c0 += rv.x; c1 += rv.y;
                }
                if (doGelu) { c0 = gelu_exact(c0); c1 = gelu_exact(c1); }
                if (outHalf) {
                    *(__half2*)((__half*)Cv + (size_t)mr * ldc + ncol) =
                        __floats2half2_rn(c0, c1);
                } else {
                    float2 o; o.x = c0; o.y = c1;
                    *(float2*)((float*)Cv + (size_t)mr * ldc + ncol) = o;
                }
            }
        }
    }
}

// ---------------------------------------------------------------------------
// Tensor-core attention (tf32 mma, unchanged math from R5).
// Inputs qb/kvm/kvl fp32; output written as __half (wo GEMM A operand).
// ---------------------------------------------------------------------------
__global__ void __launch_bounds__(128, 4) attn_mma_kernel(
    const float* __restrict__ q,   const float* __restrict__ kvm,
    const float* __restrict__ kvl, __half* __restrict__ outp)
{
    __shared__ float ks[2][32][68];
    __shared__ float vs[2][32][72];
    __shared__ float ps[4][16][36];

    const int bt   = blockIdx.x >> 4;
    const int h    = blockIdx.x & 15;
    const int tid  = threadIdx.x;
    const int w    = tid >> 5;
    const int lane = tid & 31;
    const int g    = lane >> 2;
    const int t    = lane & 3;

    uint32_t qa[8][4];
    {
        const float* Qb = q + ((size_t)bt * 64 + w * 16) * INNERV + h * DHEAD;
        #pragma unroll
        for (int k = 0; k < 8; k++) {
            qa[k][0] = __float_as_uint(Qb[(size_t)g       * INNERV + k * 8 + t]     * 0.125f);
            qa[k][1] = __float_as_uint(Qb[(size_t)(g + 8) * INNERV + k * 8 + t]     * 0.125f);
            qa[k][2] = __float_as_uint(Qb[(size_t)g       * INNERV + k * 8 + t + 4] * 0.125f);
            qa[k][3] = __float_as_uint(Qb[(size_t)(g + 8) * INNERV + k * 8 + t + 4] * 0.125f);
        }
    }

    float out[8][4];
    #pragma unroll
    for (int j = 0; j < 8; j++)
        #pragma unroll
        for (int r = 0; r < 4; r++) out[j][r] = 0.f;
    float m0 = -1e30f, m1 = -1e30f, l0 = 0.f, l1 = 0.f;

    const uint32_t kb0 = smem_u32(&ks[0][0][0]);
    const uint32_t vb0 = smem_u32(&vs[0][0][0]);

    auto load_chunk = [&](int ch, int buf) {
        const float* base;
        if (ch < 32) base = kvm + ((size_t)bt * 1024 + ch * 32) * 2048 + h * DHEAD;
        else         base = kvl + ((size_t)bt * 64 + (ch - 32) * 32) * 2048 + h * DHEAD;
        #pragma unroll
        for (int p = 0; p < 4; p++) {
            int idx = p * 128 + tid;
            int r   = idx >> 4;
            int c4  = (idx & 15) << 2;
            cp_async16(kb0 + ((buf * 32 + r) * 68 + c4) * 4,
                       base + (size_t)r * 2048 + c4);
            cp_async16(vb0 + ((buf * 32 + r) * 72 + c4) * 4,
                       base + (size_t)r * 2048 + 1024 + c4);
        }
    };

    load_chunk(0, 0);
    cp_commit();

    for (int ch = 0; ch < 34; ch++) {
        const int buf = ch & 1;
        if (ch + 1 < 34) {
            load_chunk(ch + 1, buf ^ 1);
            cp_commit();
            cp_wait1();
        } else {
            cp_wait0();
        }
        __syncthreads();

        float sim[4][4];
        #pragma unroll
        for (int j = 0; j < 4; j++)
            #pragma unroll
            for (int r = 0; r < 4; r++) sim[j][r] = 0.f;
        #pragma unroll
        for (int k = 0; k < 8; k++) {
            #pragma unroll
            for (int j = 0; j < 4; j++) {
                uint32_t b0 = __float_as_uint(ks[buf][8 * j + g][k * 8 + t]);
                uint32_t b1 = __float_as_uint(ks[buf][8 * j + g][k * 8 + t + 4]);
                mma_tf32(sim[j][0], sim[j][1], sim[j][2], sim[j][3],
                         qa[k][0], qa[k][1], qa[k][2], qa[k][3], b0, b1);
            }
        }

        float cm0 = -1e30f, cm1 = -1e30f;
        #pragma unroll
        for (int j = 0; j < 4; j++) {
            cm0 = fmaxf(cm0, fmaxf(sim[j][0], sim[j][1]));
            cm1 = fmaxf(cm1, fmaxf(sim[j][2], sim[j][3]));
        }
        cm0 = fmaxf(cm0, __shfl_xor_sync(0xffffffffu, cm0, 1));
        cm0 = fmaxf(cm0, __shfl_xor_sync(0xffffffffu, cm0, 2));
        cm1 = fmaxf(cm1, __shfl_xor_sync(0xffffffffu, cm1, 1));
        cm1 = fmaxf(cm1, __shfl_xor_sync(0xffffffffu, cm1, 2));
        float mt0 = fmaxf(m0, cm0), mt1 = fmaxf(m1, cm1);
        float corr0 = __expf(m0 - mt0), corr1 = __expf(m1 - mt1);
        float rs0 = 0.f, rs1 = 0.f;
        #pragma unroll
        for (int j = 0; j < 4; j++) {
            sim[j][0] = __expf(sim[j][0] - mt0);
            sim[j][1] = __expf(sim[j][1] - mt0);
            sim[j][2] = __expf(sim[j][2] - mt1);
            sim[j][3] = __expf(sim[j][3] - mt1);
            rs0 += sim[j][0] + sim[j][1];
            rs1 += sim[j][2] + sim[j][3];
        }
        rs0 += __shfl_xor_sync(0xffffffffu, rs0, 1);
        rs0 += __shfl_xor_sync(0xffffffffu, rs0, 2);
        rs1 += __shfl_xor_sync(0xffffffffu, rs1, 1);
        rs1 += __shfl_xor_sync(0xffffffffu, rs1, 2);
        l0 = l0 * corr0 + rs0;  m0 = mt0;
        l1 = l1 * corr1 + rs1;  m1 = mt1;
        #pragma unroll
        for (int j = 0; j < 8; j++) {
            out[j][0] *= corr0; out[j][1] *= corr0;
            out[j][2] *= corr1; out[j][3] *= corr1;
        }

        #pragma unroll
        for (int j = 0; j < 4; j++) {
            *(float2*)&ps[w][g][8 * j + 2 * t]     = make_float2(sim[j][0], sim[j][1]);
            *(float2*)&ps[w][g + 8][8 * j + 2 * t] = make_float2(sim[j][2], sim[j][3]);
        }
        __syncwarp();

        #pragma unroll
        for (int k = 0; k < 4; k++) {
            uint32_t a0 = __float_as_uint(ps[w][g][k * 8 + t]);
            uint32_t a1 = __float_as_uint(ps[w][g + 8][k * 8 + t]);
            uint32_t a2 = __float_as_uint(ps[w][g][k * 8 + t + 4]);
            uint32_t a3 = __float_as_uint(ps[w][g + 8][k * 8 + t + 4]);
            #pragma unroll
            for (int j = 0; j < 8; j++) {
                uint32_t b0 = __float_as_uint(vs[buf][k * 8 + t][8 * j + g]);
                uint32_t b1 = __float_as_uint(vs[buf][k * 8 + t + 4][8 * j + g]);
                mma_tf32(out[j][0], out[j][1], out[j][2], out[j][3],
                         a0, a1, a2, a3, b0, b1);
            }
        }
        __syncthreads();
    }

    float inv0 = 1.f / l0, inv1 = 1.f / l1;
    __half* O0 = outp + ((size_t)bt * 64 + w * 16 + g)     * INNERV + h * DHEAD;
    __half* O1 = outp + ((size_t)bt * 64 + w * 16 + g + 8) * INNERV + h * DHEAD;
    #pragma unroll
    for (int j = 0; j < 8; j++) {
        *(__half2*)(O0 + 8 * j + 2 * t) = __floats2half2_rn(out[j][0] * inv0, out[j][1] * inv0);
        *(__half2*)(O1 + 8 * j + 2 * t) = __floats2half2_rn(out[j][2] * inv1, out[j][3] * inv1);
    }
}

// ---------------------------------------------------------------------------
// Host orchestration
// ---------------------------------------------------------------------------
extern "C" void kernel_launch(void* const* d_in, const int* in_sizes, int n_in,
                              void* d_out, int out_size)
{
    const float* x       = (const float*)d_in[0];
    const float* latents = (const float*)d_in[1];
    const float* nm_g    = (const float*)d_in[2];
    const float* nm_b    = (const float*)d_in[3];
    const float* nl_g    = (const float*)d_in[4];
    const float* nl_b    = (const float*)d_in[5];
    const float* wq      = (const float*)d_in[6];
    const float* wkv     = (const float*)d_in[7];
    const float* wo      = (const float*)d_in[8];
    const float* ff_g    = (const float*)d_in[9];
    const float* ff_b    = (const float*)d_in[10];
    const float* w1      = (const float*)d_in[11];
    const float* w2      = (const float*)d_in[12];
    const float* fin_g   = (const float*)d_in[13];
    const float* fin_b   = (const float*)d_in[14];

    __half *xhat, *latn, *attnH, *ffh;
    float *kvm, *lat, *qb, *kvl, *kvbias;
    uint32_t *wkvP, *wkvPl, *wqP, *woP, *w1P, *w2P;
    cudaGetSymbolAddress((void**)&xhat,  g_xhat);
    cudaGetSymbolAddress((void**)&kvm,   g_kvm);
    cudaGetSymbolAddress((void**)&lat,   g_lat);
    cudaGetSymbolAddress((void**)&latn,  g_latn);
    cudaGetSymbolAddress((void**)&qb,    g_qb);
    cudaGetSymbolAddress((void**)&kvl,   g_kvl);
    cudaGetSymbolAddress((void**)&attnH, g_attn);
    cudaGetSymbolAddress((void**)&ffh,   g_ffh);
    cudaGetSymbolAddress((void**)&wkvP,  g_wkvP);
    cudaGetSymbolAddress((void**)&wkvPl, g_wkvPl);
    cudaGetSymbolAddress((void**)&wqP,   g_wqP);
    cudaGetSymbolAddress((void**)&woP,   g_woP);
    cudaGetSymbolAddress((void**)&w1P,   g_w1P);
    cudaGetSymbolAddress((void**)&w2P,   g_w2P);
    cudaGetSymbolAddress((void**)&kvbias, g_kvbias);

    const int K2N_KV = (DIMV / 2) * 2 * INNERV;   // 1048576
    const int K2N_SQ = (DIMV / 2) * INNERV;       // 524288
    const int K2N_W1 = (DIMV / 2) * FFV;          // 2097152
    const int K2N_W2 = (FFV / 2) * DIMV;          // 2097152

    // ---- preproc (ordered so an early launch slot holds the kvm GEMM) ----
    wpack_kernel<<<NDEPTH * K2N_KV / 256, 256>>>(wkv, wkvP, K2N_KV, 2 * INNERV, DIMV, nm_g);
    ln_kernel<<<BTV * MEDIA, 256>>>(x, xhat, nullptr, nullptr, 1);
    bias_kernel<<<dim3(2 * INNERV / 256, NDEPTH), 256>>>(nm_b, wkv, kvbias, DIMV, 2 * INNERV);
    // layer-0 media KV projection: [32768,1024]@[1024,2048] + bias (fp32 out)
    gemm_h<4><<<dim3(16, 256), 256>>>(xhat, wkvP, kvm,
        DIMV, DIMV, 2 * INNERV, 2 * INNERV, kvbias, nullptr, 0);
    init_lat_kernel<<<2048, 256>>>(latents, lat);
    wpack_kernel<<<NDEPTH * K2N_KV / 256, 256>>>(wkv, wkvPl, K2N_KV, 2 * INNERV, DIMV, nullptr);
    wpack_kernel<<<NDEPTH * K2N_SQ / 256, 256>>>(wq, wqP, K2N_SQ, INNERV, DIMV, nullptr);
    wpack_kernel<<<NDEPTH * K2N_SQ / 256, 256>>>(wo, woP, K2N_SQ, DIMV, INNERV, nullptr);
    wpack_kernel<<<NDEPTH * K2N_W1 / 256, 256>>>(w1, w1P, K2N_W1, FFV, DIMV, nullptr);
    wpack_kernel<<<NDEPTH * K2N_W2 / 256, 256>>>(w2, w2P, K2N_W2, DIMV, FFV, nullptr);

    for (int i = 0; i < NDEPTH; i++) {
        const uint32_t* wkvP_i  = wkvP  + (size_t)i * K2N_KV;
        const uint32_t* wkvPl_i = wkvPl + (size_t)i * K2N_KV;
        const uint32_t* wqP_i   = wqP   + (size_t)i * K2N_SQ;
        const uint32_t* woP_i   = woP   + (size_t)i * K2N_SQ;
        const uint32_t* w1P_i   = w1P   + (size_t)i * K2N_W1;
        const uint32_t* w2P_i   = w2P   + (size_t)i * K2N_W2;
        const float*    kvb_i   = kvbias + (size_t)i * 2 * INNERV;

        if (i > 0) {
            gemm_h<4><<<dim3(16, 256), 256>>>(xhat, wkvP_i, kvm,
                DIMV, DIMV, 2 * INNERV, 2 * INNERV, kvb_i, nullptr, 0);
        }

        ln_kernel<<<BTV * NLAT, 256>>>(lat, latn,
            nl_g + (size_t)i * DIMV, nl_b + (size_t)i * DIMV, 1);
        gemm_h<2><<<dim3(8, 32), 256>>>(latn, wqP_i, qb,
            DIMV, DIMV, INNERV, INNERV, nullptr, nullptr, 0);
        gemm_h<2><<<dim3(16, 32), 256>>>(latn, wkvPl_i, kvl,
            DIMV, DIMV, 2 * INNERV, 2 * INNERV, nullptr, nullptr, 0);

        attn_mma_kernel<<<BTV * NHEADS, 128>>>(qb, kvm, kvl, attnH);

        gemm_h<2><<<dim3(8, 32), 256>>>(attnH, woP_i, lat,
            INNERV, INNERV, DIMV, DIMV, nullptr, lat, 0);

        ln_kernel<<<BTV * NLAT, 256>>>(lat, latn,
            ff_g + (size_t)i * DIMV, ff_b + (size_t)i * DIMV, 1);
        gemm_h<2><<<dim3(32, 32), 256>>>(latn, w1P_i, ffh,
            DIMV, DIMV, FFV, FFV, nullptr, nullptr, 1 | 2);
        gemm_h<2><<<dim3(8, 32), 256>>>(ffh, w2P_i, lat,
            FFV, FFV, DIMV, DIMV, nullptr, lat, 0);
    }

    ln_kernel<<<BTV * NLAT, 256>>>(lat, (float*)d_out, fin_g, fin_b, 0);
}

// round 7
// speedup vs baseline: 2.2003x; 1.0242x over previous
#include <cuda_runtime.h>
#include <cuda_fp16.h>
#include <math.h>
#include <cstdint>

// ---------------------------------------------------------------------------
// Problem constants (PerceiverResampler)
// ---------------------------------------------------------------------------
#define DIMV   1024
#define NDEPTH 6
#define NHEADS 16
#define DHEAD  64
#define INNERV 1024
#define NLAT   64
#define FFV    4096
#define BTV    32
#define MEDIA  1024
#define LNEPS  1e-5f

// ---------------------------------------------------------------------------
// Scratch (static device allocations)
// ---------------------------------------------------------------------------
__device__ __half g_xhat[(size_t)BTV * MEDIA * DIMV];
__device__ float  g_kvm [(size_t)BTV * MEDIA * 2 * INNERV];
__device__ float  g_lat [(size_t)BTV * NLAT * DIMV];
__device__ __half g_latn[(size_t)BTV * NLAT * DIMV];
__device__ float  g_qkv [(size_t)BTV * NLAT * 3 * INNERV];    // fused q | kv
__device__ __half g_attn[(size_t)BTV * NLAT * INNERV];
__device__ __half g_ffh [(size_t)BTV * NLAT * FFV];
// k-pair-packed half weights: u32[k/2][n] = {w[k][n], w[k+1][n]}
__device__ uint32_t g_wkvP [(size_t)NDEPTH * (DIMV/2) * 2 * INNERV];   // scaled by nm_g
__device__ uint32_t g_wqkvP[(size_t)NDEPTH * (DIMV/2) * 3 * INNERV];   // wq | wkv plain
__device__ uint32_t g_woP  [(size_t)NDEPTH * (INNERV/2) * DIMV];
__device__ uint32_t g_w1P  [(size_t)NDEPTH * (DIMV/2) * FFV];
__device__ uint32_t g_w2P  [(size_t)NDEPTH * (FFV/2) * DIMV];
__device__ float g_kvbias[(size_t)NDEPTH * 2 * INNERV];                // nm_b @ wkv

// ---------------------------------------------------------------------------
// helpers
// ---------------------------------------------------------------------------
__device__ __forceinline__ uint32_t smem_u32(const void* p) {
    uint32_t a;
    asm("{ .reg .u64 t; cvta.to.shared.u64 t, %1; cvt.u32.u64 %0, t; }"
        : "=r"(a) : "l"(p));
    return a;
}
__device__ __forceinline__ void cp_async16(uint32_t dst, const void* src) {
    asm volatile("cp.async.cg.shared.global [%0], [%1], 16;" :: "r"(dst), "l"(src));
}
__device__ __forceinline__ void cp_commit() {
    asm volatile("cp.async.commit_group;" ::: "memory");
}
__device__ __forceinline__ void cp_wait1() {
    asm volatile("cp.async.wait_group 1;" ::: "memory");
}
__device__ __forceinline__ void cp_wait0() {
    asm volatile("cp.async.wait_group 0;" ::: "memory");
}
__device__ __forceinline__ void mma_f16(float& c0, float& c1, float& c2, float& c3,
                                        uint32_t a0, uint32_t a1, uint32_t a2, uint32_t a3,
                                        uint32_t b0, uint32_t b1) {
    asm volatile(
        "mma.sync.aligned.m16n8k16.row.col.f32.f16.f16.f32 "
        "{%0,%1,%2,%3}, {%4,%5,%6,%7}, {%8,%9}, {%0,%1,%2,%3};"
        : "+f"(c0), "+f"(c1), "+f"(c2), "+f"(c3)
        : "r"(a0), "r"(a1), "r"(a2), "r"(a3), "r"(b0), "r"(b1));
}
__device__ __forceinline__ void mma_tf32(float& c0, float& c1, float& c2, float& c3,
                                         uint32_t a0, uint32_t a1, uint32_t a2, uint32_t a3,
                                         uint32_t b0, uint32_t b1) {
    asm volatile(
        "mma.sync.aligned.m16n8k8.row.col.f32.tf32.tf32.f32 "
        "{%0,%1,%2,%3}, {%4,%5,%6,%7}, {%8,%9}, {%0,%1,%2,%3};"
        : "+f"(c0), "+f"(c1), "+f"(c2), "+f"(c3)
        : "r"(a0), "r"(a1), "r"(a2), "r"(a3), "r"(b0), "r"(b1));
}
__device__ __forceinline__ void ldsm4(uint32_t* r, uint32_t addr) {
    asm volatile("ldmatrix.sync.aligned.m8n8.x4.shared.b16 {%0,%1,%2,%3}, [%4];"
                 : "=r"(r[0]), "=r"(r[1]), "=r"(r[2]), "=r"(r[3]) : "r"(addr));
}
__device__ __forceinline__ float gelu_exact(float x) {
    return 0.5f * x * (1.0f + erff(x * 0.70710678118654752f));
}

// ---------------------------------------------------------------------------
// Weight pack with output stride/offset:
//   out[layer][k2][coloff + n] (row stride ldo) =
//       half2( in[layer][2k2][n]*s, in[layer][2k2+1][n]*s )
// ---------------------------------------------------------------------------
__global__ void __launch_bounds__(256) wpack_kernel(
    const float* __restrict__ in, uint32_t* __restrict__ out,
    int K2N, int N, int K, const float* __restrict__ scale,
    int ldo, int coloff)
{
    int idx = blockIdx.x * 256 + threadIdx.x;
    int layer = idx / K2N;
    int rem   = idx - layer * K2N;
    int k2 = rem / N;
    int n  = rem - k2 * N;
    const float* base = in + ((size_t)layer * K + 2 * k2) * N + n;
    float v0 = base[0], v1 = base[N];
    if (scale) {
        v0 *= scale[layer * K + 2 * k2];
        v1 *= scale[layer * K + 2 * k2 + 1];
    }
    __half2 h = __floats2half2_rn(v0, v1);
    out[((size_t)layer * (K / 2) + k2) * ldo + coloff + n] = *(uint32_t*)&h;
}

// ---------------------------------------------------------------------------
// bias[layer][n] = sum_k b[layer][k] * W[layer][k][n]  (fp32)
// ---------------------------------------------------------------------------
__global__ void __launch_bounds__(256) bias_kernel(
    const float* __restrict__ b, const float* __restrict__ W,
    float* __restrict__ out, int K, int N)
{
    int layer = blockIdx.y;
    int n = blockIdx.x * 256 + threadIdx.x;
    const float* Wl = W + (size_t)layer * K * N;
    const float* bl = b + (size_t)layer * K;
    float s = 0.f;
    for (int k = 0; k < K; k++) s = fmaf(bl[k], Wl[(size_t)k * N + n], s);
    out[(size_t)layer * N + n] = s;
}

// ---------------------------------------------------------------------------
// lat broadcast
// ---------------------------------------------------------------------------
__global__ void __launch_bounds__(256) init_lat_kernel(
    const float* __restrict__ latents, float* __restrict__ lat)
{
    int idx4 = blockIdx.x * 256 + threadIdx.x;
    int row  = idx4 >> 8;
    int c4   = idx4 & 255;
    int n    = row & 63;
    float4 v = *(const float4*)(latents + (size_t)n * DIMV + (c4 << 2));
    *(float4*)(lat + ((size_t)row << 10) + (c4 << 2)) = v;
}

// ---------------------------------------------------------------------------
// LayerNorm rows of 1024.  outHalf: write __half else float.
// ---------------------------------------------------------------------------
__global__ void __launch_bounds__(256) ln_kernel(
    const float* __restrict__ in, void* __restrict__ out,
    const float* __restrict__ g, const float* __restrict__ b, int outHalf)
{
    __shared__ float red[2][8];
    size_t row = blockIdx.x;
    const float* x = in + row * DIMV;
    int t = threadIdx.x;

    float4 v = *(const float4*)(x + (t << 2));
    float s  = v.x + v.y + v.z + v.w;
    float ss = v.x*v.x + v.y*v.y + v.z*v.z + v.w*v.w;
    #pragma unroll
    for (int off = 16; off; off >>= 1) {
        s  += __shfl_xor_sync(0xffffffffu, s,  off);
        ss += __shfl_xor_sync(0xffffffffu, ss, off);
    }
    int w = t >> 5, lane = t & 31;
    if (lane == 0) { red[0][w] = s; red[1][w] = ss; }
    __syncthreads();
    if (t == 0) {
        float ts = 0.f, tss = 0.f;
        #pragma unroll
        for (int i = 0; i < 8; i++) { ts += red[0][i]; tss += red[1][i]; }
        red[0][0] = ts; red[1][0] = tss;
    }
    __syncthreads();
    float mean = red[0][0] * (1.f / 1024.f);
    float var  = red[1][0] * (1.f / 1024.f) - mean * mean;
    float inv  = rsqrtf(var + LNEPS);

    float gx = 1.f, gy = 1.f, gz = 1.f, gw = 1.f;
    float bx = 0.f, by = 0.f, bz = 0.f, bw = 0.f;
    if (g) {
        float4 gg = *(const float4*)(g + (t << 2));
        float4 bb = *(const float4*)(b + (t << 2));
        gx = gg.x; gy = gg.y; gz = gg.z; gw = gg.w;
        bx = bb.x; by = bb.y; bz = bb.z; bw = bb.w;
    }
    float4 o;
    o.x = (v.x - mean) * inv * gx + bx;
    o.y = (v.y - mean) * inv * gy + by;
    o.z = (v.z - mean) * inv * gz + bz;
    o.w = (v.w - mean) * inv * gw + bw;
    if (outHalf) {
        __half2* oh = (__half2*)((__half*)out + row * DIMV + (t << 2));
        oh[0] = __floats2half2_rn(o.x, o.y);
        oh[1] = __floats2half2_rn(o.z, o.w);
    } else {
        *(float4*)((float*)out + row * DIMV + (t << 2)) = o;
    }
}

// ---------------------------------------------------------------------------
// fp16 mma.sync GEMM, 3-stage cp.async pipeline.
//   C[M,N] = op( A[M,K] @ B[K,N] (+bias[n]) (+resid) )
//   A: __half row-major.  B: k-pair packed u32[K/2][N].
//   Block: BM = 32*IM, BN = 128.  8 warps (2m x 4n), warp (IM*16) x 32.
//   BK=32.  ONE __syncthreads per k-tile; loads for kt+2 issued before
//   compute of kt (3 buffers -> writes touch buffer (kt-1)%3, already drained
//   by the barrier).  flags: 1 = gelu, 2 = half output.
// ---------------------------------------------------------------------------
#define SA 40     // A smem row stride in halves
#define SB 136    // B smem row stride in u32
template <int IM>
__global__ void __launch_bounds__(256, (IM == 4) ? 2 : 3) gemm_h(
    const __half* __restrict__ A, const uint32_t* __restrict__ Bp, void* __restrict__ Cv,
    int K, int lda, int ldbn, int ldc,
    const float* __restrict__ bias, const float* __restrict__ resid, int flags)
{
    constexpr int BM = 32 * IM;
    extern __shared__ char smraw[];
    __half*   As = (__half*)smraw;                              // [3][BM][SA]
    uint32_t* Bs = (uint32_t*)(smraw + 3 * BM * SA * 2);        // [3][16][SB]

    const int tid  = threadIdx.x;
    const int wid  = tid >> 5;
    const int lane = tid & 31;
    const int wm   = wid >> 2;
    const int wn   = wid & 3;
    const int g    = lane >> 2;
    const int t    = lane & 3;
    const int m0   = blockIdx.y * BM;
    const int n0   = blockIdx.x * 128;
    const int NK   = K >> 5;
    const int wbase = wm * (IM * 16);
    const int lrow = (lane & 7) + ((lane >> 3) & 1) * 8;
    const int lcol = (lane >> 4) * 8;

    const uint32_t aBase = smem_u32(As);
    const uint32_t bBase = smem_u32(Bs);

    float acc[IM][4][4];
    #pragma unroll
    for (int i = 0; i < IM; i++)
        #pragma unroll
        for (int j = 0; j < 4; j++)
            #pragma unroll
            for (int r = 0; r < 4; r++) acc[i][j][r] = 0.f;

    auto load_tile = [&](int kt, int buf) {
        const int kg = kt << 5;
        #pragma unroll
        for (int p = 0; p < IM / 2; p++) {
            int idx = p * 256 + tid;
            int row = idx >> 2;
            int c   = (idx & 3) << 3;
            cp_async16(aBase + ((buf * BM + row) * SA + c) * 2,
                       A + (size_t)(m0 + row) * lda + kg + c);
        }
        #pragma unroll
        for (int p = 0; p < 2; p++) {
            int idx = p * 256 + tid;
            int r   = idx >> 5;
            int c4  = (idx & 31) << 2;
            cp_async16(bBase + ((buf * 16 + r) * SB + c4) * 4,
                       Bp + (size_t)((kg >> 1) + r) * ldbn + n0 + c4);
        }
    };

    load_tile(0, 0);
    cp_commit();
    if (1 < NK) { load_tile(1, 1); }
    cp_commit();                       // commit even if empty: keeps group order

    for (int kt = 0; kt < NK; kt++) {
        if (kt + 1 < NK) cp_wait1(); else cp_wait0();
        __syncthreads();
        // prefetch tile kt+2 into buffer (kt+2)%3 == (kt-1)%3 (drained)
        if (kt + 2 < NK) { load_tile(kt + 2, (kt + 2) % 3); }
        cp_commit();

        const int buf = kt % 3;
        #pragma unroll
        for (int c = 0; c < 2; c++) {
            const int koff  = c << 4;
            const int k2off = c << 3;
            uint32_t af[IM][4], bf[4][2];
            #pragma unroll
            for (int i = 0; i < IM; i++) {
                uint32_t addr = aBase +
                    ((uint32_t)(buf * BM + wbase + i * 16 + lrow) * SA + koff + lcol) * 2;
                ldsm4(af[i], addr);
            }
            #pragma unroll
            for (int j = 0; j < 4; j++) {
                const int col = wn * 32 + j * 8 + g;
                bf[j][0] = Bs[(buf * 16 + k2off + t)     * SB + col];
                bf[j][1] = Bs[(buf * 16 + k2off + t + 4) * SB + col];
            }
            #pragma unroll
            for (int i = 0; i < IM; i++)
                #pragma unroll
                for (int j = 0; j < 4; j++)
                    mma_f16(acc[i][j][0], acc[i][j][1], acc[i][j][2], acc[i][j][3],
                            af[i][0], af[i][1], af[i][2], af[i][3],
                            bf[j][0], bf[j][1]);
        }
    }

    const int doGelu  = flags & 1;
    const int outHalf = flags & 2;
    #pragma unroll
    for (int i = 0; i < IM; i++) {
        int mrow = m0 + wbase + i * 16 + g;
        #pragma unroll
        for (int j = 0; j < 4; j++) {
            int ncol = n0 + wn * 32 + j * 8 + 2 * t;
            #pragma unroll
            for (int half = 0; half < 2; half++) {
                int mr = mrow + half * 8;
                float c0 = acc[i][j][2 * half + 0];
                float c1 = acc[i][j][2 * half + 1];
                if (bias) {
                    float2 bv = *(const float2*)(bias + ncol);
                    c0 += bv.x; c1 += bv.y;
                }
                if (resid) {
                    float2 rv = *(const float2*)(resid + (size_t)mr * ldc + ncol);
                    c0 += rv.x; c1 += rv.y;
                }
                if (doGelu) { c0 = gelu_exact(c0); c1 = gelu_exact(c1); }
                if (outHalf) {
                    *(__half2*)((__half*)Cv + (size_t)mr * ldc + ncol) =
                        __floats2half2_rn(c0, c1);
                } else {
                    float2 o; o.x = c0; o.y = c1;
                    *(float2*)((float*)Cv + (size_t)mr * ldc + ncol) = o;
                }
            }
        }
    }
}

// ---------------------------------------------------------------------------
// Tensor-core attention (tf32), reading fused qkv buffer (stride 3072):
//   Q = qkv[:, 0:1024], latent K/V = qkv[:, 1024:3072].  Media KV from kvm.
// ---------------------------------------------------------------------------
__global__ void __launch_bounds__(128, 4) attn_mma_kernel(
    const float* __restrict__ qkv, const float* __restrict__ kvm,
    __half* __restrict__ outp)
{
    __shared__ float ks[2][32][68];
    __shared__ float vs[2][32][72];
    __shared__ float ps[4][16][36];

    const int bt   = blockIdx.x >> 4;
    const int h    = blockIdx.x & 15;
    const int tid  = threadIdx.x;
    const int w    = tid >> 5;
    const int lane = tid & 31;
    const int g    = lane >> 2;
    const int t    = lane & 3;

    uint32_t qa[8][4];
    {
        const float* Qb = qkv + ((size_t)bt * 64 + w * 16) * 3072 + h * DHEAD;
        #pragma unroll
        for (int k = 0; k < 8; k++) {
            qa[k][0] = __float_as_uint(Qb[(size_t)g       * 3072 + k * 8 + t]     * 0.125f);
            qa[k][1] = __float_as_uint(Qb[(size_t)(g + 8) * 3072 + k * 8 + t]     * 0.125f);
            qa[k][2] = __float_as_uint(Qb[(size_t)g       * 3072 + k * 8 + t + 4] * 0.125f);
            qa[k][3] = __float_as_uint(Qb[(size_t)(g + 8) * 3072 + k * 8 + t + 4] * 0.125f);
        }
    }

    float out[8][4];
    #pragma unroll
    for (int j = 0; j < 8; j++)
        #pragma unroll
        for (int r = 0; r < 4; r++) out[j][r] = 0.f;
    float m0 = -1e30f, m1 = -1e30f, l0 = 0.f, l1 = 0.f;

    const uint32_t kb0 = smem_u32(&ks[0][0][0]);
    const uint32_t vb0 = smem_u32(&vs[0][0][0]);

    auto load_chunk = [&](int ch, int buf) {
        const float* base;
        size_t rstride;
        if (ch < 32) { base = kvm + ((size_t)bt * 1024 + ch * 32) * 2048 + h * DHEAD;              rstride = 2048; }
        else         { base = qkv + ((size_t)bt * 64 + (ch - 32) * 32) * 3072 + 1024 + h * DHEAD;  rstride = 3072; }
        #pragma unroll
        for (int p = 0; p < 4; p++) {
            int idx = p * 128 + tid;
            int r   = idx >> 4;
            int c4  = (idx & 15) << 2;
            cp_async16(kb0 + ((buf * 32 + r) * 68 + c4) * 4,
                       base + (size_t)r * rstride + c4);
            cp_async16(vb0 + ((buf * 32 + r) * 72 + c4) * 4,
                       base + (size_t)r * rstride + 1024 + c4);
        }
    };

    load_chunk(0, 0);
    cp_commit();

    for (int ch = 0; ch < 34; ch++) {
        const int buf = ch & 1;
        if (ch + 1 < 34) {
            load_chunk(ch + 1, buf ^ 1);
            cp_commit();
            cp_wait1();
        } else {
            cp_wait0();
        }
        __syncthreads();

        float sim[4][4];
        #pragma unroll
        for (int j = 0; j < 4; j++)
            #pragma unroll
            for (int r = 0; r < 4; r++) sim[j][r] = 0.f;
        #pragma unroll
        for (int k = 0; k < 8; k++) {
            #pragma unroll
            for (int j = 0; j < 4; j++) {
                uint32_t b0 = __float_as_uint(ks[buf][8 * j + g][k * 8 + t]);
                uint32_t b1 = __float_as_uint(ks[buf][8 * j + g][k * 8 + t + 4]);
                mma_tf32(sim[j][0], sim[j][1], sim[j][2], sim[j][3],
                         qa[k][0], qa[k][1], qa[k][2], qa[k][3], b0, b1);
            }
        }

        float cm0 = -1e30f, cm1 = -1e30f;
        #pragma unroll
        for (int j = 0; j < 4; j++) {
            cm0 = fmaxf(cm0, fmaxf(sim[j][0], sim[j][1]));
            cm1 = fmaxf(cm1, fmaxf(sim[j][2], sim[j][3]));
        }
        cm0 = fmaxf(cm0, __shfl_xor_sync(0xffffffffu, cm0, 1));
        cm0 = fmaxf(cm0, __shfl_xor_sync(0xffffffffu, cm0, 2));
        cm1 = fmaxf(cm1, __shfl_xor_sync(0xffffffffu, cm1, 1));
        cm1 = fmaxf(cm1, __shfl_xor_sync(0xffffffffu, cm1, 2));
        float mt0 = fmaxf(m0, cm0), mt1 = fmaxf(m1, cm1);
        float corr0 = __expf(m0 - mt0), corr1 = __expf(m1 - mt1);
        float rs0 = 0.f, rs1 = 0.f;
        #pragma unroll
        for (int j = 0; j < 4; j++) {
            sim[j][0] = __expf(sim[j][0] - mt0);
            sim[j][1] = __expf(sim[j][1] - mt0);
            sim[j][2] = __expf(sim[j][2] - mt1);
            sim[j][3] = __expf(sim[j][3] - mt1);
            rs0 += sim[j][0] + sim[j][1];
            rs1 += sim[j][2] + sim[j][3];
        }
        rs0 += __shfl_xor_sync(0xffffffffu, rs0, 1);
        rs0 += __shfl_xor_sync(0xffffffffu, rs0, 2);
        rs1 += __shfl_xor_sync(0xffffffffu, rs1, 1);
        rs1 += __shfl_xor_sync(0xffffffffu, rs1, 2);
        l0 = l0 * corr0 + rs0;  m0 = mt0;
        l1 = l1 * corr1 + rs1;  m1 = mt1;
        #pragma unroll
        for (int j = 0; j < 8; j++) {
            out[j][0] *= corr0; out[j][1] *= corr0;
            out[j][2] *= corr1; out[j][3] *= corr1;
        }

        #pragma unroll
        for (int j = 0; j < 4; j++) {
            *(float2*)&ps[w][g][8 * j + 2 * t]     = make_float2(sim[j][0], sim[j][1]);
            *(float2*)&ps[w][g + 8][8 * j + 2 * t] = make_float2(sim[j][2], sim[j][3]);
        }
        __syncwarp();

        #pragma unroll
        for (int k = 0; k < 4; k++) {
            uint32_t a0 = __float_as_uint(ps[w][g][k * 8 + t]);
            uint32_t a1 = __float_as_uint(ps[w][g + 8][k * 8 + t]);
            uint32_t a2 = __float_as_uint(ps[w][g][k * 8 + t + 4]);
            uint32_t a3 = __float_as_uint(ps[w][g + 8][k * 8 + t + 4]);
            #pragma unroll
            for (int j = 0; j < 8; j++) {
                uint32_t b0 = __float_as_uint(vs[buf][k * 8 + t][8 * j + g]);
                uint32_t b1 = __float_as_uint(vs[buf][k * 8 + t + 4][8 * j + g]);
                mma_tf32(out[j][0], out[j][1], out[j][2], out[j][3],
                         a0, a1, a2, a3, b0, b1);
            }
        }
        __syncthreads();
    }

    float inv0 = 1.f / l0, inv1 = 1.f / l1;
    __half* O0 = outp + ((size_t)bt * 64 + w * 16 + g)     * INNERV + h * DHEAD;
    __half* O1 = outp + ((size_t)bt * 64 + w * 16 + g + 8) * INNERV + h * DHEAD;
    #pragma unroll
    for (int j = 0; j < 8; j++) {
        *(__half2*)(O0 + 8 * j + 2 * t) = __floats2half2_rn(out[j][0] * inv0, out[j][1] * inv0);
        *(__half2*)(O1 + 8 * j + 2 * t) = __floats2half2_rn(out[j][2] * inv1, out[j][3] * inv1);
    }
}

// ---------------------------------------------------------------------------
// Host orchestration
// ---------------------------------------------------------------------------
extern "C" void kernel_launch(void* const* d_in, const int* in_sizes, int n_in,
                              void* d_out, int out_size)
{
    const float* x       = (const float*)d_in[0];
    const float* latents = (const float*)d_in[1];
    const float* nm_g    = (const float*)d_in[2];
    const float* nm_b    = (const float*)d_in[3];
    const float* nl_g    = (const float*)d_in[4];
    const float* nl_b    = (const float*)d_in[5];
    const float* wq      = (const float*)d_in[6];
    const float* wkv     = (const float*)d_in[7];
    const float* wo      = (const float*)d_in[8];
    const float* ff_g    = (const float*)d_in[9];
    const float* ff_b    = (const float*)d_in[10];
    const float* w1      = (const float*)d_in[11];
    const float* w2      = (const float*)d_in[12];
    const float* fin_g   = (const float*)d_in[13];
    const float* fin_b   = (const float*)d_in[14];

    __half *xhat, *latn, *attnH, *ffh;
    float *kvm, *lat, *qkv, *kvbias;
    uint32_t *wkvP, *wqkvP, *woP, *w1P, *w2P;
    cudaGetSymbolAddress((void**)&xhat,  g_xhat);
    cudaGetSymbolAddress((void**)&kvm,   g_kvm);
    cudaGetSymbolAddress((void**)&lat,   g_lat);
    cudaGetSymbolAddress((void**)&latn,  g_latn);
    cudaGetSymbolAddress((void**)&qkv,   g_qkv);
    cudaGetSymbolAddress((void**)&attnH, g_attn);
    cudaGetSymbolAddress((void**)&ffh,   g_ffh);
    cudaGetSymbolAddress((void**)&wkvP,  g_wkvP);
    cudaGetSymbolAddress((void**)&wqkvP, g_wqkvP);
    cudaGetSymbolAddress((void**)&woP,   g_woP);
    cudaGetSymbolAddress((void**)&w1P,   g_w1P);
    cudaGetSymbolAddress((void**)&w2P,   g_w2P);
    cudaGetSymbolAddress((void**)&kvbias, g_kvbias);

    const int K2N_KV = (DIMV / 2) * 2 * INNERV;
    const int K2N_SQ = (DIMV / 2) * INNERV;
    const int K2N_W1 = (DIMV / 2) * FFV;
    const int K2N_W2 = (FFV / 2) * DIMV;

    const int SM4 = 3 * 128 * SA * 2 + 3 * 16 * SB * 4;   // 56832
    const int SM2 = 3 *  64 * SA * 2 + 3 * 16 * SB * 4;   // 41472
    cudaFuncSetAttribute(gemm_h<4>, cudaFuncAttributeMaxDynamicSharedMemorySize, SM4);
    cudaFuncSetAttribute(gemm_h<2>, cudaFuncAttributeMaxDynamicSharedMemorySize, SM2);

    // ---- preproc ----
    wpack_kernel<<<NDEPTH * K2N_KV / 256, 256>>>(
        wkv, wkvP, K2N_KV, 2 * INNERV, DIMV, nm_g, 2 * INNERV, 0);
    ln_kernel<<<BTV * MEDIA, 256>>>(x, xhat, nullptr, nullptr, 1);
    bias_kernel<<<dim3(2 * INNERV / 256, NDEPTH), 256>>>(nm_b, wkv, kvbias, DIMV, 2 * INNERV);
    gemm_h<4><<<dim3(16, 256), 256, SM4>>>(xhat, wkvP, kvm,
        DIMV, DIMV, 2 * INNERV, 2 * INNERV, kvbias, nullptr, 0);
    init_lat_kernel<<<2048, 256>>>(latents, lat);
    // fused q|kv packed weights (cols 0:1024 = wq, 1024:3072 = wkv)
    wpack_kernel<<<NDEPTH * K2N_SQ / 256, 256>>>(
        wq, wqkvP, K2N_SQ, INNERV, DIMV, nullptr, 3 * INNERV, 0);
    wpack_kernel<<<NDEPTH * K2N_KV / 256, 256>>>(
        wkv, wqkvP, K2N_KV, 2 * INNERV, DIMV, nullptr, 3 * INNERV, INNERV);
    wpack_kernel<<<NDEPTH * K2N_SQ / 256, 256>>>(
        wo, woP, K2N_SQ, DIMV, INNERV, nullptr, DIMV, 0);
    wpack_kernel<<<NDEPTH * K2N_W1 / 256, 256>>>(
        w1, w1P, K2N_W1, FFV, DIMV, nullptr, FFV, 0);
    wpack_kernel<<<NDEPTH * K2N_W2 / 256, 256>>>(
        w2, w2P, K2N_W2, DIMV, FFV, nullptr, DIMV, 0);

    for (int i = 0; i < NDEPTH; i++) {
        const uint32_t* wkvP_i  = wkvP  + (size_t)i * K2N_KV;
        const uint32_t* wqkvP_i = wqkvP + (size_t)i * (DIMV / 2) * 3 * INNERV;
        const uint32_t* woP_i   = woP   + (size_t)i * K2N_SQ;
        const uint32_t* w1P_i   = w1P   + (size_t)i * K2N_W1;
        const uint32_t* w2P_i   = w2P   + (size_t)i * K2N_W2;
        const float*    kvb_i   = kvbias + (size_t)i * 2 * INNERV;

        if (i > 0) {
            gemm_h<4><<<dim3(16, 256), 256, SM4>>>(xhat, wkvP_i, kvm,
                DIMV, DIMV, 2 * INNERV, 2 * INNERV, kvb_i, nullptr, 0);
        }

        ln_kernel<<<BTV * NLAT, 256>>>(lat, latn,
            nl_g + (size_t)i * DIMV, nl_b + (size_t)i * DIMV, 1);
        // fused q + latent-kv projection: [2048,1024] @ [1024,3072]
        gemm_h<2><<<dim3(24, 32), 256, SM2>>>(latn, wqkvP_i, qkv,
            DIMV, DIMV, 3 * INNERV, 3 * INNERV, nullptr, nullptr, 0);

        attn_mma_kernel<<<BTV * NHEADS, 128>>>(qkv, kvm, attnH);

        gemm_h<2><<<dim3(8, 32), 256, SM2>>>(attnH, woP_i, lat,
            INNERV, INNERV, DIMV, DIMV, nullptr, lat, 0);

        ln_kernel<<<BTV * NLAT, 256>>>(lat, latn,
            ff_g + (size_t)i * DIMV, ff_b + (size_t)i * DIMV, 1);
        gemm_h<2><<<dim3(32, 32), 256, SM2>>>(latn, w1P_i, ffh,
            DIMV, DIMV, FFV, FFV, nullptr, nullptr, 1 | 2);
        gemm_h<2><<<dim3(8, 32), 256, SM2>>>(ffh, w2P_i, lat,
            FFV, FFV, DIMV, DIMV, nullptr, lat, 0);
    }

    ln_kernel<<<BTV * NLAT, 256>>>(lat, (float*)d_out, fin_g, fin_b, 0);
}

// round 9
// speedup vs baseline: 2.2022x; 1.0009x over previous
#include <cuda_runtime.h>
#include <cuda_fp16.h>
#include <math.h>
#include <cstdint>

// ---------------------------------------------------------------------------
// Problem constants (PerceiverResampler)
// ---------------------------------------------------------------------------
#define DIMV   1024
#define NDEPTH 6
#define NHEADS 16
#define DHEAD  64
#define INNERV 1024
#define NLAT   64
#define FFV    4096
#define BTV    32
#define MEDIA  1024
#define LNEPS  1e-5f

// ---------------------------------------------------------------------------
// Scratch (static device allocations)
// ---------------------------------------------------------------------------
__device__ __half g_xhat[(size_t)BTV * MEDIA * DIMV];
__device__ float  g_kvmA[(size_t)BTV * MEDIA * 2 * INNERV];   // ping
__device__ float  g_kvmB[(size_t)BTV * MEDIA * 2 * INNERV];   // pong
__device__ float  g_lat [(size_t)BTV * NLAT * DIMV];
__device__ __half g_latn[(size_t)BTV * NLAT * DIMV];
__device__ float  g_qkv [(size_t)BTV * NLAT * 3 * INNERV];    // fused q | kv
__device__ __half g_attn[(size_t)BTV * NLAT * INNERV];
__device__ __half g_ffh [(size_t)BTV * NLAT * FFV];
// k-pair-packed half weights: u32[k/2][n] = {w[k][n], w[k+1][n]}
__device__ uint32_t g_wkvP [(size_t)NDEPTH * (DIMV/2) * 2 * INNERV];   // scaled by nm_g
__device__ uint32_t g_wqkvP[(size_t)NDEPTH * (DIMV/2) * 3 * INNERV];   // wq | wkv plain
__device__ uint32_t g_woP  [(size_t)NDEPTH * (INNERV/2) * DIMV];
__device__ uint32_t g_w1P  [(size_t)NDEPTH * (DIMV/2) * FFV];
__device__ uint32_t g_w2P  [(size_t)NDEPTH * (FFV/2) * DIMV];
__device__ float g_kvbias[(size_t)NDEPTH * 2 * INNERV];                // nm_b @ wkv

// ---------------------------------------------------------------------------
// helpers
// ---------------------------------------------------------------------------
__device__ __forceinline__ uint32_t smem_u32(const void* p) {
    uint32_t a;
    asm("{ .reg .u64 t; cvta.to.shared.u64 t, %1; cvt.u32.u64 %0, t; }"
        : "=r"(a) : "l"(p));
    return a;
}
__device__ __forceinline__ void cp_async16(uint32_t dst, const void* src) {
    asm volatile("cp.async.cg.shared.global [%0], [%1], 16;" :: "r"(dst), "l"(src));
}
__device__ __forceinline__ void cp_commit() {
    asm volatile("cp.async.commit_group;" ::: "memory");
}
__device__ __forceinline__ void cp_wait1() {
    asm volatile("cp.async.wait_group 1;" ::: "memory");
}
__device__ __forceinline__ void cp_wait0() {
    asm volatile("cp.async.wait_group 0;" ::: "memory");
}
__device__ __forceinline__ void mma_f16(float& c0, float& c1, float& c2, float& c3,
                                        uint32_t a0, uint32_t a1, uint32_t a2, uint32_t a3,
                                        uint32_t b0, uint32_t b1) {
    asm volatile(
        "mma.sync.aligned.m16n8k16.row.col.f32.f16.f16.f32 "
        "{%0,%1,%2,%3}, {%4,%5,%6,%7}, {%8,%9}, {%0,%1,%2,%3};"
        : "+f"(c0), "+f"(c1), "+f"(c2), "+f"(c3)
        : "r"(a0), "r"(a1), "r"(a2), "r"(a3), "r"(b0), "r"(b1));
}
__device__ __forceinline__ void mma_tf32(float& c0, float& c1, float& c2, float& c3,
                                         uint32_t a0, uint32_t a1, uint32_t a2, uint32_t a3,
                                         uint32_t b0, uint32_t b1) {
    asm volatile(
        "mma.sync.aligned.m16n8k8.row.col.f32.tf32.tf32.f32 "
        "{%0,%1,%2,%3}, {%4,%5,%6,%7}, {%8,%9}, {%0,%1,%2,%3};"
        : "+f"(c0), "+f"(c1), "+f"(c2), "+f"(c3)
        : "r"(a0), "r"(a1), "r"(a2), "r"(a3), "r"(b0), "r"(b1));
}
__device__ __forceinline__ void ldsm4(uint32_t* r, uint32_t addr) {
    asm volatile("ldmatrix.sync.aligned.m8n8.x4.shared.b16 {%0,%1,%2,%3}, [%4];"
                 : "=r"(r[0]), "=r"(r[1]), "=r"(r[2]), "=r"(r[3]) : "r"(addr));
}
__device__ __forceinline__ float gelu_exact(float x) {
    return 0.5f * x * (1.0f + erff(x * 0.70710678118654752f));
}

// ---------------------------------------------------------------------------
// Weight pack with output stride/offset
// ---------------------------------------------------------------------------
__global__ void __launch_bounds__(256) wpack_kernel(
    const float* __restrict__ in, uint32_t* __restrict__ out,
    int K2N, int N, int K, const float* __restrict__ scale,
    int ldo, int coloff)
{
    int idx = blockIdx.x * 256 + threadIdx.x;
    int layer = idx / K2N;
    int rem   = idx - layer * K2N;
    int k2 = rem / N;
    int n  = rem - k2 * N;
    const float* base = in + ((size_t)layer * K + 2 * k2) * N + n;
    float v0 = base[0], v1 = base[N];
    if (scale) {
        v0 *= scale[layer * K + 2 * k2];
        v1 *= scale[layer * K + 2 * k2 + 1];
    }
    __half2 h = __floats2half2_rn(v0, v1);
    out[((size_t)layer * (K / 2) + k2) * ldo + coloff + n] = *(uint32_t*)&h;
}

// ---------------------------------------------------------------------------
// bias[layer][n] = sum_k b[layer][k] * W[layer][k][n]  (fp32)
// ---------------------------------------------------------------------------
__global__ void __launch_bounds__(256) bias_kernel(
    const float* __restrict__ b, const float* __restrict__ W,
    float* __restrict__ out, int K, int N)
{
    int layer = blockIdx.y;
    int n = blockIdx.x * 256 + threadIdx.x;
    const float* Wl = W + (size_t)layer * K * N;
    const float* bl = b + (size_t)layer * K;
    float s = 0.f;
    for (int k = 0; k < K; k++) s = fmaf(bl[k], Wl[(size_t)k * N + n], s);
    out[(size_t)layer * N + n] = s;
}

// ---------------------------------------------------------------------------
// lat broadcast
// ---------------------------------------------------------------------------
__global__ void __launch_bounds__(256) init_lat_kernel(
    const float* __restrict__ latents, float* __restrict__ lat)
{
    int idx4 = blockIdx.x * 256 + threadIdx.x;
    int row  = idx4 >> 8;
    int c4   = idx4 & 255;
    int n    = row & 63;
    float4 v = *(const float4*)(latents + (size_t)n * DIMV + (c4 << 2));
    *(float4*)(lat + ((size_t)row << 10) + (c4 << 2)) = v;
}

// ---------------------------------------------------------------------------
// LayerNorm rows of 1024.  outHalf: write __half else float.
// ---------------------------------------------------------------------------
__global__ void __launch_bounds__(256) ln_kernel(
    const float* __restrict__ in, void* __restrict__ out,
    const float* __restrict__ g, const float* __restrict__ b, int outHalf)
{
    __shared__ float red[2][8];
    size_t row = blockIdx.x;
    const float* x = in + row * DIMV;
    int t = threadIdx.x;

    float4 v = *(const float4*)(x + (t << 2));
    float s  = v.x + v.y + v.z + v.w;
    float ss = v.x*v.x + v.y*v.y + v.z*v.z + v.w*v.w;
    #pragma unroll
    for (int off = 16; off; off >>= 1) {
        s  += __shfl_xor_sync(0xffffffffu, s,  off);
        ss += __shfl_xor_sync(0xffffffffu, ss, off);
    }
    int w = t >> 5, lane = t & 31;
    if (lane == 0) { red[0][w] = s; red[1][w] = ss; }
    __syncthreads();
    if (t == 0) {
        float ts = 0.f, tss = 0.f;
        #pragma unroll
        for (int i = 0; i < 8; i++) { ts += red[0][i]; tss += red[1][i]; }
        red[0][0] = ts; red[1][0] = tss;
    }
    __syncthreads();
    float mean = red[0][0] * (1.f / 1024.f);
    float var  = red[1][0] * (1.f / 1024.f) - mean * mean;
    float inv  = rsqrtf(var + LNEPS);

    float gx = 1.f, gy = 1.f, gz = 1.f, gw = 1.f;
    float bx = 0.f, by = 0.f, bz = 0.f, bw = 0.f;
    if (g) {
        float4 gg = *(const float4*)(g + (t << 2));
        float4 bb = *(const float4*)(b + (t << 2));
        gx = gg.x; gy = gg.y; gz = gg.z; gw = gg.w;
        bx = bb.x; by = bb.y; bz = bb.z; bw = bb.w;
    }
    float4 o;
    o.x = (v.x - mean) * inv * gx + bx;
    o.y = (v.y - mean) * inv * gy + by;
    o.z = (v.z - mean) * inv * gz + bz;
    o.w = (v.w - mean) * inv * gw + bw;
    if (outHalf) {
        __half2* oh = (__half2*)((__half*)out + row * DIMV + (t << 2));
        oh[0] = __floats2half2_rn(o.x, o.y);
        oh[1] = __floats2half2_rn(o.z, o.w);
    } else {
        *(float4*)((float*)out + row * DIMV + (t << 2)) = o;
    }
}

// ---------------------------------------------------------------------------
// fp16 mma.sync GEMM, 3-stage cp.async pipeline (unchanged from R7).
// ---------------------------------------------------------------------------
#define SA 40     // A smem row stride in halves
#define SB 136    // B smem row stride in u32
template <int IM>
__global__ void __launch_bounds__(256, (IM == 4) ? 2 : 3) gemm_h(
    const __half* __restrict__ A, const uint32_t* __restrict__ Bp, void* __restrict__ Cv,
    int K, int lda, int ldbn, int ldc,
    const float* __restrict__ bias, const float* __restrict__ resid, int flags)
{
    constexpr int BM = 32 * IM;
    extern __shared__ char smraw[];
    __half*   As = (__half*)smraw;                              // [3][BM][SA]
    uint32_t* Bs = (uint32_t*)(smraw + 3 * BM * SA * 2);        // [3][16][SB]

    const int tid  = threadIdx.x;
    const int wid  = tid >> 5;
    const int lane = tid & 31;
    const int wm   = wid >> 2;
    const int wn   = wid & 3;
    const int g    = lane >> 2;
    const int t    = lane & 3;
    const int m0   = blockIdx.y * BM;
    const int n0   = blockIdx.x * 128;
    const int NK   = K >> 5;
    const int wbase = wm * (IM * 16);
    const int lrow = (lane & 7) + ((lane >> 3) & 1) * 8;
    const int lcol = (lane >> 4) * 8;

    const uint32_t aBase = smem_u32(As);
    const uint32_t bBase = smem_u32(Bs);

    float acc[IM][4][4];
    #pragma unroll
    for (int i = 0; i < IM; i++)
        #pragma unroll
        for (int j = 0; j < 4; j++)
            #pragma unroll
            for (int r = 0; r < 4; r++) acc[i][j][r] = 0.f;

    auto load_tile = [&](int kt, int buf) {
        const int kg = kt << 5;
        #pragma unroll
        for (int p = 0; p < IM / 2; p++) {
            int idx = p * 256 + tid;
            int row = idx >> 2;
            int c   = (idx & 3) << 3;
            cp_async16(aBase + ((buf * BM + row) * SA + c) * 2,
                       A + (size_t)(m0 + row) * lda + kg + c);
        }
        #pragma unroll
        for (int p = 0; p < 2; p++) {
            int idx = p * 256 + tid;
            int r   = idx >> 5;
            int c4  = (idx & 31) << 2;
            cp_async16(bBase + ((buf * 16 + r) * SB + c4) * 4,
                       Bp + (size_t)((kg >> 1) + r) * ldbn + n0 + c4);
        }
    };

    load_tile(0, 0);
    cp_commit();
    if (1 < NK) { load_tile(1, 1); }
    cp_commit();

    for (int kt = 0; kt < NK; kt++) {
        if (kt + 1 < NK) cp_wait1(); else cp_wait0();
        __syncthreads();
        if (kt + 2 < NK) { load_tile(kt + 2, (kt + 2) % 3); }
        cp_commit();

        const int buf = kt % 3;
        #pragma unroll
        for (int c = 0; c < 2; c++) {
            const int koff  = c << 4;
            const int k2off = c << 3;
            uint32_t af[IM][4], bf[4][2];
            #pragma unroll
            for (int i = 0; i < IM; i++) {
                uint32_t addr = aBase +
                    ((uint32_t)(buf * BM + wbase + i * 16 + lrow) * SA + koff + lcol) * 2;
                ldsm4(af[i], addr);
            }
            #pragma unroll
            for (int j = 0; j < 4; j++) {
                const int col = wn * 32 + j * 8 + g;
                bf[j][0] = Bs[(buf * 16 + k2off + t)     * SB + col];
                bf[j][1] = Bs[(buf * 16 + k2off + t + 4) * SB + col];
            }
            #pragma unroll
            for (int i = 0; i < IM; i++)
                #pragma unroll
                for (int j = 0; j < 4; j++)
                    mma_f16(acc[i][j][0], acc[i][j][1], acc[i][j][2], acc[i][j][3],
                            af[i][0], af[i][1], af[i][2], af[i][3],
                            bf[j][0], bf[j][1]);
        }
    }

    const int doGelu  = flags & 1;
    const int outHalf = flags & 2;
    #pragma unroll
    for (int i = 0; i < IM; i++) {
        int mrow = m0 + wbase + i * 16 + g;
        #pragma unroll
        for (int j = 0; j < 4; j++) {
            int ncol = n0 + wn * 32 + j * 8 + 2 * t;
            #pragma unroll
            for (int half = 0; half < 2; half++) {
                int mr = mrow + half * 8;
                float c0 = acc[i][j][2 * half + 0];
                float c1 = acc[i][j][2 * half + 1];
                if (bias) {
                    float2 bv = *(const float2*)(bias + ncol);
                    c0 += bv.x; c1 += bv.y;
                }
                if (resid) {
                    float2 rv = *(const float2*)(resid + (size_t)mr * ldc + ncol);
                    c0 += rv.x; c1 += rv.y;
                }
                if (doGelu) { c0 = gelu_exact(c0); c1 = gelu_exact(c1); }
                if (outHalf) {
                    *(__half2*)((__half*)Cv + (size_t)mr * ldc + ncol) =
                        __floats2half2_rn(c0, c1);
                } else {
                    float2 o; o.x = c0; o.y = c1;
                    *(float2*)((float*)Cv + (size_t)mr * ldc + ncol) = o;
                }
            }
        }
    }
}

// ---------------------------------------------------------------------------
// Tensor-core attention (tf32), fused qkv buffer (unchanged from R7).
// ---------------------------------------------------------------------------
__global__ void __launch_bounds__(128, 4) attn_mma_kernel(
    const float* __restrict__ qkv, const float* __restrict__ kvm,
    __half* __restrict__ outp)
{
    __shared__ float ks[2][32][68];
    __shared__ float vs[2][32][72];
    __shared__ float ps[4][16][36];

    const int bt   = blockIdx.x >> 4;
    const int h    = blockIdx.x & 15;
    const int tid  = threadIdx.x;
    const int w    = tid >> 5;
    const int lane = tid & 31;
    const int g    = lane >> 2;
    const int t    = lane & 3;

    uint32_t qa[8][4];
    {
        const float* Qb = qkv + ((size_t)bt * 64 + w * 16) * 3072 + h * DHEAD;
        #pragma unroll
        for (int k = 0; k < 8; k++) {
            qa[k][0] = __float_as_uint(Qb[(size_t)g       * 3072 + k * 8 + t]     * 0.125f);
            qa[k][1] = __float_as_uint(Qb[(size_t)(g + 8) * 3072 + k * 8 + t]     * 0.125f);
            qa[k][2] = __float_as_uint(Qb[(size_t)g       * 3072 + k * 8 + t + 4] * 0.125f);
            qa[k][3] = __float_as_uint(Qb[(size_t)(g + 8) * 3072 + k * 8 + t + 4] * 0.125f);
        }
    }

    float out[8][4];
    #pragma unroll
    for (int j = 0; j < 8; j++)
        #pragma unroll
        for (int r = 0; r < 4; r++) out[j][r] = 0.f;
    float m0 = -1e30f, m1 = -1e30f, l0 = 0.f, l1 = 0.f;

    const uint32_t kb0 = smem_u32(&ks[0][0][0]);
    const uint32_t vb0 = smem_u32(&vs[0][0][0]);

    auto load_chunk = [&](int ch, int buf) {
        const float* base;
        size_t rstride;
        if (ch < 32) { base = kvm + ((size_t)bt * 1024 + ch * 32) * 2048 + h * DHEAD;              rstride = 2048; }
        else         { base = qkv + ((size_t)bt * 64 + (ch - 32) * 32) * 3072 + 1024 + h * DHEAD;  rstride = 3072; }
        #pragma unroll
        for (int p = 0; p < 4; p++) {
            int idx = p * 128 + tid;
            int r   = idx >> 4;
            int c4  = (idx & 15) << 2;
            cp_async16(kb0 + ((buf * 32 + r) * 68 + c4) * 4,
                       base + (size_t)r * rstride + c4);
            cp_async16(vb0 + ((buf * 32 + r) * 72 + c4) * 4,
                       base + (size_t)r * rstride + 1024 + c4);
        }
    };

    load_chunk(0, 0);
    cp_commit();

    for (int ch = 0; ch < 34; ch++) {
        const int buf = ch & 1;
        if (ch + 1 < 34) {
            load_chunk(ch + 1, buf ^ 1);
            cp_commit();
            cp_wait1();
        } else {
            cp_wait0();
        }
        __syncthreads();

        float sim[4][4];
        #pragma unroll
        for (int j = 0; j < 4; j++)
            #pragma unroll
            for (int r = 0; r < 4; r++) sim[j][r] = 0.f;
        #pragma unroll
        for (int k = 0; k < 8; k++) {
            #pragma unroll
            for (int j = 0; j < 4; j++) {
                uint32_t b0 = __float_as_uint(ks[buf][8 * j + g][k * 8 + t]);
                uint32_t b1 = __float_as_uint(ks[buf][8 * j + g][k * 8 + t + 4]);
                mma_tf32(sim[j][0], sim[j][1], sim[j][2], sim[j][3],
                         qa[k][0], qa[k][1], qa[k][2], qa[k][3], b0, b1);
            }
        }

        float cm0 = -1e30f, cm1 = -1e30f;
        #pragma unroll
        for (int j = 0; j < 4; j++) {
            cm0 = fmaxf(cm0, fmaxf(sim[j][0], sim[j][1]));
            cm1 = fmaxf(cm1, fmaxf(sim[j][2], sim[j][3]));
        }
        cm0 = fmaxf(cm0, __shfl_xor_sync(0xffffffffu, cm0, 1));
        cm0 = fmaxf(cm0, __shfl_xor_sync(0xffffffffu, cm0, 2));
        cm1 = fmaxf(cm1, __shfl_xor_sync(0xffffffffu, cm1, 1));
        cm1 = fmaxf(cm1, __shfl_xor_sync(0xffffffffu, cm1, 2));
        float mt0 = fmaxf(m0, cm0), mt1 = fmaxf(m1, cm1);
        float corr0 = __expf(m0 - mt0), corr1 = __expf(m1 - mt1);
        float rs0 = 0.f, rs1 = 0.f;
        #pragma unroll
        for (int j = 0; j < 4; j++) {
            sim[j][0] = __expf(sim[j][0] - mt0);
            sim[j][1] = __expf(sim[j][1] - mt0);
            sim[j][2] = __expf(sim[j][2] - mt1);
            sim[j][3] = __expf(sim[j][3] - mt1);
            rs0 += sim[j][0] + sim[j][1];
            rs1 += sim[j][2] + sim[j][3];
        }
        rs0 += __shfl_xor_sync(0xffffffffu, rs0, 1);
        rs0 += __shfl_xor_sync(0xffffffffu, rs0, 2);
        rs1 += __shfl_xor_sync(0xffffffffu, rs1, 1);
        rs1 += __shfl_xor_sync(0xffffffffu, rs1, 2);
        l0 = l0 * corr0 + rs0;  m0 = mt0;
        l1 = l1 * corr1 + rs1;  m1 = mt1;
        #pragma unroll
        for (int j = 0; j < 8; j++) {
            out[j][0] *= corr0; out[j][1] *= corr0;
            out[j][2] *= corr1; out[j][3] *= corr1;
        }

        #pragma unroll
        for (int j = 0; j < 4; j++) {
            *(float2*)&ps[w][g][8 * j + 2 * t]     = make_float2(sim[j][0], sim[j][1]);
            *(float2*)&ps[w][g + 8][8 * j + 2 * t] = make_float2(sim[j][2], sim[j][3]);
        }
        __syncwarp();

        #pragma unroll
        for (int k = 0; k < 4; k++) {
            uint32_t a0 = __float_as_uint(ps[w][g][k * 8 + t]);
            uint32_t a1 = __float_as_uint(ps[w][g + 8][k * 8 + t]);
            uint32_t a2 = __float_as_uint(ps[w][g][k * 8 + t + 4]);
            uint32_t a3 = __float_as_uint(ps[w][g + 8][k * 8 + t + 4]);
            #pragma unroll
            for (int j = 0; j < 8; j++) {
                uint32_t b0 = __float_as_uint(vs[buf][k * 8 + t][8 * j + g]);
                uint32_t b1 = __float_as_uint(vs[buf][k * 8 + t + 4][8 * j + g]);
                mma_tf32(out[j][0], out[j][1], out[j][2], out[j][3],
                         a0, a1, a2, a3, b0, b1);
            }
        }
        __syncthreads();
    }

    float inv0 = 1.f / l0, inv1 = 1.f / l1;
    __half* O0 = outp + ((size_t)bt * 64 + w * 16 + g)     * INNERV + h * DHEAD;
    __half* O1 = outp + ((size_t)bt * 64 + w * 16 + g + 8) * INNERV + h * DHEAD;
    #pragma unroll
    for (int j = 0; j < 8; j++) {
        *(__half2*)(O0 + 8 * j + 2 * t) = __floats2half2_rn(out[j][0] * inv0, out[j][1] * inv0);
        *(__half2*)(O1 + 8 * j + 2 * t) = __floats2half2_rn(out[j][2] * inv1, out[j][3] * inv1);
    }
}

// ---------------------------------------------------------------------------
// Host orchestration: two-stream fork/join with CORRECT host enqueue order —
// every cudaStreamWaitEvent refers to an event already recorded in host order.
//   stream 0 (capture): preproc + latent chain
//   s1 (non-blocking):  six kvm GEMMs, ping-pong buffers
//   kvm_0, kvm_1 enqueued up front; kvm_{i+2} enqueued AFTER evAttn[i] record.
// ---------------------------------------------------------------------------
extern "C" void kernel_launch(void* const* d_in, const int* in_sizes, int n_in,
                              void* d_out, int out_size)
{
    const float* x       = (const float*)d_in[0];
    const float* latents = (const float*)d_in[1];
    const float* nm_g    = (const float*)d_in[2];
    const float* nm_b    = (const float*)d_in[3];
    const float* nl_g    = (const float*)d_in[4];
    const float* nl_b    = (const float*)d_in[5];
    const float* wq      = (const float*)d_in[6];
    const float* wkv     = (const float*)d_in[7];
    const float* wo      = (const float*)d_in[8];
    const float* ff_g    = (const float*)d_in[9];
    const float* ff_b    = (const float*)d_in[10];
    const float* w1      = (const float*)d_in[11];
    const float* w2      = (const float*)d_in[12];
    const float* fin_g   = (const float*)d_in[13];
    const float* fin_b   = (const float*)d_in[14];

    __half *xhat, *latn, *attnH, *ffh;
    float *lat, *qkv, *kvbias;
    float *kvmBuf[2];
    uint32_t *wkvP, *wqkvP, *woP, *w1P, *w2P;
    cudaGetSymbolAddress((void**)&xhat,      g_xhat);
    cudaGetSymbolAddress((void**)&kvmBuf[0], g_kvmA);
    cudaGetSymbolAddress((void**)&kvmBuf[1], g_kvmB);
    cudaGetSymbolAddress((void**)&lat,       g_lat);
    cudaGetSymbolAddress((void**)&latn,      g_latn);
    cudaGetSymbolAddress((void**)&qkv,       g_qkv);
    cudaGetSymbolAddress((void**)&attnH,     g_attn);
    cudaGetSymbolAddress((void**)&ffh,       g_ffh);
    cudaGetSymbolAddress((void**)&wkvP,      g_wkvP);
    cudaGetSymbolAddress((void**)&wqkvP,     g_wqkvP);
    cudaGetSymbolAddress((void**)&woP,       g_woP);
    cudaGetSymbolAddress((void**)&w1P,       g_w1P);
    cudaGetSymbolAddress((void**)&w2P,       g_w2P);
    cudaGetSymbolAddress((void**)&kvbias,    g_kvbias);

    const int K2N_KV = (DIMV / 2) * 2 * INNERV;
    const int K2N_SQ = (DIMV / 2) * INNERV;
    const int K2N_W1 = (DIMV / 2) * FFV;
    const int K2N_W2 = (FFV / 2) * DIMV;

    const int SM4 = 3 * 128 * SA * 2 + 3 * 16 * SB * 4;   // 56832
    const int SM2 = 3 *  64 * SA * 2 + 3 * 16 * SB * 4;   // 41472
    cudaFuncSetAttribute(gemm_h<4>, cudaFuncAttributeMaxDynamicSharedMemorySize, SM4);
    cudaFuncSetAttribute(gemm_h<2>, cudaFuncAttributeMaxDynamicSharedMemorySize, SM2);

    cudaStream_t s1;
    cudaStreamCreateWithFlags(&s1, cudaStreamNonBlocking);
    cudaEvent_t evPre, evKvm[NDEPTH], evAttn[NDEPTH];
    cudaEventCreateWithFlags(&evPre, cudaEventDisableTiming);
    for (int i = 0; i < NDEPTH; i++) {
        cudaEventCreateWithFlags(&evKvm[i],  cudaEventDisableTiming);
        cudaEventCreateWithFlags(&evAttn[i], cudaEventDisableTiming);
    }

    // ---- stream 0: minimal preproc needed by kvm ----
    wpack_kernel<<<NDEPTH * K2N_KV / 256, 256>>>(
        wkv, wkvP, K2N_KV, 2 * INNERV, DIMV, nm_g, 2 * INNERV, 0);
    ln_kernel<<<BTV * MEDIA, 256>>>(x, xhat, nullptr, nullptr, 1);
    bias_kernel<<<dim3(2 * INNERV / 256, NDEPTH), 256>>>(nm_b, wkv, kvbias, DIMV, 2 * INNERV);
    cudaEventRecord(evPre, 0);

    // ---- s1: first two kvm GEMMs (no backpressure needed, 2 buffers) ----
    cudaStreamWaitEvent(s1, evPre, 0);
    for (int i = 0; i < 2 && i < NDEPTH; i++) {
        gemm_h<4><<<dim3(16, 256), 256, SM4, s1>>>(
            xhat, wkvP + (size_t)i * K2N_KV, kvmBuf[i & 1],
            DIMV, DIMV, 2 * INNERV, 2 * INNERV,
            kvbias + (size_t)i * 2 * INNERV, nullptr, 0);
        cudaEventRecord(evKvm[i], s1);
    }

    // ---- stream 0: rest of preproc ----
    init_lat_kernel<<<2048, 256>>>(latents, lat);
    wpack_kernel<<<NDEPTH * K2N_SQ / 256, 256>>>(
        wq, wqkvP, K2N_SQ, INNERV, DIMV, nullptr, 3 * INNERV, 0);
    wpack_kernel<<<NDEPTH * K2N_KV / 256, 256>>>(
        wkv, wqkvP, K2N_KV, 2 * INNERV, DIMV, nullptr, 3 * INNERV, INNERV);
    wpack_kernel<<<NDEPTH * K2N_SQ / 256, 256>>>(
        wo, woP, K2N_SQ, DIMV, INNERV, nullptr, DIMV, 0);
    wpack_kernel<<<NDEPTH * K2N_W1 / 256, 256>>>(
        w1, w1P, K2N_W1, FFV, DIMV, nullptr, FFV, 0);
    wpack_kernel<<<NDEPTH * K2N_W2 / 256, 256>>>(
        w2, w2P, K2N_W2, DIMV, FFV, nullptr, DIMV, 0);

    // ---- stream 0: latent chain; kvm_{i+2} enqueued after evAttn[i] record ----
    for (int i = 0; i < NDEPTH; i++) {
        const uint32_t* wqkvP_i = wqkvP + (size_t)i * (DIMV / 2) * 3 * INNERV;
        const uint32_t* woP_i   = woP   + (size_t)i * K2N_SQ;
        const uint32_t* w1P_i   = w1P   + (size_t)i * K2N_W1;
        const uint32_t* w2P_i   = w2P   + (size_t)i * K2N_W2;

        ln_kernel<<<BTV * NLAT, 256>>>(lat, latn,
            nl_g + (size_t)i * DIMV, nl_b + (size_t)i * DIMV, 1);
        gemm_h<2><<<dim3(24, 32), 256, SM2>>>(latn, wqkvP_i, qkv,
            DIMV, DIMV, 3 * INNERV, 3 * INNERV, nullptr, nullptr, 0);

        cudaStreamWaitEvent(0, evKvm[i], 0);
        attn_mma_kernel<<<BTV * NHEADS, 128>>>(qkv, kvmBuf[i & 1], attnH);
        cudaEventRecord(evAttn[i], 0);

        // NOW evAttn[i] is recorded -> safe to enqueue kvm_{i+2} waiting on it.
        if (i + 2 < NDEPTH) {
            int j = i + 2;
            cudaStreamWaitEvent(s1, evAttn[i], 0);
            gemm_h<4><<<dim3(16, 256), 256, SM4, s1>>>(
                xhat, wkvP + (size_t)j * K2N_KV, kvmBuf[j & 1],
                DIMV, DIMV, 2 * INNERV, 2 * INNERV,
                kvbias + (size_t)j * 2 * INNERV, nullptr, 0);
            cudaEventRecord(evKvm[j], s1);
        }

        gemm_h<2><<<dim3(8, 32), 256, SM2>>>(attnH, woP_i, lat,
            INNERV, INNERV, DIMV, DIMV, nullptr, lat, 0);

        ln_kernel<<<BTV * NLAT, 256>>>(lat, latn,
            ff_g + (size_t)i * DIMV, ff_b + (size_t)i * DIMV, 1);
        gemm_h<2><<<dim3(32, 32), 256, SM2>>>(latn, w1P_i, ffh,
            DIMV, DIMV, FFV, FFV, nullptr, nullptr, 1 | 2);
        gemm_h<2><<<dim3(8, 32), 256, SM2>>>(ffh, w2P_i, lat,
            FFV, FFV, DIMV, DIMV, nullptr, lat, 0);
    }

    ln_kernel<<<BTV * NLAT, 256>>>(lat, (float*)d_out, fin_g, fin_b, 0);

    cudaEventDestroy(evPre);
    for (int i = 0; i < NDEPTH; i++) {
        cudaEventDestroy(evKvm[i]);
        cudaEventDestroy(evAttn[i]);
    }
    cudaStreamDestroy(s1);
}

// round 10
// speedup vs baseline: 2.2784x; 1.0346x over previous
#include <cuda_runtime.h>
#include <cuda_fp16.h>
#include <math.h>
#include <cstdint>

// ---------------------------------------------------------------------------
// Problem constants (PerceiverResampler)
// ---------------------------------------------------------------------------
#define DIMV   1024
#define NDEPTH 6
#define NHEADS 16
#define DHEAD  64
#define INNERV 1024
#define NLAT   64
#define FFV    4096
#define BTV    32
#define MEDIA  1024
#define LNEPS  1e-5f

// ---------------------------------------------------------------------------
// Scratch (static device allocations)
// ---------------------------------------------------------------------------
__device__ __half g_xhat[(size_t)BTV * MEDIA * DIMV];
__device__ float  g_kvmA[(size_t)BTV * MEDIA * 2 * INNERV];   // ping
__device__ float  g_kvmB[(size_t)BTV * MEDIA * 2 * INNERV];   // pong
__device__ float  g_lat [(size_t)BTV * NLAT * DIMV];
__device__ __half g_latn[(size_t)BTV * NLAT * DIMV];
__device__ float  g_qkv [(size_t)BTV * NLAT * 3 * INNERV];    // fused q | kv
__device__ __half g_attn[(size_t)BTV * NLAT * INNERV];
__device__ __half g_ffh [(size_t)BTV * NLAT * FFV];
// k-pair-packed half weights: u32[k/2][n] = {w[k][n], w[k+1][n]}
__device__ uint32_t g_wkvP [(size_t)NDEPTH * (DIMV/2) * 2 * INNERV];   // scaled by nm_g
__device__ uint32_t g_wqkvP[(size_t)NDEPTH * (DIMV/2) * 3 * INNERV];   // wq | wkv plain
__device__ uint32_t g_woP  [(size_t)NDEPTH * (INNERV/2) * DIMV];
__device__ uint32_t g_w1P  [(size_t)NDEPTH * (DIMV/2) * FFV];
__device__ uint32_t g_w2P  [(size_t)NDEPTH * (FFV/2) * DIMV];
__device__ float g_kvbias[(size_t)NDEPTH * 2 * INNERV];                // nm_b @ wkv

// ---------------------------------------------------------------------------
// helpers
// ---------------------------------------------------------------------------
__device__ __forceinline__ uint32_t smem_u32(const void* p) {
    uint32_t a;
    asm("{ .reg .u64 t; cvta.to.shared.u64 t, %1; cvt.u32.u64 %0, t; }"
        : "=r"(a) : "l"(p));
    return a;
}
__device__ __forceinline__ void cp_async16(uint32_t dst, const void* src) {
    asm volatile("cp.async.cg.shared.global [%0], [%1], 16;" :: "r"(dst), "l"(src));
}
__device__ __forceinline__ void cp_commit() {
    asm volatile("cp.async.commit_group;" ::: "memory");
}
__device__ __forceinline__ void cp_wait1() {
    asm volatile("cp.async.wait_group 1;" ::: "memory");
}
__device__ __forceinline__ void cp_wait0() {
    asm volatile("cp.async.wait_group 0;" ::: "memory");
}
__device__ __forceinline__ void mma_f16(float& c0, float& c1, float& c2, float& c3,
                                        uint32_t a0, uint32_t a1, uint32_t a2, uint32_t a3,
                                        uint32_t b0, uint32_t b1) {
    asm volatile(
        "mma.sync.aligned.m16n8k16.row.col.f32.f16.f16.f32 "
        "{%0,%1,%2,%3}, {%4,%5,%6,%7}, {%8,%9}, {%0,%1,%2,%3};"
        : "+f"(c0), "+f"(c1), "+f"(c2), "+f"(c3)
        : "r"(a0), "r"(a1), "r"(a2), "r"(a3), "r"(b0), "r"(b1));
}
__device__ __forceinline__ void mma_tf32(float& c0, float& c1, float& c2, float& c3,
                                         uint32_t a0, uint32_t a1, uint32_t a2, uint32_t a3,
                                         uint32_t b0, uint32_t b1) {
    asm volatile(
        "mma.sync.aligned.m16n8k8.row.col.f32.tf32.tf32.f32 "
        "{%0,%1,%2,%3}, {%4,%5,%6,%7}, {%8,%9}, {%0,%1,%2,%3};"
        : "+f"(c0), "+f"(c1), "+f"(c2), "+f"(c3)
        : "r"(a0), "r"(a1), "r"(a2), "r"(a3), "r"(b0), "r"(b1));
}
__device__ __forceinline__ void ldsm4(uint32_t* r, uint32_t addr) {
    asm volatile("ldmatrix.sync.aligned.m8n8.x4.shared.b16 {%0,%1,%2,%3}, [%4];"
                 : "=r"(r[0]), "=r"(r[1]), "=r"(r[2]), "=r"(r[3]) : "r"(addr));
}
__device__ __forceinline__ float gelu_exact(float x) {
    return 0.5f * x * (1.0f + erff(x * 0.70710678118654752f));
}

// ---------------------------------------------------------------------------
// Weight pack with output stride/offset
// ---------------------------------------------------------------------------
__global__ void __launch_bounds__(256) wpack_kernel(
    const float* __restrict__ in, uint32_t* __restrict__ out,
    int K2N, int N, int K, const float* __restrict__ scale,
    int ldo, int coloff)
{
    int idx = blockIdx.x * 256 + threadIdx.x;
    int layer = idx / K2N;
    int rem   = idx - layer * K2N;
    int k2 = rem / N;
    int n  = rem - k2 * N;
    const float* base = in + ((size_t)layer * K + 2 * k2) * N + n;
    float v0 = base[0], v1 = base[N];
    if (scale) {
        v0 *= scale[layer * K + 2 * k2];
        v1 *= scale[layer * K + 2 * k2 + 1];
    }
    __half2 h = __floats2half2_rn(v0, v1);
    out[((size_t)layer * (K / 2) + k2) * ldo + coloff + n] = *(uint32_t*)&h;
}

// ---------------------------------------------------------------------------
// bias[layer][n] = sum_k b[layer][k] * W[layer][k][n]  (fp32)
// ---------------------------------------------------------------------------
__global__ void __launch_bounds__(256) bias_kernel(
    const float* __restrict__ b, const float* __restrict__ W,
    float* __restrict__ out, int K, int N)
{
    int layer = blockIdx.y;
    int n = blockIdx.x * 256 + threadIdx.x;
    const float* Wl = W + (size_t)layer * K * N;
    const float* bl = b + (size_t)layer * K;
    float s = 0.f;
    for (int k = 0; k < K; k++) s = fmaf(bl[k], Wl[(size_t)k * N + n], s);
    out[(size_t)layer * N + n] = s;
}

// ---------------------------------------------------------------------------
// lat broadcast
// ---------------------------------------------------------------------------
__global__ void __launch_bounds__(256) init_lat_kernel(
    const float* __restrict__ latents, float* __restrict__ lat)
{
    int idx4 = blockIdx.x * 256 + threadIdx.x;
    int row  = idx4 >> 8;
    int c4   = idx4 & 255;
    int n    = row & 63;
    float4 v = *(const float4*)(latents + (size_t)n * DIMV + (c4 << 2));
    *(float4*)(lat + ((size_t)row << 10) + (c4 << 2)) = v;
}

// ---------------------------------------------------------------------------
// LayerNorm rows of 1024.  outHalf: write __half else float.
// ---------------------------------------------------------------------------
__global__ void __launch_bounds__(256) ln_kernel(
    const float* __restrict__ in, void* __restrict__ out,
    const float* __restrict__ g, const float* __restrict__ b, int outHalf)
{
    __shared__ float red[2][8];
    size_t row = blockIdx.x;
    const float* x = in + row * DIMV;
    int t = threadIdx.x;

    float4 v = *(const float4*)(x + (t << 2));
    float s  = v.x + v.y + v.z + v.w;
    float ss = v.x*v.x + v.y*v.y + v.z*v.z + v.w*v.w;
    #pragma unroll
    for (int off = 16; off; off >>= 1) {
        s  += __shfl_xor_sync(0xffffffffu, s,  off);
        ss += __shfl_xor_sync(0xffffffffu, ss, off);
    }
    int w = t >> 5, lane = t & 31;
    if (lane == 0) { red[0][w] = s; red[1][w] = ss; }
    __syncthreads();
    if (t == 0) {
        float ts = 0.f, tss = 0.f;
        #pragma unroll
        for (int i = 0; i < 8; i++) { ts += red[0][i]; tss += red[1][i]; }
        red[0][0] = ts; red[1][0] = tss;
    }
    __syncthreads();
    float mean = red[0][0] * (1.f / 1024.f);
    float var  = red[1][0] * (1.f / 1024.f) - mean * mean;
    float inv  = rsqrtf(var + LNEPS);

    float gx = 1.f, gy = 1.f, gz = 1.f, gw = 1.f;
    float bx = 0.f, by = 0.f, bz = 0.f, bw = 0.f;
    if (g) {
        float4 gg = *(const float4*)(g + (t << 2));
        float4 bb = *(const float4*)(b + (t << 2));
        gx = gg.x; gy = gg.y; gz = gg.z; gw = gg.w;
        bx = bb.x; by = bb.y; bz = bb.z; bw = bb.w;
    }
    float4 o;
    o.x = (v.x - mean) * inv * gx + bx;
    o.y = (v.y - mean) * inv * gy + by;
    o.z = (v.z - mean) * inv * gz + bz;
    o.w = (v.w - mean) * inv * gw + bw;
    if (outHalf) {
        __half2* oh = (__half2*)((__half*)out + row * DIMV + (t << 2));
        oh[0] = __floats2half2_rn(o.x, o.y);
        oh[1] = __floats2half2_rn(o.z, o.w);
    } else {
        *(float4*)((float*)out + row * DIMV + (t << 2)) = o;
    }
}

// ---------------------------------------------------------------------------
// fp16 mma.sync GEMM, 3-stage cp.async pipeline.
//   C[M,N] = op( A[M,K] @ B[K,N] (+bias[n]) (+resid) )
//   Template: IM -> BM = 32*IM;  CH -> BK = 16*CH (chunks per stage).
//   <4,4>: kvm config, BK=64, one barrier per 64-k, smem 105KB, occ 2.
//   <2,2>: latent config, BK=32, smem 40.5KB, occ 3.
//   BN = 128 fixed.  8 warps (2m x 4n).  flags: 1 = gelu, 2 = half output.
// ---------------------------------------------------------------------------
#define SB 136    // B smem row stride in u32
template <int IM, int CH>
__global__ void __launch_bounds__(256, (IM == 4) ? 2 : 3) gemm_h(
    const __half* __restrict__ A, const uint32_t* __restrict__ Bp, void* __restrict__ Cv,
    int K, int lda, int ldbn, int ldc,
    const float* __restrict__ bias, const float* __restrict__ resid, int flags)
{
    constexpr int BM  = 32 * IM;
    constexpr int SAv = 16 * CH + 8;   // A smem row stride in halves
    constexpr int BR  = 8 * CH;        // B k2-rows per stage
    extern __shared__ char smraw[];
    __half*   As = (__half*)smraw;                               // [3][BM][SAv]
    uint32_t* Bs = (uint32_t*)(smraw + 3 * BM * SAv * 2);        // [3][BR][SB]

    const int tid  = threadIdx.x;
    const int wid  = tid >> 5;
    const int lane = tid & 31;
    const int wm   = wid >> 2;
    const int wn   = wid & 3;
    const int g    = lane >> 2;
    const int t    = lane & 3;
    const int m0   = blockIdx.y * BM;
    const int n0   = blockIdx.x * 128;
    const int NK   = K / (16 * CH);
    const int wbase = wm * (IM * 16);
    const int lrow = (lane & 7) + ((lane >> 3) & 1) * 8;
    const int lcol = (lane >> 4) * 8;

    const uint32_t aBase = smem_u32(As);
    const uint32_t bBase = smem_u32(Bs);

    float acc[IM][4][4];
    #pragma unroll
    for (int i = 0; i < IM; i++)
        #pragma unroll
        for (int j = 0; j < 4; j++)
            #pragma unroll
            for (int r = 0; r < 4; r++) acc[i][j][r] = 0.f;

    auto load_tile = [&](int kt, int buf) {
        const int kg = kt * 16 * CH;
        // A: BM rows x BK halves -> BM*2*CH cp16 -> BM*CH/128 per thread
        #pragma unroll
        for (int p = 0; p < BM * CH / 128; p++) {
            int idx = p * 256 + tid;
            int row = idx / (2 * CH);
            int c   = (idx % (2 * CH)) << 3;     // halves
            cp_async16(aBase + ((buf * BM + row) * SAv + c) * 2,
                       A + (size_t)(m0 + row) * lda + kg + c);
        }
        // B: BR rows x 128 u32 -> CH cp16 per thread
        #pragma unroll
        for (int p = 0; p < CH; p++) {
            int idx = p * 256 + tid;
            int r   = idx >> 5;
            int c4  = (idx & 31) << 2;
            cp_async16(bBase + ((buf * BR + r) * SB + c4) * 4,
                       Bp + (size_t)((kg >> 1) + r) * ldbn + n0 + c4);
        }
    };

    load_tile(0, 0);
    cp_commit();
    if (1 < NK) { load_tile(1, 1); }
    cp_commit();

    for (int kt = 0; kt < NK; kt++) {
        if (kt + 1 < NK) cp_wait1(); else cp_wait0();
        __syncthreads();
        if (kt + 2 < NK) { load_tile(kt + 2, (kt + 2) % 3); }
        cp_commit();

        const int buf = kt % 3;
        #pragma unroll
        for (int c = 0; c < CH; c++) {
            const int koff  = c << 4;
            const int k2off = c << 3;
            uint32_t af[IM][4], bf[4][2];
            #pragma unroll
            for (int i = 0; i < IM; i++) {
                uint32_t addr = aBase +
                    ((uint32_t)(buf * BM + wbase + i * 16 + lrow) * SAv + koff + lcol) * 2;
                ldsm4(af[i], addr);
            }
            #pragma unroll
            for (int j = 0; j < 4; j++) {
                const int col = wn * 32 + j * 8 + g;
                bf[j][0] = Bs[(buf * BR + k2off + t)     * SB + col];
                bf[j][1] = Bs[(buf * BR + k2off + t + 4) * SB + col];
            }
            #pragma unroll
            for (int i = 0; i < IM; i++)
                #pragma unroll
                for (int j = 0; j < 4; j++)
                    mma_f16(acc[i][j][0], acc[i][j][1], acc[i][j][2], acc[i][j][3],
                            af[i][0], af[i][1], af[i][2], af[i][3],
                            bf[j][0], bf[j][1]);
        }
    }

    const int doGelu  = flags & 1;
    const int outHalf = flags & 2;
    #pragma unroll
    for (int i = 0; i < IM; i++) {
        int mrow = m0 + wbase + i * 16 + g;
        #pragma unroll
        for (int j = 0; j < 4; j++) {
            int ncol = n0 + wn * 32 + j * 8 + 2 * t;
            #pragma unroll
            for (int half = 0; half < 2; half++) {
                int mr = mrow + half * 8;
                float c0 = acc[i][j][2 * half + 0];
                float c1 = acc[i][j][2 * half + 1];
                if (bias) {
                    float2 bv = *(const float2*)(bias + ncol);
                    c0 += bv.x; c1 += bv.y;
                }
                if (resid) {
                    float2 rv = *(const float2*)(resid + (size_t)mr * ldc + ncol);
                    c0 += rv.x; c1 += rv.y;
                }
                if (doGelu) { c0 = gelu_exact(c0); c1 = gelu_exact(c1); }
                if (outHalf) {
                    *(__half2*)((__half*)Cv + (size_t)mr * ldc + ncol) =
                        __floats2half2_rn(c0, c1);
                } else {
                    float2 o; o.x = c0; o.y = c1;
                    *(float2*)((float*)Cv + (size_t)mr * ldc + ncol) = o;
                }
            }
        }
    }
}

// ---------------------------------------------------------------------------
// Tensor-core attention (tf32), fused qkv buffer (unchanged).
// ---------------------------------------------------------------------------
__global__ void __launch_bounds__(128, 4) attn_mma_kernel(
    const float* __restrict__ qkv, const float* __restrict__ kvm,
    __half* __restrict__ outp)
{
    __shared__ float ks[2][32][68];
    __shared__ float vs[2][32][72];
    __shared__ float ps[4][16][36];

    const int bt   = blockIdx.x >> 4;
    const int h    = blockIdx.x & 15;
    const int tid  = threadIdx.x;
    const int w    = tid >> 5;
    const int lane = tid & 31;
    const int g    = lane >> 2;
    const int t    = lane & 3;

    uint32_t qa[8][4];
    {
        const float* Qb = qkv + ((size_t)bt * 64 + w * 16) * 3072 + h * DHEAD;
        #pragma unroll
        for (int k = 0; k < 8; k++) {
            qa[k][0] = __float_as_uint(Qb[(size_t)g       * 3072 + k * 8 + t]     * 0.125f);
            qa[k][1] = __float_as_uint(Qb[(size_t)(g + 8) * 3072 + k * 8 + t]     * 0.125f);
            qa[k][2] = __float_as_uint(Qb[(size_t)g       * 3072 + k * 8 + t + 4] * 0.125f);
            qa[k][3] = __float_as_uint(Qb[(size_t)(g + 8) * 3072 + k * 8 + t + 4] * 0.125f);
        }
    }

    float out[8][4];
    #pragma unroll
    for (int j = 0; j < 8; j++)
        #pragma unroll
        for (int r = 0; r < 4; r++) out[j][r] = 0.f;
    float m0 = -1e30f, m1 = -1e30f, l0 = 0.f, l1 = 0.f;

    const uint32_t kb0 = smem_u32(&ks[0][0][0]);
    const uint32_t vb0 = smem_u32(&vs[0][0][0]);

    auto load_chunk = [&](int ch, int buf) {
        const float* base;
        size_t rstride;
        if (ch < 32) { base = kvm + ((size_t)bt * 1024 + ch * 32) * 2048 + h * DHEAD;              rstride = 2048; }
        else         { base = qkv + ((size_t)bt * 64 + (ch - 32) * 32) * 3072 + 1024 + h * DHEAD;  rstride = 3072; }
        #pragma unroll
        for (int p = 0; p < 4; p++) {
            int idx = p * 128 + tid;
            int r   = idx >> 4;
            int c4  = (idx & 15) << 2;
            cp_async16(kb0 + ((buf * 32 + r) * 68 + c4) * 4,
                       base + (size_t)r * rstride + c4);
            cp_async16(vb0 + ((buf * 32 + r) * 72 + c4) * 4,
                       base + (size_t)r * rstride + 1024 + c4);
        }
    };

    load_chunk(0, 0);
    cp_commit();

    for (int ch = 0; ch < 34; ch++) {
        const int buf = ch & 1;
        if (ch + 1 < 34) {
            load_chunk(ch + 1, buf ^ 1);
            cp_commit();
            cp_wait1();
        } else {
            cp_wait0();
        }
        __syncthreads();

        float sim[4][4];
        #pragma unroll
        for (int j = 0; j < 4; j++)
            #pragma unroll
            for (int r = 0; r < 4; r++) sim[j][r] = 0.f;
        #pragma unroll
        for (int k = 0; k < 8; k++) {
            #pragma unroll
            for (int j = 0; j < 4; j++) {
                uint32_t b0 = __float_as_uint(ks[buf][8 * j + g][k * 8 + t]);
                uint32_t b1 = __float_as_uint(ks[buf][8 * j + g][k * 8 + t + 4]);
                mma_tf32(sim[j][0], sim[j][1], sim[j][2], sim[j][3],
                         qa[k][0], qa[k][1], qa[k][2], qa[k][3], b0, b1);
            }
        }

        float cm0 = -1e30f, cm1 = -1e30f;
        #pragma unroll
        for (int j = 0; j < 4; j++) {
            cm0 = fmaxf(cm0, fmaxf(sim[j][0], sim[j][1]));
            cm1 = fmaxf(cm1, fmaxf(sim[j][2], sim[j][3]));
        }
        cm0 = fmaxf(cm0, __shfl_xor_sync(0xffffffffu, cm0, 1));
        cm0 = fmaxf(cm0, __shfl_xor_sync(0xffffffffu, cm0, 2));
        cm1 = fmaxf(cm1, __shfl_xor_sync(0xffffffffu, cm1, 1));
        cm1 = fmaxf(cm1, __shfl_xor_sync(0xffffffffu, cm1, 2));
        float mt0 = fmaxf(m0, cm0), mt1 = fmaxf(m1, cm1);
        float corr0 = __expf(m0 - mt0), corr1 = __expf(m1 - mt1);
        float rs0 = 0.f, rs1 = 0.f;
        #pragma unroll
        for (int j = 0; j < 4; j++) {
            sim[j][0] = __expf(sim[j][0] - mt0);
            sim[j][1] = __expf(sim[j][1] - mt0);
            sim[j][2] = __expf(sim[j][2] - mt1);
            sim[j][3] = __expf(sim[j][3] - mt1);
            rs0 += sim[j][0] + sim[j][1];
            rs1 += sim[j][2] + sim[j][3];
        }
        rs0 += __shfl_xor_sync(0xffffffffu, rs0, 1);
        rs0 += __shfl_xor_sync(0xffffffffu, rs0, 2);
        rs1 += __shfl_xor_sync(0xffffffffu, rs1, 1);
        rs1 += __shfl_xor_sync(0xffffffffu, rs1, 2);
        l0 = l0 * corr0 + rs0;  m0 = mt0;
        l1 = l1 * corr1 + rs1;  m1 = mt1;
        #pragma unroll
        for (int j = 0; j < 8; j++) {
            out[j][0] *= corr0; out[j][1] *= corr0;
            out[j][2] *= corr1; out[j][3] *= corr1;
        }

        #pragma unroll
        for (int j = 0; j < 4; j++) {
            *(float2*)&ps[w][g][8 * j + 2 * t]     = make_float2(sim[j][0], sim[j][1]);
            *(float2*)&ps[w][g + 8][8 * j + 2 * t] = make_float2(sim[j][2], sim[j][3]);
        }
        __syncwarp();

        #pragma unroll
        for (int k = 0; k < 4; k++) {
            uint32_t a0 = __float_as_uint(ps[w][g][k * 8 + t]);
            uint32_t a1 = __float_as_uint(ps[w][g + 8][k * 8 + t]);
            uint32_t a2 = __float_as_uint(ps[w][g][k * 8 + t + 4]);
            uint32_t a3 = __float_as_uint(ps[w][g + 8][k * 8 + t + 4]);
            #pragma unroll
            for (int j = 0; j < 8; j++) {
                uint32_t b0 = __float_as_uint(vs[buf][k * 8 + t][8 * j + g]);
                uint32_t b1 = __float_as_uint(vs[buf][k * 8 + t + 4][8 * j + g]);
                mma_tf32(out[j][0], out[j][1], out[j][2], out[j][3],
                         a0, a1, a2, a3, b0, b1);
            }
        }
        __syncthreads();
    }

    float inv0 = 1.f / l0, inv1 = 1.f / l1;
    __half* O0 = outp + ((size_t)bt * 64 + w * 16 + g)     * INNERV + h * DHEAD;
    __half* O1 = outp + ((size_t)bt * 64 + w * 16 + g + 8) * INNERV + h * DHEAD;
    #pragma unroll
    for (int j = 0; j < 8; j++) {
        *(__half2*)(O0 + 8 * j + 2 * t) = __floats2half2_rn(out[j][0] * inv0, out[j][1] * inv0);
        *(__half2*)(O1 + 8 * j + 2 * t) = __floats2half2_rn(out[j][2] * inv1, out[j][3] * inv1);
    }
}

// ---------------------------------------------------------------------------
// Host orchestration: two-stream fork/join (correct enqueue order, from R9).
// ---------------------------------------------------------------------------
extern "C" void kernel_launch(void* const* d_in, const int* in_sizes, int n_in,
                              void* d_out, int out_size)
{
    const float* x       = (const float*)d_in[0];
    const float* latents = (const float*)d_in[1];
    const float* nm_g    = (const float*)d_in[2];
    const float* nm_b    = (const float*)d_in[3];
    const float* nl_g    = (const float*)d_in[4];
    const float* nl_b    = (const float*)d_in[5];
    const float* wq      = (const float*)d_in[6];
    const float* wkv     = (const float*)d_in[7];
    const float* wo      = (const float*)d_in[8];
    const float* ff_g    = (const float*)d_in[9];
    const float* ff_b    = (const float*)d_in[10];
    const float* w1      = (const float*)d_in[11];
    const float* w2      = (const float*)d_in[12];
    const float* fin_g   = (const float*)d_in[13];
    const float* fin_b   = (const float*)d_in[14];

    __half *xhat, *latn, *attnH, *ffh;
    float *lat, *qkv, *kvbias;
    float *kvmBuf[2];
    uint32_t *wkvP, *wqkvP, *woP, *w1P, *w2P;
    cudaGetSymbolAddress((void**)&xhat,      g_xhat);
    cudaGetSymbolAddress((void**)&kvmBuf[0], g_kvmA);
    cudaGetSymbolAddress((void**)&kvmBuf[1], g_kvmB);
    cudaGetSymbolAddress((void**)&lat,       g_lat);
    cudaGetSymbolAddress((void**)&latn,      g_latn);
    cudaGetSymbolAddress((void**)&qkv,       g_qkv);
    cudaGetSymbolAddress((void**)&attnH,     g_attn);
    cudaGetSymbolAddress((void**)&ffh,       g_ffh);
    cudaGetSymbolAddress((void**)&wkvP,      g_wkvP);
    cudaGetSymbolAddress((void**)&wqkvP,     g_wqkvP);
    cudaGetSymbolAddress((void**)&woP,       g_woP);
    cudaGetSymbolAddress((void**)&w1P,       g_w1P);
    cudaGetSymbolAddress((void**)&w2P,       g_w2P);
    cudaGetSymbolAddress((void**)&kvbias,    g_kvbias);

    const int K2N_KV = (DIMV / 2) * 2 * INNERV;
    const int K2N_SQ = (DIMV / 2) * INNERV;
    const int K2N_W1 = (DIMV / 2) * FFV;
    const int K2N_W2 = (FFV / 2) * DIMV;

    // <4,4>: As 3*128*72*2 = 55296, Bs 3*32*136*4 = 52224 -> 107520 (occ 2)
    // <2,2>: As 3*64*40*2  = 15360, Bs 3*16*136*4 = 26112 ->  41472 (occ 3)
    const int SM44 = 3 * 128 * 72 * 2 + 3 * 32 * SB * 4;
    const int SM22 = 3 *  64 * 40 * 2 + 3 * 16 * SB * 4;
    cudaFuncSetAttribute(gemm_h<4,4>, cudaFuncAttributeMaxDynamicSharedMemorySize, SM44);
    cudaFuncSetAttribute(gemm_h<2,2>, cudaFuncAttributeMaxDynamicSharedMemorySize, SM22);

    cudaStream_t s1;
    cudaStreamCreateWithFlags(&s1, cudaStreamNonBlocking);
    cudaEvent_t evPre, evKvm[NDEPTH], evAttn[NDEPTH];
    cudaEventCreateWithFlags(&evPre, cudaEventDisableTiming);
    for (int i = 0; i < NDEPTH; i++) {
        cudaEventCreateWithFlags(&evKvm[i],  cudaEventDisableTiming);
        cudaEventCreateWithFlags(&evAttn[i], cudaEventDisableTiming);
    }

    // ---- stream 0: minimal preproc needed by kvm ----
    wpack_kernel<<<NDEPTH * K2N_KV / 256, 256>>>(
        wkv, wkvP, K2N_KV, 2 * INNERV, DIMV, nm_g, 2 * INNERV, 0);
    ln_kernel<<<BTV * MEDIA, 256>>>(x, xhat, nullptr, nullptr, 1);
    bias_kernel<<<dim3(2 * INNERV / 256, NDEPTH), 256>>>(nm_b, wkv, kvbias, DIMV, 2 * INNERV);
    cudaEventRecord(evPre, 0);

    // ---- s1: first two kvm GEMMs ----
    cudaStreamWaitEvent(s1, evPre, 0);
    for (int i = 0; i < 2 && i < NDEPTH; i++) {
        gemm_h<4,4><<<dim3(16, 256), 256, SM44, s1>>>(
            xhat, wkvP + (size_t)i * K2N_KV, kvmBuf[i & 1],
            DIMV, DIMV, 2 * INNERV, 2 * INNERV,
            kvbias + (size_t)i * 2 * INNERV, nullptr, 0);
        cudaEventRecord(evKvm[i], s1);
    }

    // ---- stream 0: rest of preproc ----
    init_lat_kernel<<<2048, 256>>>(latents, lat);
    wpack_kernel<<<NDEPTH * K2N_SQ / 256, 256>>>(
        wq, wqkvP, K2N_SQ, INNERV, DIMV, nullptr, 3 * INNERV, 0);
    wpack_kernel<<<NDEPTH * K2N_KV / 256, 256>>>(
        wkv, wqkvP, K2N_KV, 2 * INNERV, DIMV, nullptr, 3 * INNERV, INNERV);
    wpack_kernel<<<NDEPTH * K2N_SQ / 256, 256>>>(
        wo, woP, K2N_SQ, DIMV, INNERV, nullptr, DIMV, 0);
    wpack_kernel<<<NDEPTH * K2N_W1 / 256, 256>>>(
        w1, w1P, K2N_W1, FFV, DIMV, nullptr, FFV, 0);
    wpack_kernel<<<NDEPTH * K2N_W2 / 256, 256>>>(
        w2, w2P, K2N_W2, DIMV, FFV, nullptr, DIMV, 0);

    // ---- stream 0: latent chain; kvm_{i+2} enqueued after evAttn[i] record ----
    for (int i = 0; i < NDEPTH; i++) {
        const uint32_t* wqkvP_i = wqkvP + (size_t)i * (DIMV / 2) * 3 * INNERV;
        const uint32_t* woP_i   = woP   + (size_t)i * K2N_SQ;
        const uint32_t* w1P_i   = w1P   + (size_t)i * K2N_W1;
        const uint32_t* w2P_i   = w2P   + (size_t)i * K2N_W2;

        ln_kernel<<<BTV * NLAT, 256>>>(lat, latn,
            nl_g + (size_t)i * DIMV, nl_b + (size_t)i * DIMV, 1);
        gemm_h<2,2><<<dim3(24, 32), 256, SM22>>>(latn, wqkvP_i, qkv,
            DIMV, DIMV, 3 * INNERV, 3 * INNERV, nullptr, nullptr, 0);

        cudaStreamWaitEvent(0, evKvm[i], 0);
        attn_mma_kernel<<<BTV * NHEADS, 128>>>(qkv, kvmBuf[i & 1], attnH);
        cudaEventRecord(evAttn[i], 0);

        if (i + 2 < NDEPTH) {
            int j = i + 2;
            cudaStreamWaitEvent(s1, evAttn[i], 0);
            gemm_h<4,4><<<dim3(16, 256), 256, SM44, s1>>>(
                xhat, wkvP + (size_t)j * K2N_KV, kvmBuf[j & 1],
                DIMV, DIMV, 2 * INNERV, 2 * INNERV,
                kvbias + (size_t)j * 2 * INNERV, nullptr, 0);
            cudaEventRecord(evKvm[j], s1);
        }

        gemm_h<2,2><<<dim3(8, 32), 256, SM22>>>(attnH, woP_i, lat,
            INNERV, INNERV, DIMV, DIMV, nullptr, lat, 0);

        ln_kernel<<<BTV * NLAT, 256>>>(lat, latn,
            ff_g + (size_t)i * DIMV, ff_b + (size_t)i * DIMV, 1);
        gemm_h<2,2><<<dim3(32, 32), 256, SM22>>>(latn, w1P_i, ffh,
            DIMV, DIMV, FFV, FFV, nullptr, nullptr, 1 | 2);
        gemm_h<2,2><<<dim3(8, 32), 256, SM22>>>(ffh, w2P_i, lat,
            FFV, FFV, DIMV, DIMV, nullptr, lat, 0);
    }

    ln_kernel<<<BTV * NLAT, 256>>>(lat, (float*)d_out, fin_g, fin_b, 0);

    cudaEventDestroy(evPre);
    for (int i = 0; i < NDEPTH; i++) {
        cudaEventDestroy(evKvm[i]);
        cudaEventDestroy(evAttn[i]);
    }
    cudaStreamDestroy(s1);
}

// round 11
// speedup vs baseline: 2.3782x; 1.0438x over previous
#include <cuda_runtime.h>
#include <cuda_fp16.h>
#include <math.h>
#include <cstdint>

// ---------------------------------------------------------------------------
// Problem constants (PerceiverResampler)
// ---------------------------------------------------------------------------
#define DIMV   1024
#define NDEPTH 6
#define NHEADS 16
#define DHEAD  64
#define INNERV 1024
#define NLAT   64
#define FFV    4096
#define BTV    32
#define MEDIA  1024
#define LNEPS  1e-5f

// ---------------------------------------------------------------------------
// Scratch (static device allocations)
// ---------------------------------------------------------------------------
__device__ __half g_xhat[(size_t)BTV * MEDIA * DIMV];
__device__ __half g_kvmA[(size_t)BTV * MEDIA * 2 * INNERV];   // ping (half)
__device__ __half g_kvmB[(size_t)BTV * MEDIA * 2 * INNERV];   // pong (half)
__device__ float  g_lat [(size_t)BTV * NLAT * DIMV];
__device__ __half g_latn[(size_t)BTV * NLAT * DIMV];
__device__ __half g_qkv [(size_t)BTV * NLAT * 3 * INNERV];    // fused q | k | v (half)
__device__ __half g_attn[(size_t)BTV * NLAT * INNERV];
__device__ __half g_ffh [(size_t)BTV * NLAT * FFV];
// k-pair-packed half weights: u32[k/2][n] = {w[k][n], w[k+1][n]}
__device__ uint32_t g_wkvP [(size_t)NDEPTH * (DIMV/2) * 2 * INNERV];   // scaled by nm_g
__device__ uint32_t g_wqkvP[(size_t)NDEPTH * (DIMV/2) * 3 * INNERV];   // wq | wkv plain
__device__ uint32_t g_woP  [(size_t)NDEPTH * (INNERV/2) * DIMV];
__device__ uint32_t g_w1P  [(size_t)NDEPTH * (DIMV/2) * FFV];
__device__ uint32_t g_w2P  [(size_t)NDEPTH * (FFV/2) * DIMV];
__device__ float g_kvbias[(size_t)NDEPTH * 2 * INNERV];                // nm_b @ wkv

// ---------------------------------------------------------------------------
// helpers
// ---------------------------------------------------------------------------
__device__ __forceinline__ uint32_t smem_u32(const void* p) {
    uint32_t a;
    asm("{ .reg .u64 t; cvta.to.shared.u64 t, %1; cvt.u32.u64 %0, t; }"
        : "=r"(a) : "l"(p));
    return a;
}
__device__ __forceinline__ void cp_async16(uint32_t dst, const void* src) {
    asm volatile("cp.async.cg.shared.global [%0], [%1], 16;" :: "r"(dst), "l"(src));
}
__device__ __forceinline__ void cp_commit() {
    asm volatile("cp.async.commit_group;" ::: "memory");
}
__device__ __forceinline__ void cp_wait1() {
    asm volatile("cp.async.wait_group 1;" ::: "memory");
}
__device__ __forceinline__ void cp_wait0() {
    asm volatile("cp.async.wait_group 0;" ::: "memory");
}
__device__ __forceinline__ void mma_f16(float& c0, float& c1, float& c2, float& c3,
                                        uint32_t a0, uint32_t a1, uint32_t a2, uint32_t a3,
                                        uint32_t b0, uint32_t b1) {
    asm volatile(
        "mma.sync.aligned.m16n8k16.row.col.f32.f16.f16.f32 "
        "{%0,%1,%2,%3}, {%4,%5,%6,%7}, {%8,%9}, {%0,%1,%2,%3};"
        : "+f"(c0), "+f"(c1), "+f"(c2), "+f"(c3)
        : "r"(a0), "r"(a1), "r"(a2), "r"(a3), "r"(b0), "r"(b1));
}
__device__ __forceinline__ void ldsm4(uint32_t* r, uint32_t addr) {
    asm volatile("ldmatrix.sync.aligned.m8n8.x4.shared.b16 {%0,%1,%2,%3}, [%4];"
                 : "=r"(r[0]), "=r"(r[1]), "=r"(r[2]), "=r"(r[3]) : "r"(addr));
}
__device__ __forceinline__ void ldsm4t(uint32_t* r, uint32_t addr) {
    asm volatile("ldmatrix.sync.aligned.m8n8.x4.trans.shared.b16 {%0,%1,%2,%3}, [%4];"
                 : "=r"(r[0]), "=r"(r[1]), "=r"(r[2]), "=r"(r[3]) : "r"(addr));
}
__device__ __forceinline__ float gelu_exact(float x) {
    return 0.5f * x * (1.0f + erff(x * 0.70710678118654752f));
}

// ---------------------------------------------------------------------------
// Weight pack with output stride/offset
// ---------------------------------------------------------------------------
__global__ void __launch_bounds__(256) wpack_kernel(
    const float* __restrict__ in, uint32_t* __restrict__ out,
    int K2N, int N, int K, const float* __restrict__ scale,
    int ldo, int coloff)
{
    int idx = blockIdx.x * 256 + threadIdx.x;
    int layer = idx / K2N;
    int rem   = idx - layer * K2N;
    int k2 = rem / N;
    int n  = rem - k2 * N;
    const float* base = in + ((size_t)layer * K + 2 * k2) * N + n;
    float v0 = base[0], v1 = base[N];
    if (scale) {
        v0 *= scale[layer * K + 2 * k2];
        v1 *= scale[layer * K + 2 * k2 + 1];
    }
    __half2 h = __floats2half2_rn(v0, v1);
    out[((size_t)layer * (K / 2) + k2) * ldo + coloff + n] = *(uint32_t*)&h;
}

// ---------------------------------------------------------------------------
// bias[layer][n] = sum_k b[layer][k] * W[layer][k][n]  (fp32)
// ---------------------------------------------------------------------------
__global__ void __launch_bounds__(256) bias_kernel(
    const float* __restrict__ b, const float* __restrict__ W,
    float* __restrict__ out, int K, int N)
{
    int layer = blockIdx.y;
    int n = blockIdx.x * 256 + threadIdx.x;
    const float* Wl = W + (size_t)layer * K * N;
    const float* bl = b + (size_t)layer * K;
    float s = 0.f;
    for (int k = 0; k < K; k++) s = fmaf(bl[k], Wl[(size_t)k * N + n], s);
    out[(size_t)layer * N + n] = s;
}

// ---------------------------------------------------------------------------
// lat broadcast
// ---------------------------------------------------------------------------
__global__ void __launch_bounds__(256) init_lat_kernel(
    const float* __restrict__ latents, float* __restrict__ lat)
{
    int idx4 = blockIdx.x * 256 + threadIdx.x;
    int row  = idx4 >> 8;
    int c4   = idx4 & 255;
    int n    = row & 63;
    float4 v = *(const float4*)(latents + (size_t)n * DIMV + (c4 << 2));
    *(float4*)(lat + ((size_t)row << 10) + (c4 << 2)) = v;
}

// ---------------------------------------------------------------------------
// LayerNorm rows of 1024.  outHalf: write __half else float.
// ---------------------------------------------------------------------------
__global__ void __launch_bounds__(256) ln_kernel(
    const float* __restrict__ in, void* __restrict__ out,
    const float* __restrict__ g, const float* __restrict__ b, int outHalf)
{
    __shared__ float red[2][8];
    size_t row = blockIdx.x;
    const float* x = in + row * DIMV;
    int t = threadIdx.x;

    float4 v = *(const float4*)(x + (t << 2));
    float s  = v.x + v.y + v.z + v.w;
    float ss = v.x*v.x + v.y*v.y + v.z*v.z + v.w*v.w;
    #pragma unroll
    for (int off = 16; off; off >>= 1) {
        s  += __shfl_xor_sync(0xffffffffu, s,  off);
        ss += __shfl_xor_sync(0xffffffffu, ss, off);
    }
    int w = t >> 5, lane = t & 31;
    if (lane == 0) { red[0][w] = s; red[1][w] = ss; }
    __syncthreads();
    if (t == 0) {
        float ts = 0.f, tss = 0.f;
        #pragma unroll
        for (int i = 0; i < 8; i++) { ts += red[0][i]; tss += red[1][i]; }
        red[0][0] = ts; red[1][0] = tss;
    }
    __syncthreads();
    float mean = red[0][0] * (1.f / 1024.f);
    float var  = red[1][0] * (1.f / 1024.f) - mean * mean;
    float inv  = rsqrtf(var + LNEPS);

    float gx = 1.f, gy = 1.f, gz = 1.f, gw = 1.f;
    float bx = 0.f, by = 0.f, bz = 0.f, bw = 0.f;
    if (g) {
        float4 gg = *(const float4*)(g + (t << 2));
        float4 bb = *(const float4*)(b + (t << 2));
        gx = gg.x; gy = gg.y; gz = gg.z; gw = gg.w;
        bx = bb.x; by = bb.y; bz = bb.z; bw = bb.w;
    }
    float4 o;
    o.x = (v.x - mean) * inv * gx + bx;
    o.y = (v.y - mean) * inv * gy + by;
    o.z = (v.z - mean) * inv * gz + bz;
    o.w = (v.w - mean) * inv * gw + bw;
    if (outHalf) {
        __half2* oh = (__half2*)((__half*)out + row * DIMV + (t << 2));
        oh[0] = __floats2half2_rn(o.x, o.y);
        oh[1] = __floats2half2_rn(o.z, o.w);
    } else {
        *(float4*)((float*)out + row * DIMV + (t << 2)) = o;
    }
}

// ---------------------------------------------------------------------------
// fp16 mma.sync GEMM, 3-stage cp.async pipeline (unchanged from R10).
//   <4,4>: kvm config, BK=64.  <2,2>: latent config, BK=32.
//   flags: 1 = gelu, 2 = half output.
// ---------------------------------------------------------------------------
#define SB 136    // B smem row stride in u32
template <int IM, int CH>
__global__ void __launch_bounds__(256, (IM == 4) ? 2 : 3) gemm_h(
    const __half* __restrict__ A, const uint32_t* __restrict__ Bp, void* __restrict__ Cv,
    int K, int lda, int ldbn, int ldc,
    const float* __restrict__ bias, const float* __restrict__ resid, int flags)
{
    constexpr int BM  = 32 * IM;
    constexpr int SAv = 16 * CH + 8;   // A smem row stride in halves
    constexpr int BR  = 8 * CH;        // B k2-rows per stage
    extern __shared__ char smraw[];
    __half*   As = (__half*)smraw;                               // [3][BM][SAv]
    uint32_t* Bs = (uint32_t*)(smraw + 3 * BM * SAv * 2);        // [3][BR][SB]

    const int tid  = threadIdx.x;
    const int wid  = tid >> 5;
    const int lane = tid & 31;
    const int wm   = wid >> 2;
    const int wn   = wid & 3;
    const int g    = lane >> 2;
    const int t    = lane & 3;
    const int m0   = blockIdx.y * BM;
    const int n0   = blockIdx.x * 128;
    const int NK   = K / (16 * CH);
    const int wbase = wm * (IM * 16);
    const int lrow = (lane & 7) + ((lane >> 3) & 1) * 8;
    const int lcol = (lane >> 4) * 8;

    const uint32_t aBase = smem_u32(As);
    const uint32_t bBase = smem_u32(Bs);

    float acc[IM][4][4];
    #pragma unroll
    for (int i = 0; i < IM; i++)
        #pragma unroll
        for (int j = 0; j < 4; j++)
            #pragma unroll
            for (int r = 0; r < 4; r++) acc[i][j][r] = 0.f;

    auto load_tile = [&](int kt, int buf) {
        const int kg = kt * 16 * CH;
        #pragma unroll
        for (int p = 0; p < BM * CH / 128; p++) {
            int idx = p * 256 + tid;
            int row = idx / (2 * CH);
            int c   = (idx % (2 * CH)) << 3;
            cp_async16(aBase + ((buf * BM + row) * SAv + c) * 2,
                       A + (size_t)(m0 + row) * lda + kg + c);
        }
        #pragma unroll
        for (int p = 0; p < CH; p++) {
            int idx = p * 256 + tid;
            int r   = idx >> 5;
            int c4  = (idx & 31) << 2;
            cp_async16(bBase + ((buf * BR + r) * SB + c4) * 4,
                       Bp + (size_t)((kg >> 1) + r) * ldbn + n0 + c4);
        }
    };

    load_tile(0, 0);
    cp_commit();
    if (1 < NK) { load_tile(1, 1); }
    cp_commit();

    for (int kt = 0; kt < NK; kt++) {
        if (kt + 1 < NK) cp_wait1(); else cp_wait0();
        __syncthreads();
        if (kt + 2 < NK) { load_tile(kt + 2, (kt + 2) % 3); }
        cp_commit();

        const int buf = kt % 3;
        #pragma unroll
        for (int c = 0; c < CH; c++) {
            const int koff  = c << 4;
            const int k2off = c << 3;
            uint32_t af[IM][4], bf[4][2];
            #pragma unroll
            for (int i = 0; i < IM; i++) {
                uint32_t addr = aBase +
                    ((uint32_t)(buf * BM + wbase + i * 16 + lrow) * SAv + koff + lcol) * 2;
                ldsm4(af[i], addr);
            }
            #pragma unroll
            for (int j = 0; j < 4; j++) {
                const int col = wn * 32 + j * 8 + g;
                bf[j][0] = Bs[(buf * BR + k2off + t)     * SB + col];
                bf[j][1] = Bs[(buf * BR + k2off + t + 4) * SB + col];
            }
            #pragma unroll
            for (int i = 0; i < IM; i++)
                #pragma unroll
                for (int j = 0; j < 4; j++)
                    mma_f16(acc[i][j][0], acc[i][j][1], acc[i][j][2], acc[i][j][3],
                            af[i][0], af[i][1], af[i][2], af[i][3],
                            bf[j][0], bf[j][1]);
        }
    }

    const int doGelu  = flags & 1;
    const int outHalf = flags & 2;
    #pragma unroll
    for (int i = 0; i < IM; i++) {
        int mrow = m0 + wbase + i * 16 + g;
        #pragma unroll
        for (int j = 0; j < 4; j++) {
            int ncol = n0 + wn * 32 + j * 8 + 2 * t;
            #pragma unroll
            for (int half = 0; half < 2; half++) {
                int mr = mrow + half * 8;
                float c0 = acc[i][j][2 * half + 0];
                float c1 = acc[i][j][2 * half + 1];
                if (bias) {
                    float2 bv = *(const float2*)(bias + ncol);
                    c0 += bv.x; c1 += bv.y;
                }
                if (resid) {
                    float2 rv = *(const float2*)(resid + (size_t)mr * ldc + ncol);
                    c0 += rv.x; c1 += rv.y;
                }
                if (doGelu) { c0 = gelu_exact(c0); c1 = gelu_exact(c1); }
                if (outHalf) {
                    *(__half2*)((__half*)Cv + (size_t)mr * ldc + ncol) =
                        __floats2half2_rn(c0, c1);
                } else {
                    float2 o; o.x = c0; o.y = c1;
                    *(float2*)((float*)Cv + (size_t)mr * ldc + ncol) = o;
                }
            }
        }
    }
}

// ---------------------------------------------------------------------------
// fp16 tensor-core attention.  Block = (bt, head), 4 warps; warp w owns 16
// q-rows.  KV streamed in 64-token chunks (16 media + 1 latent = 17), half
// precision end-to-end, fp32 accumulators + softmax.
//   QK: A = Q frags (regs), B = K via half2 LDS (ks[tok][d], stride 72).
//   PV: A = P via ldmatrix.x4 (ps), B = V via ldmatrix.x4.trans (vs[tok][d]).
// ---------------------------------------------------------------------------
__global__ void __launch_bounds__(128, 4) attn_h_kernel(
    const __half* __restrict__ qkv, const __half* __restrict__ kvm,
    __half* __restrict__ outp)
{
    __shared__ __half ks[2][64][72];
    __shared__ __half vs[2][64][72];
    __shared__ __half ps[4][16][72];

    const int bt   = blockIdx.x >> 4;
    const int h    = blockIdx.x & 15;
    const int tid  = threadIdx.x;
    const int w    = tid >> 5;
    const int lane = tid & 31;
    const int g    = lane >> 2;
    const int t    = lane & 3;
    const int lrow = (lane & 7) + ((lane >> 3) & 1) * 8;
    const int lcol = (lane >> 4) * 8;

    // Q fragments (half2, pre-scaled by dh^-0.5 = 0.125, exact in fp16)
    uint32_t qa[4][4];
    {
        const __half* Qb = qkv + ((size_t)bt * 64 + w * 16) * 3072 + h * DHEAD;
        const __half2 sc = __float2half2_rn(0.125f);
        #pragma unroll
        for (int c = 0; c < 4; c++) {
            __half2 v0 = __hmul2(*(const __half2*)(Qb + (size_t)g       * 3072 + 16 * c + 2 * t),     sc);
            __half2 v1 = __hmul2(*(const __half2*)(Qb + (size_t)(g + 8) * 3072 + 16 * c + 2 * t),     sc);
            __half2 v2 = __hmul2(*(const __half2*)(Qb + (size_t)g       * 3072 + 16 * c + 2 * t + 8), sc);
            __half2 v3 = __hmul2(*(const __half2*)(Qb + (size_t)(g + 8) * 3072 + 16 * c + 2 * t + 8), sc);
            qa[c][0] = *(uint32_t*)&v0;
            qa[c][1] = *(uint32_t*)&v1;
            qa[c][2] = *(uint32_t*)&v2;
            qa[c][3] = *(uint32_t*)&v3;
        }
    }

    float out[8][4];
    #pragma unroll
    for (int j = 0; j < 8; j++)
        #pragma unroll
        for (int r = 0; r < 4; r++) out[j][r] = 0.f;
    float m0 = -1e30f, m1 = -1e30f, l0 = 0.f, l1 = 0.f;

    const uint32_t kb0 = smem_u32(&ks[0][0][0]);
    const uint32_t vb0 = smem_u32(&vs[0][0][0]);

    auto load_chunk = [&](int ch, int buf) {
        const __half* base;
        size_t rs;
        if (ch < 16) { base = kvm + ((size_t)bt * 1024 + ch * 64) * 2048 + h * DHEAD; rs = 2048; }
        else         { base = qkv + ((size_t)bt * 64) * 3072 + 1024 + h * DHEAD;      rs = 3072; }
        #pragma unroll
        for (int p = 0; p < 4; p++) {
            int idx = p * 128 + tid;      // 0..511
            int r   = idx >> 3;           // token 0..63
            int c8  = (idx & 7) << 3;     // d offset 0..56 (halves)
            cp_async16(kb0 + ((buf * 64 + r) * 72 + c8) * 2,
                       base + (size_t)r * rs + c8);
            cp_async16(vb0 + ((buf * 64 + r) * 72 + c8) * 2,
                       base + (size_t)r * rs + 1024 + c8);
        }
    };

    load_chunk(0, 0);
    cp_commit();

    for (int ch = 0; ch < 17; ch++) {
        const int buf = ch & 1;
        if (ch + 1 < 17) {
            load_chunk(ch + 1, buf ^ 1);
            cp_commit();
            cp_wait1();
        } else {
            cp_wait0();
        }
        __syncthreads();

        // ---- QK^T: 8 token-tiles x 4 k16 chunks over d ----
        float sim[8][4];
        #pragma unroll
        for (int j = 0; j < 8; j++)
            #pragma unroll
            for (int r = 0; r < 4; r++) sim[j][r] = 0.f;
        #pragma unroll
        for (int c = 0; c < 4; c++) {
            #pragma unroll
            for (int j = 0; j < 8; j++) {
                uint32_t b0 = *(const uint32_t*)&ks[buf][8 * j + g][16 * c + 2 * t];
                uint32_t b1 = *(const uint32_t*)&ks[buf][8 * j + g][16 * c + 2 * t + 8];
                mma_f16(sim[j][0], sim[j][1], sim[j][2], sim[j][3],
                        qa[c][0], qa[c][1], qa[c][2], qa[c][3], b0, b1);
            }
        }

        // ---- online softmax (rows g, g+8; quad shuffles over t) ----
        float cm0 = -1e30f, cm1 = -1e30f;
        #pragma unroll
        for (int j = 0; j < 8; j++) {
            cm0 = fmaxf(cm0, fmaxf(sim[j][0], sim[j][1]));
            cm1 = fmaxf(cm1, fmaxf(sim[j][2], sim[j][3]));
        }
        cm0 = fmaxf(cm0, __shfl_xor_sync(0xffffffffu, cm0, 1));
        cm0 = fmaxf(cm0, __shfl_xor_sync(0xffffffffu, cm0, 2));
        cm1 = fmaxf(cm1, __shfl_xor_sync(0xffffffffu, cm1, 1));
        cm1 = fmaxf(cm1, __shfl_xor_sync(0xffffffffu, cm1, 2));
        float mt0 = fmaxf(m0, cm0), mt1 = fmaxf(m1, cm1);
        float corr0 = __expf(m0 - mt0), corr1 = __expf(m1 - mt1);
        float rs0 = 0.f, rs1 = 0.f;
        #pragma unroll
        for (int j = 0; j < 8; j++) {
            sim[j][0] = __expf(sim[j][0] - mt0);
            sim[j][1] = __expf(sim[j][1] - mt0);
            sim[j][2] = __expf(sim[j][2] - mt1);
            sim[j][3] = __expf(sim[j][3] - mt1);
            rs0 += sim[j][0] + sim[j][1];
            rs1 += sim[j][2] + sim[j][3];
        }
        rs0 += __shfl_xor_sync(0xffffffffu, rs0, 1);
        rs0 += __shfl_xor_sync(0xffffffffu, rs0, 2);
        rs1 += __shfl_xor_sync(0xffffffffu, rs1, 1);
        rs1 += __shfl_xor_sync(0xffffffffu, rs1, 2);
        l0 = l0 * corr0 + rs0;  m0 = mt0;
        l1 = l1 * corr1 + rs1;  m1 = mt1;
        #pragma unroll
        for (int j = 0; j < 8; j++) {
            out[j][0] *= corr0; out[j][1] *= corr0;
            out[j][2] *= corr1; out[j][3] *= corr1;
        }

        // ---- stage P (half) in per-warp smem ----
        #pragma unroll
        for (int j = 0; j < 8; j++) {
            __half2 p0 = __floats2half2_rn(sim[j][0], sim[j][1]);
            __half2 p1 = __floats2half2_rn(sim[j][2], sim[j][3]);
            *(uint32_t*)&ps[w][g][8 * j + 2 * t]     = *(uint32_t*)&p0;
            *(uint32_t*)&ps[w][g + 8][8 * j + 2 * t] = *(uint32_t*)&p1;
        }
        __syncwarp();

        // ---- P @ V: 4 k16 token-chunks x 4 d16 tiles ----
        #pragma unroll
        for (int c = 0; c < 4; c++) {
            uint32_t af[4];
            ldsm4(af, smem_u32(&ps[w][lrow][16 * c + lcol]));
            #pragma unroll
            for (int jn = 0; jn < 4; jn++) {
                uint32_t bv[4];
                ldsm4t(bv, smem_u32(&vs[buf][16 * c + (lane & 15)][16 * jn + lcol]));
                mma_f16(out[2 * jn][0], out[2 * jn][1], out[2 * jn][2], out[2 * jn][3],
                        af[0], af[1], af[2], af[3], bv[0], bv[1]);
                mma_f16(out[2 * jn + 1][0], out[2 * jn + 1][1], out[2 * jn + 1][2], out[2 * jn + 1][3],
                        af[0], af[1], af[2], af[3], bv[2], bv[3]);
            }
        }
        __syncthreads();
    }

    float inv0 = 1.f / l0, inv1 = 1.f / l1;
    __half* O0 = outp + ((size_t)bt * 64 + w * 16 + g)     * INNERV + h * DHEAD;
    __half* O1 = outp + ((size_t)bt * 64 + w * 16 + g + 8) * INNERV + h * DHEAD;
    #pragma unroll
    for (int j = 0; j < 8; j++) {
        *(__half2*)(O0 + 8 * j + 2 * t) = __floats2half2_rn(out[j][0] * inv0, out[j][1] * inv0);
        *(__half2*)(O1 + 8 * j + 2 * t) = __floats2half2_rn(out[j][2] * inv1, out[j][3] * inv1);
    }
}

// ---------------------------------------------------------------------------
// Host orchestration: two-stream fork/join (correct enqueue order).
// ---------------------------------------------------------------------------
extern "C" void kernel_launch(void* const* d_in, const int* in_sizes, int n_in,
                              void* d_out, int out_size)
{
    const float* x       = (const float*)d_in[0];
    const float* latents = (const float*)d_in[1];
    const float* nm_g    = (const float*)d_in[2];
    const float* nm_b    = (const float*)d_in[3];
    const float* nl_g    = (const float*)d_in[4];
    const float* nl_b    = (const float*)d_in[5];
    const float* wq      = (const float*)d_in[6];
    const float* wkv     = (const float*)d_in[7];
    const float* wo      = (const float*)d_in[8];
    const float* ff_g    = (const float*)d_in[9];
    const float* ff_b    = (const float*)d_in[10];
    const float* w1      = (const float*)d_in[11];
    const float* w2      = (const float*)d_in[12];
    const float* fin_g   = (const float*)d_in[13];
    const float* fin_b   = (const float*)d_in[14];

    __half *xhat, *latn, *attnH, *ffh, *qkv;
    __half *kvmBuf[2];
    float *lat, *kvbias;
    uint32_t *wkvP, *wqkvP, *woP, *w1P, *w2P;
    cudaGetSymbolAddress((void**)&xhat,      g_xhat);
    cudaGetSymbolAddress((void**)&kvmBuf[0], g_kvmA);
    cudaGetSymbolAddress((void**)&kvmBuf[1], g_kvmB);
    cudaGetSymbolAddress((void**)&lat,       g_lat);
    cudaGetSymbolAddress((void**)&latn,      g_latn);
    cudaGetSymbolAddress((void**)&qkv,       g_qkv);
    cudaGetSymbolAddress((void**)&attnH,     g_attn);
    cudaGetSymbolAddress((void**)&ffh,       g_ffh);
    cudaGetSymbolAddress((void**)&wkvP,      g_wkvP);
    cudaGetSymbolAddress((void**)&wqkvP,     g_wqkvP);
    cudaGetSymbolAddress((void**)&woP,       g_woP);
    cudaGetSymbolAddress((void**)&w1P,       g_w1P);
    cudaGetSymbolAddress((void**)&w2P,       g_w2P);
    cudaGetSymbolAddress((void**)&kvbias,    g_kvbias);

    const int K2N_KV = (DIMV / 2) * 2 * INNERV;
    const int K2N_SQ = (DIMV / 2) * INNERV;
    const int K2N_W1 = (DIMV / 2) * FFV;
    const int K2N_W2 = (FFV / 2) * DIMV;

    const int SM44 = 3 * 128 * 72 * 2 + 3 * 32 * SB * 4;
    const int SM22 = 3 *  64 * 40 * 2 + 3 * 16 * SB * 4;
    cudaFuncSetAttribute(gemm_h<4,4>, cudaFuncAttributeMaxDynamicSharedMemorySize, SM44);
    cudaFuncSetAttribute(gemm_h<2,2>, cudaFuncAttributeMaxDynamicSharedMemorySize, SM22);

    cudaStream_t s1;
    cudaStreamCreateWithFlags(&s1, cudaStreamNonBlocking);
    cudaEvent_t evPre, evKvm[NDEPTH], evAttn[NDEPTH];
    cudaEventCreateWithFlags(&evPre, cudaEventDisableTiming);
    for (int i = 0; i < NDEPTH; i++) {
        cudaEventCreateWithFlags(&evKvm[i],  cudaEventDisableTiming);
        cudaEventCreateWithFlags(&evAttn[i], cudaEventDisableTiming);
    }

    // ---- stream 0: minimal preproc needed by kvm ----
    wpack_kernel<<<NDEPTH * K2N_KV / 256, 256>>>(
        wkv, wkvP, K2N_KV, 2 * INNERV, DIMV, nm_g, 2 * INNERV, 0);
    ln_kernel<<<BTV * MEDIA, 256>>>(x, xhat, nullptr, nullptr, 1);
    bias_kernel<<<dim3(2 * INNERV / 256, NDEPTH), 256>>>(nm_b, wkv, kvbias, DIMV, 2 * INNERV);
    cudaEventRecord(evPre, 0);

    // ---- s1: first two kvm GEMMs (half output) ----
    cudaStreamWaitEvent(s1, evPre, 0);
    for (int i = 0; i < 2 && i < NDEPTH; i++) {
        gemm_h<4,4><<<dim3(16, 256), 256, SM44, s1>>>(
            xhat, wkvP + (size_t)i * K2N_KV, kvmBuf[i & 1],
            DIMV, DIMV, 2 * INNERV, 2 * INNERV,
            kvbias + (size_t)i * 2 * INNERV, nullptr, 2);
        cudaEventRecord(evKvm[i], s1);
    }

    // ---- stream 0: rest of preproc ----
    init_lat_kernel<<<2048, 256>>>(latents, lat);
    wpack_kernel<<<NDEPTH * K2N_SQ / 256, 256>>>(
        wq, wqkvP, K2N_SQ, INNERV, DIMV, nullptr, 3 * INNERV, 0);
    wpack_kernel<<<NDEPTH * K2N_KV / 256, 256>>>(
        wkv, wqkvP, K2N_KV, 2 * INNERV, DIMV, nullptr, 3 * INNERV, INNERV);
    wpack_kernel<<<NDEPTH * K2N_SQ / 256, 256>>>(
        wo, woP, K2N_SQ, DIMV, INNERV, nullptr, DIMV, 0);
    wpack_kernel<<<NDEPTH * K2N_W1 / 256, 256>>>(
        w1, w1P, K2N_W1, FFV, DIMV, nullptr, FFV, 0);
    wpack_kernel<<<NDEPTH * K2N_W2 / 256, 256>>>(
        w2, w2P, K2N_W2, DIMV, FFV, nullptr, DIMV, 0);

    // ---- stream 0: latent chain; kvm_{i+2} enqueued after evAttn[i] record ----
    for (int i = 0; i < NDEPTH; i++) {
        const uint32_t* wqkvP_i = wqkvP + (size_t)i * (DIMV / 2) * 3 * INNERV;
        const uint32_t* woP_i   = woP   + (size_t)i * K2N_SQ;
        const uint32_t* w1P_i   = w1P   + (size_t)i * K2N_W1;
        const uint32_t* w2P_i   = w2P   + (size_t)i * K2N_W2;

        ln_kernel<<<BTV * NLAT, 256>>>(lat, latn,
            nl_g + (size_t)i * DIMV, nl_b + (size_t)i * DIMV, 1);
        gemm_h<2,2><<<dim3(24, 32), 256, SM22>>>(latn, wqkvP_i, qkv,
            DIMV, DIMV, 3 * INNERV, 3 * INNERV, nullptr, nullptr, 2);

        cudaStreamWaitEvent(0, evKvm[i], 0);
        attn_h_kernel<<<BTV * NHEADS, 128>>>(qkv, kvmBuf[i & 1], attnH);
        cudaEventRecord(evAttn[i], 0);

        if (i + 2 < NDEPTH) {
            int j = i + 2;
            cudaStreamWaitEvent(s1, evAttn[i], 0);
            gemm_h<4,4><<<dim3(16, 256), 256, SM44, s1>>>(
                xhat, wkvP + (size_t)j * K2N_KV, kvmBuf[j & 1],
                DIMV, DIMV, 2 * INNERV, 2 * INNERV,
                kvbias + (size_t)j * 2 * INNERV, nullptr, 2);
            cudaEventRecord(evKvm[j], s1);
        }

        gemm_h<2,2><<<dim3(8, 32), 256, SM22>>>(attnH, woP_i, lat,
            INNERV, INNERV, DIMV, DIMV, nullptr, lat, 0);

        ln_kernel<<<BTV * NLAT, 256>>>(lat, latn,
            ff_g + (size_t)i * DIMV, ff_b + (size_t)i * DIMV, 1);
        gemm_h<2,2><<<dim3(32, 32), 256, SM22>>>(latn, w1P_i, ffh,
            DIMV, DIMV, FFV, FFV, nullptr, nullptr, 1 | 2);
        gemm_h<2,2><<<dim3(8, 32), 256, SM22>>>(ffh, w2P_i, lat,
            FFV, FFV, DIMV, DIMV, nullptr, lat, 0);
    }

    ln_kernel<<<BTV * NLAT, 256>>>(lat, (float*)d_out, fin_g, fin_b, 0);

    cudaEventDestroy(evPre);
    for (int i = 0; i < NDEPTH; i++) {
        cudaEventDestroy(evKvm[i]);
        cudaEventDestroy(evAttn[i]);
    }
    cudaStreamDestroy(s1);
}